// round 8
// baseline (speedup 1.0000x reference)
#include <cuda_runtime.h>
#include <cuda_bf16.h>
#include <math.h>
#include <stdint.h>

#define B_    2
#define T_    1024
#define BT_   2048
#define DIM_  2048
#define NH_   16
#define DH_   128
#define DRH_  64
#define DC_   512
#define NE_   16
#define TOPK_ 4
#define MOE_  1024
#define MOESH_ 2048
#define CAP_  2048
#define QKD_  192   // DH + DRH

// ---------------- scratch (static device globals; no runtime alloc) ----------
__device__ float g_h  [BT_*DIM_];
__device__ float g_ckv[BT_*DC_];
__device__ float g_cq [BT_*DC_];
__device__ float g_Q  [BT_*NH_*QKD_];
__device__ float g_K  [BT_*NH_*QKD_];
__device__ float g_V  [BT_*NH_*DH_];
__device__ float g_kr [BT_*DRH_];
__device__ float g_S  [(size_t)B_*NH_*T_*T_];
__device__ float g_O  [BT_*NH_*DH_];
__device__ float g_Wo [DIM_*NH_*DH_];
__device__ float g_x1 [BT_*DIM_];
__device__ float g_xn [BT_*DIM_];
__device__ float g_a1 [BT_*MOESH_];
__device__ float g_a3 [BT_*MOESH_];
__device__ float g_h1 [(size_t)NE_*CAP_*MOE_];
__device__ float g_h2 [(size_t)NE_*CAP_*MOE_];
__device__ int   g_cnt[NE_];
__device__ int   g_tok[NE_*CAP_];
__device__ float g_wt [NE_*CAP_];

// ---------------- 3xTF32 tensor-core GEMM -------------------------------------
// Double-buffered BK=8, hi/lo packed uint2, prefetch distance 2, zero-fill.
// MODE 0: C = A(M,K) * B(K,N)      (NN)
// MODE 1: C = A(M,K) * B(N,K)^T    (NT)
// MODE 2: C = A(K,M)^T * B(K,N)    (TN)
struct GemmP {
    const float* A; const float* B; float* C; const float* res;
    int M, N, K, lda, ldb, ldc;
    float alpha;
    long long aO1, aO2, bO1, bO2, cO1, cO2;
    int zdiv, cap;
    const int* Mvec;    // per-z dynamic M (row count)
    const int* aRows;   // per-z row gather indices into A
    const int* cRows;   // per-z row scatter indices into C (atomicAdd)
    const float* wRow;  // per-row scatter weight
    int causal;         // MODE1 logits: skip blocks entirely above diagonal
    int causalAV;       // MODE2 AV: K loop starts at m0 (S lower-triangular)
};

__device__ __forceinline__ uint32_t f2t(float x) {
    uint32_t u; asm("cvt.rna.tf32.f32 %0, %1;" : "=r"(u) : "f"(x)); return u;
}

__device__ __forceinline__ uint2 split_hl(float x) {
    uint32_t h = f2t(x);
    uint32_t l = f2t(x - __uint_as_float(h));
    return make_uint2(h, l);
}

__device__ __forceinline__ void mma_tf32(float* c, const uint32_t* a, const uint32_t* b) {
    asm volatile("mma.sync.aligned.m16n8k8.row.col.f32.tf32.tf32.f32 "
        "{%0,%1,%2,%3}, {%4,%5,%6,%7}, {%8,%9}, {%0,%1,%2,%3};\n"
        : "+f"(c[0]), "+f"(c[1]), "+f"(c[2]), "+f"(c[3])
        : "r"(a[0]), "r"(a[1]), "r"(a[2]), "r"(a[3]), "r"(b[0]), "r"(b[1]));
}

template<int MODE>
__global__ __launch_bounds__(256, 2) void gemm_k(GemmP p) {
    __shared__ uint2 sA[2][8][132];   // [buf][k][m] = (hi, lo)
    __shared__ uint2 sB[2][8][132];   // [buf][k][n]

    int z = blockIdx.z, z1 = z / p.zdiv, z2 = z - z1 * p.zdiv;
    const float* A  = p.A + z1 * p.aO1 + z2 * p.aO2;
    const float* Bp = p.B + z1 * p.bO1 + z2 * p.bO2;
    float*       C  = p.C + z1 * p.cO1 + z2 * p.cO2;
    int M = p.Mvec ? p.Mvec[z] : p.M;
    int m0 = blockIdx.y * 128, n0 = blockIdx.x * 128;
    if (m0 >= M) return;
    if (MODE == 1 && p.causal && n0 >= m0 + 128) return;  // fully masked block
    int tid = threadIdx.x, lane = tid & 31, warp = tid >> 5;
    int wm = (warp & 1) << 6, wn = (warp >> 1) << 5;   // warp tile 64x32
    int gid = lane >> 2, tg = lane & 3;

    // ---- per-thread load setup (zero-fill out of range; never clamp) ----
    bool aValid; const float* aPtr; int aK, aM;
    if (MODE != 2) {                    // A[row][k]
        int r = m0 + (tid >> 1);
        aValid = (r < M);
        long long ar = 0;
        if (aValid) ar = p.aRows ? (long long)p.aRows[(long long)z * p.cap + r]
                                 : (long long)r;
        aPtr = A + ar * (long long)p.lda + (tid & 1) * 4;
        aK = (tid & 1) * 4;  aM = tid >> 1;
    } else {                            // A[k][m]
        int m = m0 + (tid & 31) * 4;
        aValid = (m < M);
        aPtr = A + (long long)(tid >> 5) * p.lda + (aValid ? m : 0);
        aK = tid >> 5;       aM = (tid & 31) * 4;
    }
    bool bValid; const float* bPtr; int bK, bM;
    if (MODE == 1) {                    // B[n][k]
        int cl = n0 + (tid >> 1);
        bValid = (cl < p.N);
        bPtr = Bp + (bValid ? (long long)cl * p.ldb : 0) + (tid & 1) * 4;
        bK = (tid & 1) * 4;  bM = tid >> 1;
    } else {                            // B[k][n]
        int n = n0 + (tid & 31) * 4;
        bValid = (n < p.N);
        bPtr = Bp + (long long)(tid >> 5) * p.ldb + (bValid ? n : 0);
        bK = tid >> 5;       bM = (tid & 31) * 4;
    }

    float acc[4][4][4];
#pragma unroll
    for (int mi = 0; mi < 4; mi++)
#pragma unroll
        for (int ni = 0; ni < 4; ni++)
#pragma unroll
            for (int q = 0; q < 4; q++) acc[mi][ni][q] = 0.f;

    const float4 z4 = make_float4(0.f, 0.f, 0.f, 0.f);
    int kStart = (MODE == 2 && p.causalAV) ? m0 : 0;   // m0 % 8 == 0
    int nIter = (p.K - kStart) >> 3;

    auto loadG = [&](int chunk, float4& oa, float4& ob) {
        int k = kStart + chunk * 8;
        long long ka = (MODE == 2) ? (long long)k * p.lda : (long long)k;
        long long kb = (MODE == 1) ? (long long)k : (long long)k * p.ldb;
        oa = aValid ? *(const float4*)(aPtr + ka) : z4;
        ob = bValid ? *(const float4*)(bPtr + kb) : z4;
    };
    auto storeS = [&](int buf, const float4& ia, const float4& ib) {
        const float* a4 = (const float*)&ia;
        const float* b4 = (const float*)&ib;
#pragma unroll
        for (int j = 0; j < 4; j++) {
            if (MODE == 2) sA[buf][aK][aM + j] = split_hl(a4[j]);
            else           sA[buf][aK + j][aM] = split_hl(a4[j]);
            if (MODE == 1) sB[buf][bK + j][bM] = split_hl(b4[j]);
            else           sB[buf][bK][bM + j] = split_hl(b4[j]);
        }
    };

    // prefetch pipeline: reg slot = chunk & 1; smem buf = chunk & 1
    float4 ra[2], rb[2];
    loadG(0, ra[0], rb[0]);
    if (nIter > 1) loadG(1, ra[1], rb[1]);
    storeS(0, ra[0], rb[0]);
    __syncthreads();

    for (int it = 0; it < nIter; it++) {
        int cur = it & 1;
        // issue load of chunk it+2 into reg slot (it+2)&1 == cur (chunk it consumed)
        if (it + 2 < nIter) loadG(it + 2, ra[cur], rb[cur]);

        // MMAs on smem[cur]
        uint2 vB0[4], vB1[4];
#pragma unroll
        for (int ni = 0; ni < 4; ni++) {
            int nb2 = wn + ni * 8 + gid;
            vB0[ni] = sB[cur][tg    ][nb2];
            vB1[ni] = sB[cur][tg + 4][nb2];
        }
#pragma unroll
        for (int mi = 0; mi < 4; mi++) {
            int mb = wm + mi * 16 + gid;
            uint2 a0 = sA[cur][tg    ][mb];
            uint2 a1 = sA[cur][tg    ][mb + 8];
            uint2 a2 = sA[cur][tg + 4][mb];
            uint2 a3 = sA[cur][tg + 4][mb + 8];
            uint32_t ah[4] = {a0.x, a1.x, a2.x, a3.x};
            uint32_t al[4] = {a0.y, a1.y, a2.y, a3.y};
#pragma unroll
            for (int ni = 0; ni < 4; ni++) {
                uint32_t bh[2] = {vB0[ni].x, vB1[ni].x};
                mma_tf32(acc[mi][ni], ah, bh);
            }
#pragma unroll
            for (int ni = 0; ni < 4; ni++) {
                uint32_t bh[2] = {vB0[ni].x, vB1[ni].x};
                mma_tf32(acc[mi][ni], al, bh);
            }
#pragma unroll
            for (int ni = 0; ni < 4; ni++) {
                uint32_t bl[2] = {vB0[ni].y, vB1[ni].y};
                mma_tf32(acc[mi][ni], ah, bl);
            }
        }

        // store chunk it+1 (loaded at iter it-1) into the other buffer
        if (it + 1 < nIter) {
            int nxt = (it + 1) & 1;
            storeS(nxt, ra[nxt], rb[nxt]);
        }
        __syncthreads();
    }

    // epilogue: c0,c1 -> row gid, cols 2tg,2tg+1 ; c2,c3 -> row gid+8
#pragma unroll
    for (int mi = 0; mi < 4; mi++) {
#pragma unroll
        for (int half = 0; half < 2; half++) {
            int m = m0 + wm + mi * 16 + gid + half * 8;
            if (m >= M) continue;
            long long crow; float w = p.alpha;
            if (p.cRows) {
                crow = (long long)p.cRows[(long long)z * p.cap + m] * p.ldc;
                w *= p.wRow[(long long)z * p.cap + m];
            } else {
                crow = (long long)m * p.ldc;
            }
#pragma unroll
            for (int ni = 0; ni < 4; ni++) {
                int n = n0 + wn + ni * 8 + tg * 2;
                if (n >= p.N) continue;
                float v0 = acc[mi][ni][half * 2 + 0] * w;
                float v1 = acc[mi][ni][half * 2 + 1] * w;
                if (p.cRows) {
                    atomicAdd(&C[crow + n],     v0);
                    atomicAdd(&C[crow + n + 1], v1);
                } else {
                    if (p.res) { v0 += p.res[crow + n]; v1 += p.res[crow + n + 1]; }
                    C[crow + n]     = v0;
                    C[crow + n + 1] = v1;
                }
            }
        }
    }
}

// ---------------- small fused kernels -----------------------------------------
__global__ void rmsnorm_k(const float* __restrict__ x, const float* __restrict__ w,
                          float* __restrict__ o) {
    int r = blockIdx.x;
    const float* xr = x + (long long)r * DIM_;
    float s = 0.f;
    for (int d = threadIdx.x; d < DIM_; d += 256) { float v = xr[d]; s += v * v; }
    __shared__ float red[256];
    red[threadIdx.x] = s; __syncthreads();
    for (int off = 128; off; off >>= 1) {
        if (threadIdx.x < off) red[threadIdx.x] += red[threadIdx.x + off];
        __syncthreads();
    }
    float inv = rsqrtf(red[0] / (float)DIM_ + 1e-6f);
    float* orow = o + (long long)r * DIM_;
    for (int d = threadIdx.x; d < DIM_; d += 256) orow[d] = w[d] * xr[d] * inv;
}

__device__ __forceinline__ void rope_cs(int t, int j, float& c, float& s) {
    float freq = 1.0f / powf(10000.0f, (float)(2 * j) / (float)DRH_);
    float ang = (float)t * freq;
    sincosf(ang, &s, &c);
}

__global__ void rope_q_k(float* __restrict__ Q) {
    int idx = blockIdx.x;            // bt*NH + h
    int bt = idx / NH_;
    int t = bt % T_;
    int j = threadIdx.x;             // 0..31
    float* base = Q + (long long)idx * QKD_ + DH_;
    float re = base[j], im = base[32 + j];
    float c, s; rope_cs(t, j, c, s);
    base[j]      = re * c - im * s;
    base[32 + j] = re * s + im * c;
}

__global__ void rope_kr_k(const float* __restrict__ kr, float* __restrict__ Kb) {
    int bt = blockIdx.x;
    int t = bt % T_;
    int j = threadIdx.x;             // 0..31
    float re = kr[bt * DRH_ + j], im = kr[bt * DRH_ + 32 + j];
    float c, s; rope_cs(t, j, c, s);
    float o1 = (re * c - im * s) / (float)NH_;
    float o2 = (re * s + im * c) / (float)NH_;
    for (int h = 0; h < NH_; h++) {
        float* base = Kb + ((long long)bt * NH_ + h) * QKD_ + DH_;
        base[j] = o1; base[32 + j] = o2;
    }
}

__global__ void softmax_k(float* __restrict__ S) {
    long long r = blockIdx.x;        // (b,h,t) row
    int t = (int)(r & (T_ - 1));
    float* row = S + r * (long long)T_;
    int n = t + 1;
    __shared__ float red[256];
    int tid = threadIdx.x;
    float mx = -INFINITY;
    for (int l = tid; l < n; l += 256) mx = fmaxf(mx, row[l]);
    red[tid] = mx; __syncthreads();
    for (int off = 128; off; off >>= 1) {
        if (tid < off) red[tid] = fmaxf(red[tid], red[tid + off]);
        __syncthreads();
    }
    mx = red[0]; __syncthreads();
    float sum = 0.f;
    for (int l = tid; l < n; l += 256) { float e = expf(row[l] - mx); row[l] = e; sum += e; }
    red[tid] = sum; __syncthreads();
    for (int off = 128; off; off >>= 1) {
        if (tid < off) red[tid] += red[tid + off];
        __syncthreads();
    }
    float inv = 1.f / red[0];
    for (int l = tid; l < T_; l += 256) row[l] = (l < n) ? row[l] * inv : 0.f;
}

__global__ void pack_wo_k(const float* __restrict__ wo, float* __restrict__ out) {
    long long i = (long long)blockIdx.x * 256 + threadIdx.x;  // d*2048 + h*128 + k
    if (i >= (long long)DIM_ * 2048) return;
    int d = (int)(i >> 11);
    int r = (int)(i & 2047);
    int h = r >> 7, k = r & 127;
    out[i] = wo[(long long)d * 2048 + k * NH_ + h];
}

__global__ void gate_k(const float* __restrict__ xn, const float* __restrict__ gw,
                       const float* __restrict__ gb, float* affOut,
                       int* __restrict__ cnt, int* __restrict__ tok,
                       float* __restrict__ wt) {
    int bt = blockIdx.x;
    __shared__ float xrow[DIM_];
    __shared__ float aff[NE_];
    int tid = threadIdx.x;
    for (int d = tid; d < DIM_; d += 256) xrow[d] = xn[(long long)bt * DIM_ + d];
    __syncthreads();
    int w = tid >> 5, lane = tid & 31;
    for (int e = w; e < NE_; e += 8) {
        float s = 0.f;
        const float* gr = gw + (long long)e * DIM_;
        for (int d = lane; d < DIM_; d += 32) s += xrow[d] * gr[d];
        for (int o = 16; o; o >>= 1) s += __shfl_xor_sync(0xffffffffu, s, o);
        if (lane == 0) aff[e] = 1.f / (1.f + expf(-s)) + gb[e];
    }
    __syncthreads();
    if (tid == 0) {
        if (affOut) for (int e = 0; e < NE_; e++) affOut[(long long)bt * NE_ + e] = aff[e];
        bool used[NE_] = {};
        float wv[TOPK_]; int wi[TOPK_]; float sum = 0.f;
        for (int k = 0; k < TOPK_; k++) {
            float best = -1e30f; int bi = 0;
            for (int e = 0; e < NE_; e++)
                if (!used[e] && aff[e] > best) { best = aff[e]; bi = e; }
            used[bi] = true; wv[k] = best; wi[k] = bi; sum += best;
        }
        for (int k = 0; k < TOPK_; k++) {
            int e = wi[k];
            int pos = atomicAdd(&cnt[e], 1);
            tok[e * CAP_ + pos] = bt;
            wt [e * CAP_ + pos] = wv[k] / sum;
        }
    }
}

__global__ void silumul_k(float4* __restrict__ a, const float4* __restrict__ b, long long n4) {
    long long i = (long long)blockIdx.x * 256 + threadIdx.x;
    if (i >= n4) return;
    float4 x = a[i], y = b[i];
    x.x *= y.x; x.y *= y.y; x.z *= y.z; x.w *= y.w;
    x.x = x.x / (1.f + expf(-x.x));
    x.y = x.y / (1.f + expf(-x.y));
    x.z = x.z / (1.f + expf(-x.z));
    x.w = x.w / (1.f + expf(-x.w));
    a[i] = x;
}

__global__ void silumul_routed_k(float4* __restrict__ a, const float4* __restrict__ b,
                                 const int* __restrict__ cnt) {
    long long i = (long long)blockIdx.x * 256 + threadIdx.x;   // NE*CAP*MOE/4
    long long el = i << 2;
    int e = (int)(el >> 21);                // CAP_*MOE_ = 2^21
    int ri = (int)((el >> 10) & (CAP_ - 1));
    if (ri >= cnt[e]) return;
    float4 x = a[i], y = b[i];
    x.x *= y.x; x.y *= y.y; x.z *= y.z; x.w *= y.w;
    x.x = x.x / (1.f + expf(-x.x));
    x.y = x.y / (1.f + expf(-x.y));
    x.z = x.z / (1.f + expf(-x.z));
    x.w = x.w / (1.f + expf(-x.w));
    a[i] = x;
}

// ---------------- host-side launch helpers ------------------------------------
template<int MODE>
static void gemm(const float* A, const float* B, float* C, int M, int N, int K,
                 int lda, int ldb, int ldc, float alpha, const float* res,
                 int nz, int zdiv,
                 long long a1, long long a2, long long b1, long long b2,
                 long long c1, long long c2,
                 const int* Mvec = nullptr, const int* aRows = nullptr,
                 const int* cRows = nullptr, const float* wRow = nullptr,
                 int cap = 0, int causal = 0, int causalAV = 0) {
    GemmP p;
    p.A = A; p.B = B; p.C = C; p.res = res;
    p.M = M; p.N = N; p.K = K; p.lda = lda; p.ldb = ldb; p.ldc = ldc;
    p.alpha = alpha;
    p.aO1 = a1; p.aO2 = a2; p.bO1 = b1; p.bO2 = b2; p.cO1 = c1; p.cO2 = c2;
    p.zdiv = zdiv; p.cap = cap;
    p.Mvec = Mvec; p.aRows = aRows; p.cRows = cRows; p.wRow = wRow;
    p.causal = causal; p.causalAV = causalAV;
    dim3 g((N + 127) / 128, (M + 127) / 128, nz);
    gemm_k<MODE><<<g, 256>>>(p);
}

extern "C" void kernel_launch(void* const* d_in, const int* in_sizes, int n_in,
                              void* d_out, int out_size) {
    const float* x      = (const float*)d_in[0];
    const float* attn_w = (const float*)d_in[3];
    const float* ffn_w  = (const float*)d_in[4];
    const float* gate_w = (const float*)d_in[5];
    const float* gate_b = (const float*)d_in[6];
    const float* w1s    = (const float*)d_in[7];
    const float* w2s    = (const float*)d_in[8];
    const float* w3s    = (const float*)d_in[9];
    const float* w1r    = (const float*)d_in[10];
    const float* w2r    = (const float*)d_in[11];
    const float* w3r    = (const float*)d_in[12];
    const float* wdkv   = (const float*)d_in[13];
    const float* wuk    = (const float*)d_in[14];
    const float* wuv    = (const float*)d_in[15];
    const float* wdq    = (const float*)d_in[16];
    const float* wuq    = (const float*)d_in[17];
    const float* wqr    = (const float*)d_in[18];
    const float* wkr    = (const float*)d_in[19];
    const float* wo     = (const float*)d_in[20];
    float* out = (float*)d_out;

    float *h, *ckv, *cq, *Q, *K, *V, *kr, *S, *O, *Wo, *x1, *xn, *a1, *a3, *h1, *h2, *wt;
    int *cnt, *tok;
    cudaGetSymbolAddress((void**)&h,   g_h);
    cudaGetSymbolAddress((void**)&ckv, g_ckv);
    cudaGetSymbolAddress((void**)&cq,  g_cq);
    cudaGetSymbolAddress((void**)&Q,   g_Q);
    cudaGetSymbolAddress((void**)&K,   g_K);
    cudaGetSymbolAddress((void**)&V,   g_V);
    cudaGetSymbolAddress((void**)&kr,  g_kr);
    cudaGetSymbolAddress((void**)&S,   g_S);
    cudaGetSymbolAddress((void**)&O,   g_O);
    cudaGetSymbolAddress((void**)&Wo,  g_Wo);
    cudaGetSymbolAddress((void**)&x1,  g_x1);
    cudaGetSymbolAddress((void**)&xn,  g_xn);
    cudaGetSymbolAddress((void**)&a1,  g_a1);
    cudaGetSymbolAddress((void**)&a3,  g_a3);
    cudaGetSymbolAddress((void**)&h1,  g_h1);
    cudaGetSymbolAddress((void**)&h2,  g_h2);
    cudaGetSymbolAddress((void**)&cnt, g_cnt);
    cudaGetSymbolAddress((void**)&tok, g_tok);
    cudaGetSymbolAddress((void**)&wt,  g_wt);

    // ---- attention ----
    rmsnorm_k<<<BT_, 256>>>(x, attn_w, h);
    gemm<1>(h, wdkv, ckv, BT_, DC_, DIM_, DIM_, DIM_, DC_, 1.f, nullptr, 1, 1, 0,0,0,0,0,0);
    gemm<1>(h, wdq,  cq,  BT_, DC_, DIM_, DIM_, DIM_, DC_, 1.f, nullptr, 1, 1, 0,0,0,0,0,0);
    gemm<1>(ckv, wuk, K,       BT_, DH_,  DC_, DC_, NH_*DC_, NH_*QKD_, 1.f, nullptr,
            NH_, NH_, 0,0, 0, DC_, 0, QKD_);
    gemm<1>(ckv, wuv, V,       BT_, DH_,  DC_, DC_, NH_*DC_, NH_*DH_,  1.f, nullptr,
            NH_, NH_, 0,0, 0, DC_, 0, DH_);
    gemm<1>(cq,  wuq, Q,       BT_, DH_,  DC_, DC_, NH_*DC_, NH_*QKD_, 1.f, nullptr,
            NH_, NH_, 0,0, 0, DC_, 0, QKD_);
    gemm<1>(cq,  wqr, Q + DH_, BT_, DRH_, DC_, DC_, NH_*DC_, NH_*QKD_, 1.f, nullptr,
            NH_, NH_, 0,0, 0, DC_, 0, QKD_);
    gemm<1>(h, wkr, kr, BT_, DRH_, DIM_, DIM_, DIM_, DRH_, 1.f, nullptr, 1, 1, 0,0,0,0,0,0);
    rope_q_k<<<BT_ * NH_, 32>>>(Q);
    rope_kr_k<<<BT_, 32>>>(kr, K);
    // logits (batched over b,h), scaled; causal block skip
    float scale = 1.0f / sqrtf((float)QKD_);
    gemm<1>(Q, K, S, T_, T_, QKD_, NH_*QKD_, NH_*QKD_, T_, scale, nullptr,
            B_*NH_, NH_,
            (long long)T_*NH_*QKD_, QKD_,
            (long long)T_*NH_*QKD_, QKD_,
            (long long)NH_*T_*T_, (long long)T_*T_,
            nullptr, nullptr, nullptr, nullptr, 0, /*causal=*/1);
    softmax_k<<<B_ * NH_ * T_, 256>>>(S);
    // out[l,k] = sum_t S[t,l] V[t,k]  (TN); skip K chunks with t < l (S==0 there)
    gemm<2>(S, V, O, T_, DH_, T_, T_, NH_*DH_, NH_*DH_, 1.f, nullptr,
            B_*NH_, NH_,
            (long long)NH_*T_*T_, (long long)T_*T_,
            (long long)T_*NH_*DH_, DH_,
            (long long)T_*NH_*DH_, DH_,
            nullptr, nullptr, nullptr, nullptr, 0, 0, /*causalAV=*/1);
    // attn projection + residual
    pack_wo_k<<<(DIM_*2048 + 255)/256, 256>>>(wo, Wo);
    gemm<1>(O, Wo, x1, BT_, DIM_, NH_*DH_, NH_*DH_, NH_*DH_, DIM_, 1.f, x,
            1, 1, 0,0,0,0,0,0);

    // ---- MoE ----
    rmsnorm_k<<<BT_, 256>>>(x1, ffn_w, xn);
    cudaMemsetAsync(cnt, 0, NE_ * sizeof(int));
    float* affOut = (out_size >= BT_*DIM_ + BT_*NE_) ? out + (long long)BT_*DIM_ : nullptr;
    gate_k<<<BT_, 256>>>(xn, gate_w, gate_b, affOut, cnt, tok, wt);
    // shared expert
    gemm<0>(xn, w1s, a1, BT_, MOESH_, DIM_, DIM_, MOESH_, MOESH_, 1.f, nullptr, 1,1,0,0,0,0,0,0);
    gemm<0>(xn, w3s, a3, BT_, MOESH_, DIM_, DIM_, MOESH_, MOESH_, 1.f, nullptr, 1,1,0,0,0,0,0,0);
    silumul_k<<<((BT_*MOESH_/4) + 255)/256, 256>>>((float4*)a1, (const float4*)a3,
                                                   (long long)BT_*MOESH_/4);
    gemm<0>(a1, w2s, out, BT_, DIM_, MOESH_, MOESH_, DIM_, DIM_, 1.f, x1, 1,1,0,0,0,0,0,0);
    // routed experts (top-4 only; gathered GEMMs with dynamic M, fused weighted scatter)
    gemm<0>(xn, w1r, h1, CAP_, MOE_, DIM_, DIM_, MOE_, MOE_, 1.f, nullptr,
            NE_, NE_, 0,0, 0, (long long)DIM_*MOE_, 0, (long long)CAP_*MOE_,
            cnt, tok, nullptr, nullptr, CAP_);
    gemm<0>(xn, w3r, h2, CAP_, MOE_, DIM_, DIM_, MOE_, MOE_, 1.f, nullptr,
            NE_, NE_, 0,0, 0, (long long)DIM_*MOE_, 0, (long long)CAP_*MOE_,
            cnt, tok, nullptr, nullptr, CAP_);
    silumul_routed_k<<<(((long long)NE_*CAP_*MOE_/4) + 255)/256, 256>>>(
        (float4*)h1, (const float4*)h2, cnt);
    gemm<0>(h1, w2r, out, CAP_, DIM_, MOE_, MOE_, DIM_, DIM_, 1.f, nullptr,
            NE_, NE_, 0, (long long)CAP_*MOE_, 0, (long long)MOE_*DIM_, 0, 0,
            cnt, nullptr, tok, wt, CAP_);
}

// round 9
// speedup vs baseline: 1.1100x; 1.1100x over previous
#include <cuda_runtime.h>
#include <cuda_bf16.h>
#include <math.h>
#include <stdint.h>

#define B_    2
#define T_    1024
#define BT_   2048
#define DIM_  2048
#define NH_   16
#define DH_   128
#define DRH_  64
#define DC_   512
#define NE_   16
#define TOPK_ 4
#define MOE_  1024
#define MOESH_ 2048
#define CAP_  2048
#define QKD_  192   // DH + DRH

// ---------------- scratch (static device globals; no runtime alloc) ----------
// raw buffers
__device__ float g_kr [BT_*DRH_];
__device__ float g_S  [(size_t)B_*NH_*T_*T_];
__device__ float g_x1 [BT_*DIM_];
__device__ float g_xn [BT_*DIM_];
__device__ float g_a1 [BT_*MOESH_];
__device__ float g_a3 [BT_*MOESH_];
__device__ float g_r1 [(size_t)NE_*CAP_*MOE_];
__device__ float g_r2 [(size_t)NE_*CAP_*MOE_];
__device__ int   g_cnt[NE_];
__device__ int   g_tok[NE_*CAP_];
__device__ float g_wt [NE_*CAP_];
// split (hi,lo) buffers
__device__ __align__(16) uint2 g_h2  [BT_*DIM_];
__device__ __align__(16) uint2 g_ckv2[BT_*DC_];
__device__ __align__(16) uint2 g_cq2 [BT_*DC_];
__device__ __align__(16) uint2 g_Q2  [BT_*NH_*QKD_];
__device__ __align__(16) uint2 g_K2  [BT_*NH_*QKD_];
__device__ __align__(16) uint2 g_V2  [BT_*NH_*DH_];
__device__ __align__(16) uint2 g_O2  [BT_*NH_*DH_];
__device__ __align__(16) uint2 g_Wo2 [DIM_*NH_*DH_];
__device__ __align__(16) uint2 g_xn2 [BT_*DIM_];
__device__ __align__(16) uint2 g_a1s [BT_*MOESH_];
__device__ __align__(16) uint2 g_h1s [(size_t)NE_*CAP_*MOE_];
// split weights
__device__ __align__(16) uint2 g_wdkv2[DC_*DIM_];
__device__ __align__(16) uint2 g_wdq2 [DC_*DIM_];
__device__ __align__(16) uint2 g_wuk2 [DH_*NH_*DC_];
__device__ __align__(16) uint2 g_wuv2 [DH_*NH_*DC_];
__device__ __align__(16) uint2 g_wuq2 [DH_*NH_*DC_];
__device__ __align__(16) uint2 g_wqr2 [DRH_*NH_*DC_];
__device__ __align__(16) uint2 g_wkr2 [DRH_*DIM_];
__device__ __align__(16) uint2 g_w1s2 [DIM_*MOESH_];
__device__ __align__(16) uint2 g_w3s2 [DIM_*MOESH_];
__device__ __align__(16) uint2 g_w2s2 [MOESH_*DIM_];

__device__ __forceinline__ uint32_t f2t(float x) {
    uint32_t u; asm("cvt.rna.tf32.f32 %0, %1;" : "=r"(u) : "f"(x)); return u;
}
__device__ __forceinline__ uint2 split_hl(float x) {
    uint32_t h = f2t(x);
    uint32_t l = f2t(x - __uint_as_float(h));
    return make_uint2(h, l);
}
__device__ __forceinline__ void mma_tf32(float* c, const uint32_t* a, const uint32_t* b) {
    asm volatile("mma.sync.aligned.m16n8k8.row.col.f32.tf32.tf32.f32 "
        "{%0,%1,%2,%3}, {%4,%5,%6,%7}, {%8,%9}, {%0,%1,%2,%3};\n"
        : "+f"(c[0]), "+f"(c[1]), "+f"(c[2]), "+f"(c[3])
        : "r"(a[0]), "r"(a[1]), "r"(a[2]), "r"(a[3]), "r"(b[0]), "r"(b[1]));
}

// ---------------- 3xTF32 tensor-core GEMM -------------------------------------
// Double-buffered BK=8, hi/lo packed uint2 smem, R7 prefetch schedule.
// MODE 0: NN, 1: NT, 2: TN.  ASPLIT/BSPLIT: operand already (hi,lo)-packed.
struct GemmP {
    const void* A; const void* B; void* C; const float* res;
    int M, N, K, lda, ldb, ldc;
    float alpha;
    long long aO1, aO2, bO1, bO2, cO1, cO2;
    int zdiv, cap;
    const int* Mvec;
    const int* aRows;
    const int* cRows;
    const float* wRow;
    int causal, causalAV, outSplit;
};

template<int MODE, int ASPLIT, int BSPLIT>
__global__ __launch_bounds__(256, 2) void gemm_k(GemmP p) {
    __shared__ uint2 sA[2][8][132];
    __shared__ uint2 sB[2][8][132];

    int z = blockIdx.z, z1 = z / p.zdiv, z2 = z - z1 * p.zdiv;
    long long zA = z1 * p.aO1 + z2 * p.aO2;
    long long zB = z1 * p.bO1 + z2 * p.bO2;
    long long zC = z1 * p.cO1 + z2 * p.cO2;
    int M = p.Mvec ? p.Mvec[z] : p.M;
    int m0 = blockIdx.y * 128, n0 = blockIdx.x * 128;
    if (m0 >= M) return;
    if (MODE == 1 && p.causal && n0 >= m0 + 128) return;
    int tid = threadIdx.x, lane = tid & 31, warp = tid >> 5;
    int wm = (warp & 1) << 6, wn = (warp >> 1) << 5;
    int gid = lane >> 2, tg = lane & 3;

    // per-thread load descriptors (element offsets; zero-fill out of range)
    bool aValid; long long aOff; int aK, aM;
    if (MODE != 2) {
        int r = m0 + (tid >> 1);
        aValid = (r < M);
        long long ar = 0;
        if (aValid) ar = p.aRows ? (long long)p.aRows[(long long)z * p.cap + r]
                                 : (long long)r;
        aOff = zA + ar * (long long)p.lda + (tid & 1) * 4;
        aK = (tid & 1) * 4;  aM = tid >> 1;
    } else {
        int m = m0 + (tid & 31) * 4;
        aValid = (m < M);
        aOff = zA + (long long)(tid >> 5) * p.lda + (aValid ? m : 0);
        aK = tid >> 5;       aM = (tid & 31) * 4;
    }
    bool bValid; long long bOff; int bK, bM;
    if (MODE == 1) {
        int cl = n0 + (tid >> 1);
        bValid = (cl < p.N);
        bOff = zB + (bValid ? (long long)cl * p.ldb : 0) + (tid & 1) * 4;
        bK = (tid & 1) * 4;  bM = tid >> 1;
    } else {
        int n = n0 + (tid & 31) * 4;
        bValid = (n < p.N);
        bOff = zB + (long long)(tid >> 5) * p.ldb + (bValid ? n : 0);
        bK = tid >> 5;       bM = (tid & 31) * 4;
    }

    float acc[4][4][4];
#pragma unroll
    for (int mi = 0; mi < 4; mi++)
#pragma unroll
        for (int ni = 0; ni < 4; ni++)
#pragma unroll
            for (int q = 0; q < 4; q++) acc[mi][ni][q] = 0.f;

    const float4 z4 = make_float4(0.f, 0.f, 0.f, 0.f);
    const uint4  uz = make_uint4(0u, 0u, 0u, 0u);
    int kStart = (MODE == 2 && p.causalAV) ? m0 : 0;
    int nIter = (p.K - kStart) >> 3;

    auto loadA = [&](int chunk, float4& f, uint4& u0, uint4& u1) {
        int k = kStart + chunk * 8;
        long long ka = (MODE == 2) ? (long long)k * p.lda : (long long)k;
        if (ASPLIT) {
            const uint4* pa = (const uint4*)((const uint2*)p.A + aOff + ka);
            u0 = aValid ? pa[0] : uz;
            u1 = aValid ? pa[1] : uz;
        } else {
            f = aValid ? *(const float4*)((const float*)p.A + aOff + ka) : z4;
        }
    };
    auto loadB = [&](int chunk, float4& f, uint4& u0, uint4& u1) {
        int k = kStart + chunk * 8;
        long long kb = (MODE == 1) ? (long long)k : (long long)k * p.ldb;
        if (BSPLIT) {
            const uint4* pb = (const uint4*)((const uint2*)p.B + bOff + kb);
            u0 = bValid ? pb[0] : uz;
            u1 = bValid ? pb[1] : uz;
        } else {
            f = bValid ? *(const float4*)((const float*)p.B + bOff + kb) : z4;
        }
    };
    auto storeA = [&](int buf, const float4& f, const uint4& u0, const uint4& u1) {
        uint2 e[4];
        if (ASPLIT) {
            e[0] = make_uint2(u0.x, u0.y); e[1] = make_uint2(u0.z, u0.w);
            e[2] = make_uint2(u1.x, u1.y); e[3] = make_uint2(u1.z, u1.w);
        } else {
            const float* a4 = (const float*)&f;
#pragma unroll
            for (int j = 0; j < 4; j++) e[j] = split_hl(a4[j]);
        }
#pragma unroll
        for (int j = 0; j < 4; j++) {
            if (MODE == 2) sA[buf][aK][aM + j] = e[j];
            else           sA[buf][aK + j][aM] = e[j];
        }
    };
    auto storeB = [&](int buf, const float4& f, const uint4& u0, const uint4& u1) {
        uint2 e[4];
        if (BSPLIT) {
            e[0] = make_uint2(u0.x, u0.y); e[1] = make_uint2(u0.z, u0.w);
            e[2] = make_uint2(u1.x, u1.y); e[3] = make_uint2(u1.z, u1.w);
        } else {
            const float* b4 = (const float*)&f;
#pragma unroll
            for (int j = 0; j < 4; j++) e[j] = split_hl(b4[j]);
        }
#pragma unroll
        for (int j = 0; j < 4; j++) {
            if (MODE == 1) sB[buf][bK + j][bM] = e[j];
            else           sB[buf][bK][bM + j] = e[j];
        }
    };

    float4 fa, fb, nfa, nfb;
    uint4 ua0, ua1, ub0, ub1, nua0, nua1, nub0, nub1;
    loadA(0, fa, ua0, ua1); loadB(0, fb, ub0, ub1);
    storeA(0, fa, ua0, ua1); storeB(0, fb, ub0, ub1);
    __syncthreads();

    for (int it = 0; it < nIter; it++) {
        int cur = it & 1;
        if (it + 1 < nIter) {
            loadA(it + 1, nfa, nua0, nua1);
            loadB(it + 1, nfb, nub0, nub1);
        }

        uint2 vB0[4], vB1[4];
#pragma unroll
        for (int ni = 0; ni < 4; ni++) {
            int nb2 = wn + ni * 8 + gid;
            vB0[ni] = sB[cur][tg    ][nb2];
            vB1[ni] = sB[cur][tg + 4][nb2];
        }
#pragma unroll
        for (int mi = 0; mi < 4; mi++) {
            int mb = wm + mi * 16 + gid;
            uint2 a0 = sA[cur][tg    ][mb];
            uint2 a1 = sA[cur][tg    ][mb + 8];
            uint2 a2 = sA[cur][tg + 4][mb];
            uint2 a3 = sA[cur][tg + 4][mb + 8];
            uint32_t ah[4] = {a0.x, a1.x, a2.x, a3.x};
            uint32_t al[4] = {a0.y, a1.y, a2.y, a3.y};
#pragma unroll
            for (int ni = 0; ni < 4; ni++) {
                uint32_t bh[2] = {vB0[ni].x, vB1[ni].x};
                mma_tf32(acc[mi][ni], ah, bh);
            }
#pragma unroll
            for (int ni = 0; ni < 4; ni++) {
                uint32_t bh[2] = {vB0[ni].x, vB1[ni].x};
                mma_tf32(acc[mi][ni], al, bh);
            }
#pragma unroll
            for (int ni = 0; ni < 4; ni++) {
                uint32_t bl[2] = {vB0[ni].y, vB1[ni].y};
                mma_tf32(acc[mi][ni], ah, bl);
            }
        }

        if (it + 1 < nIter) {
            storeA(cur ^ 1, nfa, nua0, nua1);
            storeB(cur ^ 1, nfb, nub0, nub1);
        }
        __syncthreads();
    }

    // epilogue
#pragma unroll
    for (int mi = 0; mi < 4; mi++) {
#pragma unroll
        for (int half = 0; half < 2; half++) {
            int m = m0 + wm + mi * 16 + gid + half * 8;
            if (m >= M) continue;
            long long crow; float w = p.alpha;
            if (p.cRows) {
                crow = (long long)p.cRows[(long long)z * p.cap + m] * p.ldc;
                w *= p.wRow[(long long)z * p.cap + m];
            } else {
                crow = zC + (long long)m * p.ldc;
            }
#pragma unroll
            for (int ni = 0; ni < 4; ni++) {
                int n = n0 + wn + ni * 8 + tg * 2;
                if (n >= p.N) continue;
                float v0 = acc[mi][ni][half * 2 + 0] * w;
                float v1 = acc[mi][ni][half * 2 + 1] * w;
                if (p.cRows) {
                    atomicAdd(&((float*)p.C)[crow + n],     v0);
                    atomicAdd(&((float*)p.C)[crow + n + 1], v1);
                } else if (p.outSplit) {
                    uint2* Cs = (uint2*)p.C;
                    Cs[crow + n]     = split_hl(v0);
                    Cs[crow + n + 1] = split_hl(v1);
                } else {
                    float* Cf = (float*)p.C;
                    if (p.res) { v0 += p.res[crow + n]; v1 += p.res[crow + n + 1]; }
                    Cf[crow + n]     = v0;
                    Cf[crow + n + 1] = v1;
                }
            }
        }
    }
}

// ---------------- small fused kernels -----------------------------------------
__global__ void split_arr_k(const float4* __restrict__ in, uint4* __restrict__ out,
                            long long n4) {
    long long i = (long long)blockIdx.x * 256 + threadIdx.x;
    if (i >= n4) return;
    float4 v = in[i];
    uint2 a = split_hl(v.x), b = split_hl(v.y), c = split_hl(v.z), d = split_hl(v.w);
    out[2 * i]     = make_uint4(a.x, a.y, b.x, b.y);
    out[2 * i + 1] = make_uint4(c.x, c.y, d.x, d.y);
}

__global__ void rmsnorm_k(const float* __restrict__ x, const float* __restrict__ w,
                          float* __restrict__ oraw, uint2* __restrict__ osp) {
    int r = blockIdx.x;
    const float* xr = x + (long long)r * DIM_;
    float s = 0.f;
    for (int d = threadIdx.x; d < DIM_; d += 256) { float v = xr[d]; s += v * v; }
    __shared__ float red[256];
    red[threadIdx.x] = s; __syncthreads();
    for (int off = 128; off; off >>= 1) {
        if (threadIdx.x < off) red[threadIdx.x] += red[threadIdx.x + off];
        __syncthreads();
    }
    float inv = rsqrtf(red[0] / (float)DIM_ + 1e-6f);
    for (int d = threadIdx.x; d < DIM_; d += 256) {
        float v = w[d] * xr[d] * inv;
        if (oraw) oraw[(long long)r * DIM_ + d] = v;
        osp[(long long)r * DIM_ + d] = split_hl(v);
    }
}

__device__ __forceinline__ void rope_cs(int t, int j, float& c, float& s) {
    float freq = 1.0f / powf(10000.0f, (float)(2 * j) / (float)DRH_);
    float ang = (float)t * freq;
    sincosf(ang, &s, &c);
}

__global__ void rope_q_k(uint2* __restrict__ Q) {
    int idx = blockIdx.x;            // bt*NH + h
    int bt = idx / NH_;
    int t = bt % T_;
    int j = threadIdx.x;             // 0..31
    uint2* base = Q + (long long)idx * QKD_ + DH_;
    uint2 ur = base[j], ui = base[32 + j];
    float re = __uint_as_float(ur.x) + __uint_as_float(ur.y);
    float im = __uint_as_float(ui.x) + __uint_as_float(ui.y);
    float c, s; rope_cs(t, j, c, s);
    base[j]      = split_hl(re * c - im * s);
    base[32 + j] = split_hl(re * s + im * c);
}

__global__ void rope_kr_k(const float* __restrict__ kr, uint2* __restrict__ Kb) {
    int bt = blockIdx.x;
    int t = bt % T_;
    int j = threadIdx.x;             // 0..31
    float re = kr[bt * DRH_ + j], im = kr[bt * DRH_ + 32 + j];
    float c, s; rope_cs(t, j, c, s);
    uint2 s1 = split_hl((re * c - im * s) / (float)NH_);
    uint2 s2 = split_hl((re * s + im * c) / (float)NH_);
    for (int h = 0; h < NH_; h++) {
        uint2* base = Kb + ((long long)bt * NH_ + h) * QKD_ + DH_;
        base[j] = s1; base[32 + j] = s2;
    }
}

__global__ void softmax_k(float* __restrict__ S) {
    long long r = blockIdx.x;
    int t = (int)(r & (T_ - 1));
    float* row = S + r * (long long)T_;
    int n = t + 1;
    __shared__ float red[256];
    int tid = threadIdx.x;
    float mx = -INFINITY;
    for (int l = tid; l < n; l += 256) mx = fmaxf(mx, row[l]);
    red[tid] = mx; __syncthreads();
    for (int off = 128; off; off >>= 1) {
        if (tid < off) red[tid] = fmaxf(red[tid], red[tid + off]);
        __syncthreads();
    }
    mx = red[0]; __syncthreads();
    float sum = 0.f;
    for (int l = tid; l < n; l += 256) { float e = expf(row[l] - mx); row[l] = e; sum += e; }
    red[tid] = sum; __syncthreads();
    for (int off = 128; off; off >>= 1) {
        if (tid < off) red[tid] += red[tid + off];
        __syncthreads();
    }
    float inv = 1.f / red[0];
    for (int l = tid; l < T_; l += 256) row[l] = (l < n) ? row[l] * inv : 0.f;
}

__global__ void pack_wo_k(const float* __restrict__ wo, uint2* __restrict__ out) {
    long long i = (long long)blockIdx.x * 256 + threadIdx.x;  // d*2048 + h*128 + k
    if (i >= (long long)DIM_ * 2048) return;
    int d = (int)(i >> 11);
    int r = (int)(i & 2047);
    int h = r >> 7, k = r & 127;
    out[i] = split_hl(wo[(long long)d * 2048 + k * NH_ + h]);
}

__global__ void gate_k(const float* __restrict__ xn, const float* __restrict__ gw,
                       const float* __restrict__ gb, float* affOut,
                       int* __restrict__ cnt, int* __restrict__ tok,
                       float* __restrict__ wt) {
    int bt = blockIdx.x;
    __shared__ float xrow[DIM_];
    __shared__ float aff[NE_];
    int tid = threadIdx.x;
    for (int d = tid; d < DIM_; d += 256) xrow[d] = xn[(long long)bt * DIM_ + d];
    __syncthreads();
    int w = tid >> 5, lane = tid & 31;
    for (int e = w; e < NE_; e += 8) {
        float s = 0.f;
        const float* gr = gw + (long long)e * DIM_;
        for (int d = lane; d < DIM_; d += 32) s += xrow[d] * gr[d];
        for (int o = 16; o; o >>= 1) s += __shfl_xor_sync(0xffffffffu, s, o);
        if (lane == 0) aff[e] = 1.f / (1.f + expf(-s)) + gb[e];
    }
    __syncthreads();
    if (tid == 0) {
        if (affOut) for (int e = 0; e < NE_; e++) affOut[(long long)bt * NE_ + e] = aff[e];
        bool used[NE_] = {};
        float wv[TOPK_]; int wi[TOPK_]; float sum = 0.f;
        for (int k = 0; k < TOPK_; k++) {
            float best = -1e30f; int bi = 0;
            for (int e = 0; e < NE_; e++)
                if (!used[e] && aff[e] > best) { best = aff[e]; bi = e; }
            used[bi] = true; wv[k] = best; wi[k] = bi; sum += best;
        }
        for (int k = 0; k < TOPK_; k++) {
            int e = wi[k];
            int pos = atomicAdd(&cnt[e], 1);
            tok[e * CAP_ + pos] = bt;
            wt [e * CAP_ + pos] = wv[k] / sum;
        }
    }
}

__global__ void silumul_k(const float4* __restrict__ a, const float4* __restrict__ b,
                          uint4* __restrict__ o, long long n4) {
    long long i = (long long)blockIdx.x * 256 + threadIdx.x;
    if (i >= n4) return;
    float4 x = a[i], y = b[i];
    x.x *= y.x; x.y *= y.y; x.z *= y.z; x.w *= y.w;
    x.x = x.x / (1.f + expf(-x.x));
    x.y = x.y / (1.f + expf(-x.y));
    x.z = x.z / (1.f + expf(-x.z));
    x.w = x.w / (1.f + expf(-x.w));
    uint2 e0 = split_hl(x.x), e1 = split_hl(x.y), e2 = split_hl(x.z), e3 = split_hl(x.w);
    o[2 * i]     = make_uint4(e0.x, e0.y, e1.x, e1.y);
    o[2 * i + 1] = make_uint4(e2.x, e2.y, e3.x, e3.y);
}

__global__ void silumul_routed_k(const float4* __restrict__ a, const float4* __restrict__ b,
                                 uint4* __restrict__ o, const int* __restrict__ cnt) {
    long long i = (long long)blockIdx.x * 256 + threadIdx.x;
    long long el = i << 2;
    int e = (int)(el >> 21);
    int ri = (int)((el >> 10) & (CAP_ - 1));
    if (ri >= cnt[e]) return;
    float4 x = a[i], y = b[i];
    x.x *= y.x; x.y *= y.y; x.z *= y.z; x.w *= y.w;
    x.x = x.x / (1.f + expf(-x.x));
    x.y = x.y / (1.f + expf(-x.y));
    x.z = x.z / (1.f + expf(-x.z));
    x.w = x.w / (1.f + expf(-x.w));
    uint2 e0 = split_hl(x.x), e1 = split_hl(x.y), e2 = split_hl(x.z), e3 = split_hl(x.w);
    o[2 * i]     = make_uint4(e0.x, e0.y, e1.x, e1.y);
    o[2 * i + 1] = make_uint4(e2.x, e2.y, e3.x, e3.y);
}

// ---------------- host-side launch helpers ------------------------------------
template<int MODE, int AS, int BS>
static void gemm(const void* A, const void* B, void* C, int M, int N, int K,
                 int lda, int ldb, int ldc, float alpha, const float* res,
                 int nz, int zdiv,
                 long long a1, long long a2, long long b1, long long b2,
                 long long c1, long long c2,
                 const int* Mvec = nullptr, const int* aRows = nullptr,
                 const int* cRows = nullptr, const float* wRow = nullptr,
                 int cap = 0, int causal = 0, int causalAV = 0, int outSplit = 0) {
    GemmP p;
    p.A = A; p.B = B; p.C = C; p.res = res;
    p.M = M; p.N = N; p.K = K; p.lda = lda; p.ldb = ldb; p.ldc = ldc;
    p.alpha = alpha;
    p.aO1 = a1; p.aO2 = a2; p.bO1 = b1; p.bO2 = b2; p.cO1 = c1; p.cO2 = c2;
    p.zdiv = zdiv; p.cap = cap;
    p.Mvec = Mvec; p.aRows = aRows; p.cRows = cRows; p.wRow = wRow;
    p.causal = causal; p.causalAV = causalAV; p.outSplit = outSplit;
    dim3 g((N + 127) / 128, (M + 127) / 128, nz);
    gemm_k<MODE, AS, BS><<<g, 256>>>(p);
}

static void splitArr(const float* in, uint2* out, long long n) {
    long long n4 = n >> 2;
    split_arr_k<<<(unsigned)((n4 + 255) / 256), 256>>>((const float4*)in, (uint4*)out, n4);
}

extern "C" void kernel_launch(void* const* d_in, const int* in_sizes, int n_in,
                              void* d_out, int out_size) {
    const float* x      = (const float*)d_in[0];
    const float* attn_w = (const float*)d_in[3];
    const float* ffn_w  = (const float*)d_in[4];
    const float* gate_w = (const float*)d_in[5];
    const float* gate_b = (const float*)d_in[6];
    const float* w1s    = (const float*)d_in[7];
    const float* w2s    = (const float*)d_in[8];
    const float* w3s    = (const float*)d_in[9];
    const float* w1r    = (const float*)d_in[10];
    const float* w2r    = (const float*)d_in[11];
    const float* w3r    = (const float*)d_in[12];
    const float* wdkv   = (const float*)d_in[13];
    const float* wuk    = (const float*)d_in[14];
    const float* wuv    = (const float*)d_in[15];
    const float* wdq    = (const float*)d_in[16];
    const float* wuq    = (const float*)d_in[17];
    const float* wqr    = (const float*)d_in[18];
    const float* wkr    = (const float*)d_in[19];
    const float* wo     = (const float*)d_in[20];
    float* out = (float*)d_out;

    float *kr, *S, *x1, *xn, *a1, *a3, *r1, *r2, *wt;
    int *cnt, *tok;
    uint2 *h2, *ckv2, *cq2, *Q2, *K2, *V2, *O2, *Wo2, *xn2, *a1s, *h1s;
    uint2 *wdkv2, *wdq2, *wuk2, *wuv2, *wuq2, *wqr2, *wkr2, *w1s2, *w3s2, *w2s2;
    cudaGetSymbolAddress((void**)&kr,  g_kr);
    cudaGetSymbolAddress((void**)&S,   g_S);
    cudaGetSymbolAddress((void**)&x1,  g_x1);
    cudaGetSymbolAddress((void**)&xn,  g_xn);
    cudaGetSymbolAddress((void**)&a1,  g_a1);
    cudaGetSymbolAddress((void**)&a3,  g_a3);
    cudaGetSymbolAddress((void**)&r1,  g_r1);
    cudaGetSymbolAddress((void**)&r2,  g_r2);
    cudaGetSymbolAddress((void**)&cnt, g_cnt);
    cudaGetSymbolAddress((void**)&tok, g_tok);
    cudaGetSymbolAddress((void**)&wt,  g_wt);
    cudaGetSymbolAddress((void**)&h2,  g_h2);
    cudaGetSymbolAddress((void**)&ckv2, g_ckv2);
    cudaGetSymbolAddress((void**)&cq2, g_cq2);
    cudaGetSymbolAddress((void**)&Q2,  g_Q2);
    cudaGetSymbolAddress((void**)&K2,  g_K2);
    cudaGetSymbolAddress((void**)&V2,  g_V2);
    cudaGetSymbolAddress((void**)&O2,  g_O2);
    cudaGetSymbolAddress((void**)&Wo2, g_Wo2);
    cudaGetSymbolAddress((void**)&xn2, g_xn2);
    cudaGetSymbolAddress((void**)&a1s, g_a1s);
    cudaGetSymbolAddress((void**)&h1s, g_h1s);
    cudaGetSymbolAddress((void**)&wdkv2, g_wdkv2);
    cudaGetSymbolAddress((void**)&wdq2,  g_wdq2);
    cudaGetSymbolAddress((void**)&wuk2,  g_wuk2);
    cudaGetSymbolAddress((void**)&wuv2,  g_wuv2);
    cudaGetSymbolAddress((void**)&wuq2,  g_wuq2);
    cudaGetSymbolAddress((void**)&wqr2,  g_wqr2);
    cudaGetSymbolAddress((void**)&wkr2,  g_wkr2);
    cudaGetSymbolAddress((void**)&w1s2,  g_w1s2);
    cudaGetSymbolAddress((void**)&w3s2,  g_w3s2);
    cudaGetSymbolAddress((void**)&w2s2,  g_w2s2);

    // ---- weight pre-split (once per launch) ----
    splitArr(wdkv, wdkv2, (long long)DC_*DIM_);
    splitArr(wdq,  wdq2,  (long long)DC_*DIM_);
    splitArr(wuk,  wuk2,  (long long)DH_*NH_*DC_);
    splitArr(wuv,  wuv2,  (long long)DH_*NH_*DC_);
    splitArr(wuq,  wuq2,  (long long)DH_*NH_*DC_);
    splitArr(wqr,  wqr2,  (long long)DRH_*NH_*DC_);
    splitArr(wkr,  wkr2,  (long long)DRH_*DIM_);
    splitArr(w1s,  w1s2,  (long long)DIM_*MOESH_);
    splitArr(w3s,  w3s2,  (long long)DIM_*MOESH_);
    splitArr(w2s,  w2s2,  (long long)MOESH_*DIM_);
    pack_wo_k<<<(DIM_*2048 + 255)/256, 256>>>(wo, Wo2);

    // ---- attention ----
    rmsnorm_k<<<BT_, 256>>>(x, attn_w, nullptr, h2);
    gemm<1,1,1>(h2, wdkv2, ckv2, BT_, DC_, DIM_, DIM_, DIM_, DC_, 1.f, nullptr,
                1, 1, 0,0,0,0,0,0, nullptr,nullptr,nullptr,nullptr, 0,0,0, 1);
    gemm<1,1,1>(h2, wdq2,  cq2,  BT_, DC_, DIM_, DIM_, DIM_, DC_, 1.f, nullptr,
                1, 1, 0,0,0,0,0,0, nullptr,nullptr,nullptr,nullptr, 0,0,0, 1);
    gemm<1,1,1>(ckv2, wuk2, K2, BT_, DH_,  DC_, DC_, NH_*DC_, NH_*QKD_, 1.f, nullptr,
                NH_, NH_, 0,0, 0, DC_, 0, QKD_, nullptr,nullptr,nullptr,nullptr, 0,0,0, 1);
    gemm<1,1,1>(ckv2, wuv2, V2, BT_, DH_,  DC_, DC_, NH_*DC_, NH_*DH_,  1.f, nullptr,
                NH_, NH_, 0,0, 0, DC_, 0, DH_, nullptr,nullptr,nullptr,nullptr, 0,0,0, 1);
    gemm<1,1,1>(cq2, wuq2, Q2,  BT_, DH_,  DC_, DC_, NH_*DC_, NH_*QKD_, 1.f, nullptr,
                NH_, NH_, 0,0, 0, DC_, 0, QKD_, nullptr,nullptr,nullptr,nullptr, 0,0,0, 1);
    gemm<1,1,1>(cq2, wqr2, Q2 + DH_, BT_, DRH_, DC_, DC_, NH_*DC_, NH_*QKD_, 1.f, nullptr,
                NH_, NH_, 0,0, 0, DC_, 0, QKD_, nullptr,nullptr,nullptr,nullptr, 0,0,0, 1);
    gemm<1,1,1>(h2, wkr2, kr, BT_, DRH_, DIM_, DIM_, DIM_, DRH_, 1.f, nullptr,
                1, 1, 0,0,0,0,0,0);
    rope_q_k<<<BT_ * NH_, 32>>>(Q2);
    rope_kr_k<<<BT_, 32>>>(kr, K2);
    float scale = 1.0f / sqrtf((float)QKD_);
    gemm<1,1,1>(Q2, K2, S, T_, T_, QKD_, NH_*QKD_, NH_*QKD_, T_, scale, nullptr,
                B_*NH_, NH_,
                (long long)T_*NH_*QKD_, QKD_,
                (long long)T_*NH_*QKD_, QKD_,
                (long long)NH_*T_*T_, (long long)T_*T_,
                nullptr, nullptr, nullptr, nullptr, 0, /*causal=*/1);
    softmax_k<<<B_ * NH_ * T_, 256>>>(S);
    gemm<2,0,1>(S, V2, O2, T_, DH_, T_, T_, NH_*DH_, NH_*DH_, 1.f, nullptr,
                B_*NH_, NH_,
                (long long)NH_*T_*T_, (long long)T_*T_,
                (long long)T_*NH_*DH_, DH_,
                (long long)T_*NH_*DH_, DH_,
                nullptr, nullptr, nullptr, nullptr, 0, 0, /*causalAV=*/1, /*outSplit=*/1);
    gemm<1,1,1>(O2, Wo2, x1, BT_, DIM_, NH_*DH_, NH_*DH_, NH_*DH_, DIM_, 1.f, x,
                1, 1, 0,0,0,0,0,0);

    // ---- MoE ----
    rmsnorm_k<<<BT_, 256>>>(x1, ffn_w, xn, xn2);
    cudaMemsetAsync(cnt, 0, NE_ * sizeof(int));
    float* affOut = (out_size >= BT_*DIM_ + BT_*NE_) ? out + (long long)BT_*DIM_ : nullptr;
    gate_k<<<BT_, 256>>>(xn, gate_w, gate_b, affOut, cnt, tok, wt);
    gemm<0,1,1>(xn2, w1s2, a1, BT_, MOESH_, DIM_, DIM_, MOESH_, MOESH_, 1.f, nullptr,
                1,1, 0,0,0,0,0,0);
    gemm<0,1,1>(xn2, w3s2, a3, BT_, MOESH_, DIM_, DIM_, MOESH_, MOESH_, 1.f, nullptr,
                1,1, 0,0,0,0,0,0);
    silumul_k<<<((BT_*MOESH_/4) + 255)/256, 256>>>((const float4*)a1, (const float4*)a3,
                                                   (uint4*)a1s, (long long)BT_*MOESH_/4);
    gemm<0,1,1>(a1s, w2s2, out, BT_, DIM_, MOESH_, MOESH_, DIM_, DIM_, 1.f, x1,
                1,1, 0,0,0,0,0,0);
    gemm<0,1,0>(xn2, w1r, r1, CAP_, MOE_, DIM_, DIM_, MOE_, MOE_, 1.f, nullptr,
                NE_, NE_, 0,0, 0, (long long)DIM_*MOE_, 0, (long long)CAP_*MOE_,
                cnt, tok, nullptr, nullptr, CAP_);
    gemm<0,1,0>(xn2, w3r, r2, CAP_, MOE_, DIM_, DIM_, MOE_, MOE_, 1.f, nullptr,
                NE_, NE_, 0,0, 0, (long long)DIM_*MOE_, 0, (long long)CAP_*MOE_,
                cnt, tok, nullptr, nullptr, CAP_);
    silumul_routed_k<<<(((long long)NE_*CAP_*MOE_/4) + 255)/256, 256>>>(
        (const float4*)r1, (const float4*)r2, (uint4*)h1s, cnt);
    gemm<0,1,0>(h1s, w2r, out, CAP_, DIM_, MOE_, MOE_, DIM_, DIM_, 1.f, nullptr,
                NE_, NE_, 0, (long long)CAP_*MOE_, 0, (long long)MOE_*DIM_, 0, 0,
                cnt, nullptr, tok, wt, CAP_);
}

// round 10
// speedup vs baseline: 1.1699x; 1.0540x over previous
#include <cuda_runtime.h>
#include <cuda_bf16.h>
#include <math.h>
#include <stdint.h>

#define B_    2
#define T_    1024
#define BT_   2048
#define DIM_  2048
#define NH_   16
#define DH_   128
#define DRH_  64
#define DC_   512
#define NE_   16
#define TOPK_ 4
#define MOE_  1024
#define MOESH_ 2048
#define CAP_  2048
#define QKD_  192   // DH + DRH

// ---------------- scratch (static device globals; no runtime alloc) ----------
__device__ float g_kr [BT_*DRH_];
__device__ float g_S  [(size_t)B_*NH_*T_*T_];
__device__ float g_V  [BT_*NH_*DH_];
__device__ float g_x1 [BT_*DIM_];
__device__ float g_xn [BT_*DIM_];
__device__ float g_a1 [BT_*MOESH_];
__device__ float g_a3 [BT_*MOESH_];
__device__ float g_r1 [(size_t)NE_*CAP_*MOE_];
__device__ float g_r2 [(size_t)NE_*CAP_*MOE_];
__device__ int   g_cnt[NE_];
__device__ int   g_tok[NE_*CAP_];
__device__ float g_wt [NE_*CAP_];
// split (hi,lo) buffers
__device__ __align__(16) uint2 g_h2  [BT_*DIM_];
__device__ __align__(16) uint2 g_ckv2[BT_*DC_];
__device__ __align__(16) uint2 g_cq2 [BT_*DC_];
__device__ __align__(16) uint2 g_Q2  [BT_*NH_*QKD_];
__device__ __align__(16) uint2 g_K2  [BT_*NH_*QKD_];
__device__ __align__(16) uint2 g_O2  [BT_*NH_*DH_];
__device__ __align__(16) uint2 g_Wo2 [DIM_*NH_*DH_];
__device__ __align__(16) uint2 g_xn2 [BT_*DIM_];
__device__ __align__(16) uint2 g_a1s [BT_*MOESH_];
// split weights
__device__ __align__(16) uint2 g_wdkv2[DC_*DIM_];
__device__ __align__(16) uint2 g_wdq2 [DC_*DIM_];
__device__ __align__(16) uint2 g_wuk2 [DH_*NH_*DC_];
__device__ __align__(16) uint2 g_wuv2 [DH_*NH_*DC_];
__device__ __align__(16) uint2 g_wuq2 [DH_*NH_*DC_];
__device__ __align__(16) uint2 g_wqr2 [DRH_*NH_*DC_];
__device__ __align__(16) uint2 g_wkr2 [DRH_*DIM_];
__device__ __align__(16) uint2 g_w1s2 [DIM_*MOESH_];
__device__ __align__(16) uint2 g_w3s2 [DIM_*MOESH_];
__device__ __align__(16) uint2 g_w2s2 [MOESH_*DIM_];

__device__ __forceinline__ uint32_t f2t(float x) {
    uint32_t u; asm("cvt.rna.tf32.f32 %0, %1;" : "=r"(u) : "f"(x)); return u;
}
__device__ __forceinline__ uint2 split_hl(float x) {
    uint32_t h = f2t(x);
    uint32_t l = f2t(x - __uint_as_float(h));
    return make_uint2(h, l);
}
__device__ __forceinline__ void mma_tf32(float* c, const uint32_t* a, const uint32_t* b) {
    asm volatile("mma.sync.aligned.m16n8k8.row.col.f32.tf32.tf32.f32 "
        "{%0,%1,%2,%3}, {%4,%5,%6,%7}, {%8,%9}, {%0,%1,%2,%3};\n"
        : "+f"(c[0]), "+f"(c[1]), "+f"(c[2]), "+f"(c[3])
        : "r"(a[0]), "r"(a[1]), "r"(a[2]), "r"(a[3]), "r"(b[0]), "r"(b[1]));
}

struct GemmP {
    const void* A; const void* B; void* C; const float* res;
    int M, N, K, lda, ldb, ldc;
    float alpha;
    long long aO1, aO2, bO1, bO2, cO1, cO2;
    int zdiv, cap;
    const int* Mvec;
    const int* aRows;
    const int* cRows;
    const float* wRow;
    int causal, causalAV, outSplit;
};

// ============ cp.async GEMM: both operands pre-split uint2 =====================
// MODE 0: NN, 1: NT. 4-stage pipeline, 8B cp.async per element.
// smem per stage: A[8][132] uint2 (1056) + B[8][132] (1056) = 2112 uint2.
#define CA_STAGE_U2 2112
#define CA_SMEM_BYTES (4 * CA_STAGE_U2 * 8)

__device__ __forceinline__ void cp_async8(uint32_t saddr, const void* gaddr, int sz) {
    asm volatile("cp.async.ca.shared.global [%0], [%1], 8, %2;"
                 :: "r"(saddr), "l"(gaddr), "r"(sz) : "memory");
}

template<int MODE>
__global__ __launch_bounds__(256, 2) void gemm_ca(GemmP p) {
    extern __shared__ uint2 dyn[];
    uint32_t smemBase = (uint32_t)__cvta_generic_to_shared(dyn);

    int z = blockIdx.z, z1 = z / p.zdiv, z2 = z - z1 * p.zdiv;
    long long zA = z1 * p.aO1 + z2 * p.aO2;
    long long zB = z1 * p.bO1 + z2 * p.bO2;
    long long zC = z1 * p.cO1 + z2 * p.cO2;
    int m0 = blockIdx.y * 128, n0 = blockIdx.x * 128;
    if (MODE == 1 && p.causal && n0 >= m0 + 128) return;
    int tid = threadIdx.x, lane = tid & 31, warp = tid >> 5;
    int wm = (warp & 1) << 6, wn = (warp >> 1) << 5;
    int gid = lane >> 2, tg = lane & 3;

    // element descriptors: 4 per operand (1024 elems / 256 threads)
    long long gA[4]; uint32_t sAoff[4]; int szA[4];
    long long gB[4]; uint32_t sBoff[4]; int szB[4];
    long long strideB = (MODE == 1) ? 8 : (long long)8 * p.ldb;
#pragma unroll
    for (int i = 0; i < 4; i++) {
        int e = tid + 256 * i;
        int am = e >> 3, ak = e & 7;
        bool va = (m0 + am) < p.M;
        gA[i] = zA + (long long)(va ? (m0 + am) : 0) * p.lda + ak;
        sAoff[i] = (uint32_t)(ak * 132 + am) * 8;
        szA[i] = va ? 8 : 0;
        if (MODE == 1) {
            int bn = e >> 3, bk = e & 7;
            bool vb = (n0 + bn) < p.N;
            gB[i] = zB + (long long)(vb ? (n0 + bn) : 0) * p.ldb + bk;
            sBoff[i] = (uint32_t)(1056 + bk * 132 + bn) * 8;
            szB[i] = vb ? 8 : 0;
        } else {
            int bk = e >> 7, bn = e & 127;
            bool vb = (n0 + bn) < p.N;
            gB[i] = zB + (long long)bk * p.ldb + n0 + (vb ? bn : 0);
            sBoff[i] = (uint32_t)(1056 + bk * 132 + bn) * 8;
            szB[i] = vb ? 8 : 0;
        }
    }

    float acc[4][4][4];
#pragma unroll
    for (int mi = 0; mi < 4; mi++)
#pragma unroll
        for (int ni = 0; ni < 4; ni++)
#pragma unroll
            for (int q = 0; q < 4; q++) acc[mi][ni][q] = 0.f;

    int nIter = p.K >> 3;
    const uint2* Ag = (const uint2*)p.A;
    const uint2* Bg = (const uint2*)p.B;

    auto issue = [&](int stage, int chunk) {
        uint32_t base = smemBase + (uint32_t)stage * CA_STAGE_U2 * 8;
        long long ka = (long long)chunk * 8;
        long long kb = (long long)chunk * strideB;
#pragma unroll
        for (int i = 0; i < 4; i++)
            cp_async8(base + sAoff[i], Ag + gA[i] + ka, szA[i]);
#pragma unroll
        for (int i = 0; i < 4; i++)
            cp_async8(base + sBoff[i], Bg + gB[i] + kb, szB[i]);
    };

#pragma unroll
    for (int s = 0; s < 3; s++) {
        if (s < nIter) issue(s, s);
        asm volatile("cp.async.commit_group;" ::: "memory");
    }

    for (int it = 0; it < nIter; it++) {
        asm volatile("cp.async.wait_group 2;" ::: "memory");
        __syncthreads();
        if (it + 3 < nIter) issue((it + 3) & 3, it + 3);
        asm volatile("cp.async.commit_group;" ::: "memory");

        const uint2* sA = dyn + (it & 3) * CA_STAGE_U2;
        const uint2* sB = sA + 1056;
        uint2 vB0[4], vB1[4];
#pragma unroll
        for (int ni = 0; ni < 4; ni++) {
            int nb2 = wn + ni * 8 + gid;
            vB0[ni] = sB[tg * 132 + nb2];
            vB1[ni] = sB[(tg + 4) * 132 + nb2];
        }
#pragma unroll
        for (int mi = 0; mi < 4; mi++) {
            int mb = wm + mi * 16 + gid;
            uint2 a0 = sA[tg * 132 + mb];
            uint2 a1 = sA[tg * 132 + mb + 8];
            uint2 a2 = sA[(tg + 4) * 132 + mb];
            uint2 a3 = sA[(tg + 4) * 132 + mb + 8];
            uint32_t ah[4] = {a0.x, a1.x, a2.x, a3.x};
            uint32_t al[4] = {a0.y, a1.y, a2.y, a3.y};
#pragma unroll
            for (int ni = 0; ni < 4; ni++) {
                uint32_t bh[2] = {vB0[ni].x, vB1[ni].x};
                mma_tf32(acc[mi][ni], ah, bh);
            }
#pragma unroll
            for (int ni = 0; ni < 4; ni++) {
                uint32_t bh[2] = {vB0[ni].x, vB1[ni].x};
                mma_tf32(acc[mi][ni], al, bh);
            }
#pragma unroll
            for (int ni = 0; ni < 4; ni++) {
                uint32_t bl[2] = {vB0[ni].y, vB1[ni].y};
                mma_tf32(acc[mi][ni], ah, bl);
            }
        }
    }

    // epilogue
#pragma unroll
    for (int mi = 0; mi < 4; mi++) {
#pragma unroll
        for (int half = 0; half < 2; half++) {
            int m = m0 + wm + mi * 16 + gid + half * 8;
            if (m >= p.M) continue;
            long long crow = zC + (long long)m * p.ldc;
#pragma unroll
            for (int ni = 0; ni < 4; ni++) {
                int n = n0 + wn + ni * 8 + tg * 2;
                if (n >= p.N) continue;
                float v0 = acc[mi][ni][half * 2 + 0] * p.alpha;
                float v1 = acc[mi][ni][half * 2 + 1] * p.alpha;
                if (p.outSplit) {
                    uint2* Cs = (uint2*)p.C;
                    Cs[crow + n]     = split_hl(v0);
                    Cs[crow + n + 1] = split_hl(v1);
                } else {
                    float* Cf = (float*)p.C;
                    if (p.res) { v0 += p.res[crow + n]; v1 += p.res[crow + n + 1]; }
                    Cf[crow + n]     = v0;
                    Cf[crow + n + 1] = v1;
                }
            }
        }
    }
}

// ============ fallback GEMM (raw operands, R7 schedule) ========================
// MODE 0: NN, 2: TN. In-loop hi/lo conversion, double-buffered BK=8.
template<int MODE>
__global__ __launch_bounds__(256, 2) void gemm_k(GemmP p) {
    __shared__ uint2 sA[2][8][132];
    __shared__ uint2 sB[2][8][132];

    int z = blockIdx.z, z1 = z / p.zdiv, z2 = z - z1 * p.zdiv;
    const float* A  = (const float*)p.A + z1 * p.aO1 + z2 * p.aO2;
    const float* Bp = (const float*)p.B + z1 * p.bO1 + z2 * p.bO2;
    long long zC = z1 * p.cO1 + z2 * p.cO2;
    int M = p.Mvec ? p.Mvec[z] : p.M;
    int m0 = blockIdx.y * 128, n0 = blockIdx.x * 128;
    if (m0 >= M) return;
    int tid = threadIdx.x, lane = tid & 31, warp = tid >> 5;
    int wm = (warp & 1) << 6, wn = (warp >> 1) << 5;
    int gid = lane >> 2, tg = lane & 3;

    bool aValid; const float* aPtr; int aK, aM;
    if (MODE != 2) {
        int r = m0 + (tid >> 1);
        aValid = (r < M);
        long long ar = 0;
        if (aValid) ar = p.aRows ? (long long)p.aRows[(long long)z * p.cap + r]
                                 : (long long)r;
        aPtr = A + ar * (long long)p.lda + (tid & 1) * 4;
        aK = (tid & 1) * 4;  aM = tid >> 1;
    } else {
        int m = m0 + (tid & 31) * 4;
        aValid = (m < M);
        aPtr = A + (long long)(tid >> 5) * p.lda + (aValid ? m : 0);
        aK = tid >> 5;       aM = (tid & 31) * 4;
    }
    bool bValid; const float* bPtr; int bK, bM;
    {
        int n = n0 + (tid & 31) * 4;
        bValid = (n < p.N);
        bPtr = Bp + (long long)(tid >> 5) * p.ldb + (bValid ? n : 0);
        bK = tid >> 5;       bM = (tid & 31) * 4;
    }

    float acc[4][4][4];
#pragma unroll
    for (int mi = 0; mi < 4; mi++)
#pragma unroll
        for (int ni = 0; ni < 4; ni++)
#pragma unroll
            for (int q = 0; q < 4; q++) acc[mi][ni][q] = 0.f;

    const float4 z4 = make_float4(0.f, 0.f, 0.f, 0.f);
    int kStart = (MODE == 2 && p.causalAV) ? m0 : 0;
    int nIter = (p.K - kStart) >> 3;

    auto loadG = [&](int chunk, float4& oa, float4& ob) {
        int k = kStart + chunk * 8;
        long long ka = (MODE == 2) ? (long long)k * p.lda : (long long)k;
        long long kb = (long long)k * p.ldb;
        oa = aValid ? *(const float4*)(aPtr + ka) : z4;
        ob = bValid ? *(const float4*)(bPtr + kb) : z4;
    };
    auto storeS = [&](int buf, const float4& ia, const float4& ib) {
        const float* a4 = (const float*)&ia;
        const float* b4 = (const float*)&ib;
#pragma unroll
        for (int j = 0; j < 4; j++) {
            if (MODE == 2) sA[buf][aK][aM + j] = split_hl(a4[j]);
            else           sA[buf][aK + j][aM] = split_hl(a4[j]);
            sB[buf][bK][bM + j] = split_hl(b4[j]);
        }
    };

    float4 va, vb;
    loadG(0, va, vb);
    storeS(0, va, vb);
    __syncthreads();

    for (int it = 0; it < nIter; it++) {
        int cur = it & 1;
        float4 na = z4, nb = z4;
        if (it + 1 < nIter) loadG(it + 1, na, nb);

        uint2 vB0[4], vB1[4];
#pragma unroll
        for (int ni = 0; ni < 4; ni++) {
            int nb2 = wn + ni * 8 + gid;
            vB0[ni] = sB[cur][tg    ][nb2];
            vB1[ni] = sB[cur][tg + 4][nb2];
        }
#pragma unroll
        for (int mi = 0; mi < 4; mi++) {
            int mb = wm + mi * 16 + gid;
            uint2 a0 = sA[cur][tg    ][mb];
            uint2 a1 = sA[cur][tg    ][mb + 8];
            uint2 a2 = sA[cur][tg + 4][mb];
            uint2 a3 = sA[cur][tg + 4][mb + 8];
            uint32_t ah[4] = {a0.x, a1.x, a2.x, a3.x};
            uint32_t al[4] = {a0.y, a1.y, a2.y, a3.y};
#pragma unroll
            for (int ni = 0; ni < 4; ni++) {
                uint32_t bh[2] = {vB0[ni].x, vB1[ni].x};
                mma_tf32(acc[mi][ni], ah, bh);
            }
#pragma unroll
            for (int ni = 0; ni < 4; ni++) {
                uint32_t bh[2] = {vB0[ni].x, vB1[ni].x};
                mma_tf32(acc[mi][ni], al, bh);
            }
#pragma unroll
            for (int ni = 0; ni < 4; ni++) {
                uint32_t bl[2] = {vB0[ni].y, vB1[ni].y};
                mma_tf32(acc[mi][ni], ah, bl);
            }
        }

        if (it + 1 < nIter) storeS(cur ^ 1, na, nb);
        __syncthreads();
    }

#pragma unroll
    for (int mi = 0; mi < 4; mi++) {
#pragma unroll
        for (int half = 0; half < 2; half++) {
            int m = m0 + wm + mi * 16 + gid + half * 8;
            if (m >= M) continue;
            long long crow; float w = p.alpha;
            if (p.cRows) {
                crow = (long long)p.cRows[(long long)z * p.cap + m] * p.ldc;
                w *= p.wRow[(long long)z * p.cap + m];
            } else {
                crow = zC + (long long)m * p.ldc;
            }
#pragma unroll
            for (int ni = 0; ni < 4; ni++) {
                int n = n0 + wn + ni * 8 + tg * 2;
                if (n >= p.N) continue;
                float v0 = acc[mi][ni][half * 2 + 0] * w;
                float v1 = acc[mi][ni][half * 2 + 1] * w;
                if (p.cRows) {
                    atomicAdd(&((float*)p.C)[crow + n],     v0);
                    atomicAdd(&((float*)p.C)[crow + n + 1], v1);
                } else if (p.outSplit) {
                    uint2* Cs = (uint2*)p.C;
                    Cs[crow + n]     = split_hl(v0);
                    Cs[crow + n + 1] = split_hl(v1);
                } else {
                    float* Cf = (float*)p.C;
                    if (p.res) { v0 += p.res[crow + n]; v1 += p.res[crow + n + 1]; }
                    Cf[crow + n]     = v0;
                    Cf[crow + n + 1] = v1;
                }
            }
        }
    }
}

// ---------------- small fused kernels -----------------------------------------
__global__ void split_arr_k(const float4* __restrict__ in, uint4* __restrict__ out,
                            long long n4) {
    long long i = (long long)blockIdx.x * 256 + threadIdx.x;
    if (i >= n4) return;
    float4 v = in[i];
    uint2 a = split_hl(v.x), b = split_hl(v.y), c = split_hl(v.z), d = split_hl(v.w);
    out[2 * i]     = make_uint4(a.x, a.y, b.x, b.y);
    out[2 * i + 1] = make_uint4(c.x, c.y, d.x, d.y);
}

__global__ void rmsnorm_k(const float* __restrict__ x, const float* __restrict__ w,
                          float* __restrict__ oraw, uint2* __restrict__ osp) {
    int r = blockIdx.x;
    const float* xr = x + (long long)r * DIM_;
    float s = 0.f;
    for (int d = threadIdx.x; d < DIM_; d += 256) { float v = xr[d]; s += v * v; }
    __shared__ float red[256];
    red[threadIdx.x] = s; __syncthreads();
    for (int off = 128; off; off >>= 1) {
        if (threadIdx.x < off) red[threadIdx.x] += red[threadIdx.x + off];
        __syncthreads();
    }
    float inv = rsqrtf(red[0] / (float)DIM_ + 1e-6f);
    for (int d = threadIdx.x; d < DIM_; d += 256) {
        float v = w[d] * xr[d] * inv;
        if (oraw) oraw[(long long)r * DIM_ + d] = v;
        osp[(long long)r * DIM_ + d] = split_hl(v);
    }
}

__device__ __forceinline__ void rope_cs(int t, int j, float& c, float& s) {
    float freq = 1.0f / powf(10000.0f, (float)(2 * j) / (float)DRH_);
    float ang = (float)t * freq;
    sincosf(ang, &s, &c);
}

__global__ void rope_q_k(uint2* __restrict__ Q) {
    int idx = blockIdx.x;
    int bt = idx / NH_;
    int t = bt % T_;
    int j = threadIdx.x;
    uint2* base = Q + (long long)idx * QKD_ + DH_;
    uint2 ur = base[j], ui = base[32 + j];
    float re = __uint_as_float(ur.x) + __uint_as_float(ur.y);
    float im = __uint_as_float(ui.x) + __uint_as_float(ui.y);
    float c, s; rope_cs(t, j, c, s);
    base[j]      = split_hl(re * c - im * s);
    base[32 + j] = split_hl(re * s + im * c);
}

__global__ void rope_kr_k(const float* __restrict__ kr, uint2* __restrict__ Kb) {
    int bt = blockIdx.x;
    int t = bt % T_;
    int j = threadIdx.x;
    float re = kr[bt * DRH_ + j], im = kr[bt * DRH_ + 32 + j];
    float c, s; rope_cs(t, j, c, s);
    uint2 s1 = split_hl((re * c - im * s) / (float)NH_);
    uint2 s2 = split_hl((re * s + im * c) / (float)NH_);
    for (int h = 0; h < NH_; h++) {
        uint2* base = Kb + ((long long)bt * NH_ + h) * QKD_ + DH_;
        base[j] = s1; base[32 + j] = s2;
    }
}

__global__ void softmax_k(float* __restrict__ S) {
    long long r = blockIdx.x;
    int t = (int)(r & (T_ - 1));
    float* row = S + r * (long long)T_;
    int n = t + 1;
    __shared__ float red[256];
    int tid = threadIdx.x;
    float mx = -INFINITY;
    for (int l = tid; l < n; l += 256) mx = fmaxf(mx, row[l]);
    red[tid] = mx; __syncthreads();
    for (int off = 128; off; off >>= 1) {
        if (tid < off) red[tid] = fmaxf(red[tid], red[tid + off]);
        __syncthreads();
    }
    mx = red[0]; __syncthreads();
    float sum = 0.f;
    for (int l = tid; l < n; l += 256) { float e = expf(row[l] - mx); row[l] = e; sum += e; }
    red[tid] = sum; __syncthreads();
    for (int off = 128; off; off >>= 1) {
        if (tid < off) red[tid] += red[tid + off];
        __syncthreads();
    }
    float inv = 1.f / red[0];
    for (int l = tid; l < T_; l += 256) row[l] = (l < n) ? row[l] * inv : 0.f;
}

__global__ void pack_wo_k(const float* __restrict__ wo, uint2* __restrict__ out) {
    long long i = (long long)blockIdx.x * 256 + threadIdx.x;
    if (i >= (long long)DIM_ * 2048) return;
    int d = (int)(i >> 11);
    int r = (int)(i & 2047);
    int h = r >> 7, k = r & 127;
    out[i] = split_hl(wo[(long long)d * 2048 + k * NH_ + h]);
}

__global__ void gate_k(const float* __restrict__ xn, const float* __restrict__ gw,
                       const float* __restrict__ gb, float* affOut,
                       int* __restrict__ cnt, int* __restrict__ tok,
                       float* __restrict__ wt) {
    int bt = blockIdx.x;
    __shared__ float xrow[DIM_];
    __shared__ float aff[NE_];
    int tid = threadIdx.x;
    for (int d = tid; d < DIM_; d += 256) xrow[d] = xn[(long long)bt * DIM_ + d];
    __syncthreads();
    int w = tid >> 5, lane = tid & 31;
    for (int e = w; e < NE_; e += 8) {
        float s = 0.f;
        const float* gr = gw + (long long)e * DIM_;
        for (int d = lane; d < DIM_; d += 32) s += xrow[d] * gr[d];
        for (int o = 16; o; o >>= 1) s += __shfl_xor_sync(0xffffffffu, s, o);
        if (lane == 0) aff[e] = 1.f / (1.f + expf(-s)) + gb[e];
    }
    __syncthreads();
    if (tid == 0) {
        if (affOut) for (int e = 0; e < NE_; e++) affOut[(long long)bt * NE_ + e] = aff[e];
        bool used[NE_] = {};
        float wv[TOPK_]; int wi[TOPK_]; float sum = 0.f;
        for (int k = 0; k < TOPK_; k++) {
            float best = -1e30f; int bi = 0;
            for (int e = 0; e < NE_; e++)
                if (!used[e] && aff[e] > best) { best = aff[e]; bi = e; }
            used[bi] = true; wv[k] = best; wi[k] = bi; sum += best;
        }
        for (int k = 0; k < TOPK_; k++) {
            int e = wi[k];
            int pos = atomicAdd(&cnt[e], 1);
            tok[e * CAP_ + pos] = bt;
            wt [e * CAP_ + pos] = wv[k] / sum;
        }
    }
}

__global__ void silumul_k(const float4* __restrict__ a, const float4* __restrict__ b,
                          uint4* __restrict__ o, long long n4) {
    long long i = (long long)blockIdx.x * 256 + threadIdx.x;
    if (i >= n4) return;
    float4 x = a[i], y = b[i];
    x.x *= y.x; x.y *= y.y; x.z *= y.z; x.w *= y.w;
    x.x = x.x / (1.f + expf(-x.x));
    x.y = x.y / (1.f + expf(-x.y));
    x.z = x.z / (1.f + expf(-x.z));
    x.w = x.w / (1.f + expf(-x.w));
    uint2 e0 = split_hl(x.x), e1 = split_hl(x.y), e2 = split_hl(x.z), e3 = split_hl(x.w);
    o[2 * i]     = make_uint4(e0.x, e0.y, e1.x, e1.y);
    o[2 * i + 1] = make_uint4(e2.x, e2.y, e3.x, e3.y);
}

__global__ void silumul_routed_k(float4* __restrict__ a, const float4* __restrict__ b,
                                 const int* __restrict__ cnt) {
    long long i = (long long)blockIdx.x * 256 + threadIdx.x;
    long long el = i << 2;
    int e = (int)(el >> 21);
    int ri = (int)((el >> 10) & (CAP_ - 1));
    if (ri >= cnt[e]) return;
    float4 x = a[i], y = b[i];
    x.x *= y.x; x.y *= y.y; x.z *= y.z; x.w *= y.w;
    x.x = x.x / (1.f + expf(-x.x));
    x.y = x.y / (1.f + expf(-x.y));
    x.z = x.z / (1.f + expf(-x.z));
    x.w = x.w / (1.f + expf(-x.w));
    a[i] = x;
}

// ---------------- host-side launch helpers ------------------------------------
static GemmP mkP(const void* A, const void* B, void* C, int M, int N, int K,
                 int lda, int ldb, int ldc, float alpha, const float* res,
                 int zdiv, long long a1, long long a2, long long b1, long long b2,
                 long long c1, long long c2,
                 const int* Mvec, const int* aRows, const int* cRows,
                 const float* wRow, int cap, int causal, int causalAV, int outSplit) {
    GemmP p;
    p.A = A; p.B = B; p.C = C; p.res = res;
    p.M = M; p.N = N; p.K = K; p.lda = lda; p.ldb = ldb; p.ldc = ldc;
    p.alpha = alpha;
    p.aO1 = a1; p.aO2 = a2; p.bO1 = b1; p.bO2 = b2; p.cO1 = c1; p.cO2 = c2;
    p.zdiv = zdiv; p.cap = cap;
    p.Mvec = Mvec; p.aRows = aRows; p.cRows = cRows; p.wRow = wRow;
    p.causal = causal; p.causalAV = causalAV; p.outSplit = outSplit;
    return p;
}

template<int MODE>
static void gemmCA(const uint2* A, const uint2* B, void* C, int M, int N, int K,
                   int lda, int ldb, int ldc, float alpha, const float* res,
                   int nz, int zdiv,
                   long long a1, long long a2, long long b1, long long b2,
                   long long c1, long long c2,
                   int causal = 0, int outSplit = 0) {
    GemmP p = mkP(A, B, C, M, N, K, lda, ldb, ldc, alpha, res, zdiv,
                  a1, a2, b1, b2, c1, c2,
                  nullptr, nullptr, nullptr, nullptr, 0, causal, 0, outSplit);
    cudaFuncSetAttribute(gemm_ca<MODE>, cudaFuncAttributeMaxDynamicSharedMemorySize,
                         CA_SMEM_BYTES);
    dim3 g((N + 127) / 128, (M + 127) / 128, nz);
    gemm_ca<MODE><<<g, 256, CA_SMEM_BYTES>>>(p);
}

template<int MODE>
static void gemmRaw(const float* A, const float* B, void* C, int M, int N, int K,
                    int lda, int ldb, int ldc, float alpha, const float* res,
                    int nz, int zdiv,
                    long long a1, long long a2, long long b1, long long b2,
                    long long c1, long long c2,
                    const int* Mvec = nullptr, const int* aRows = nullptr,
                    const int* cRows = nullptr, const float* wRow = nullptr,
                    int cap = 0, int causalAV = 0, int outSplit = 0) {
    GemmP p = mkP(A, B, C, M, N, K, lda, ldb, ldc, alpha, res, zdiv,
                  a1, a2, b1, b2, c1, c2,
                  Mvec, aRows, cRows, wRow, cap, 0, causalAV, outSplit);
    dim3 g((N + 127) / 128, (M + 127) / 128, nz);
    gemm_k<MODE><<<g, 256>>>(p);
}

static void splitArr(const float* in, uint2* out, long long n) {
    long long n4 = n >> 2;
    split_arr_k<<<(unsigned)((n4 + 255) / 256), 256>>>((const float4*)in, (uint4*)out, n4);
}

extern "C" void kernel_launch(void* const* d_in, const int* in_sizes, int n_in,
                              void* d_out, int out_size) {
    const float* x      = (const float*)d_in[0];
    const float* attn_w = (const float*)d_in[3];
    const float* ffn_w  = (const float*)d_in[4];
    const float* gate_w = (const float*)d_in[5];
    const float* gate_b = (const float*)d_in[6];
    const float* w1s    = (const float*)d_in[7];
    const float* w2s    = (const float*)d_in[8];
    const float* w3s    = (const float*)d_in[9];
    const float* w1r    = (const float*)d_in[10];
    const float* w2r    = (const float*)d_in[11];
    const float* w3r    = (const float*)d_in[12];
    const float* wdkv   = (const float*)d_in[13];
    const float* wuk    = (const float*)d_in[14];
    const float* wuv    = (const float*)d_in[15];
    const float* wdq    = (const float*)d_in[16];
    const float* wuq    = (const float*)d_in[17];
    const float* wqr    = (const float*)d_in[18];
    const float* wkr    = (const float*)d_in[19];
    const float* wo     = (const float*)d_in[20];
    float* out = (float*)d_out;

    float *kr, *S, *V, *x1, *xn, *a1, *a3, *r1, *r2, *wt;
    int *cnt, *tok;
    uint2 *h2, *ckv2, *cq2, *Q2, *K2, *O2, *Wo2, *xn2, *a1s;
    uint2 *wdkv2, *wdq2, *wuk2, *wuv2, *wuq2, *wqr2, *wkr2, *w1s2, *w3s2, *w2s2;
    cudaGetSymbolAddress((void**)&kr,  g_kr);
    cudaGetSymbolAddress((void**)&S,   g_S);
    cudaGetSymbolAddress((void**)&V,   g_V);
    cudaGetSymbolAddress((void**)&x1,  g_x1);
    cudaGetSymbolAddress((void**)&xn,  g_xn);
    cudaGetSymbolAddress((void**)&a1,  g_a1);
    cudaGetSymbolAddress((void**)&a3,  g_a3);
    cudaGetSymbolAddress((void**)&r1,  g_r1);
    cudaGetSymbolAddress((void**)&r2,  g_r2);
    cudaGetSymbolAddress((void**)&cnt, g_cnt);
    cudaGetSymbolAddress((void**)&tok, g_tok);
    cudaGetSymbolAddress((void**)&wt,  g_wt);
    cudaGetSymbolAddress((void**)&h2,  g_h2);
    cudaGetSymbolAddress((void**)&ckv2, g_ckv2);
    cudaGetSymbolAddress((void**)&cq2, g_cq2);
    cudaGetSymbolAddress((void**)&Q2,  g_Q2);
    cudaGetSymbolAddress((void**)&K2,  g_K2);
    cudaGetSymbolAddress((void**)&O2,  g_O2);
    cudaGetSymbolAddress((void**)&Wo2, g_Wo2);
    cudaGetSymbolAddress((void**)&xn2, g_xn2);
    cudaGetSymbolAddress((void**)&a1s, g_a1s);
    cudaGetSymbolAddress((void**)&wdkv2, g_wdkv2);
    cudaGetSymbolAddress((void**)&wdq2,  g_wdq2);
    cudaGetSymbolAddress((void**)&wuk2,  g_wuk2);
    cudaGetSymbolAddress((void**)&wuv2,  g_wuv2);
    cudaGetSymbolAddress((void**)&wuq2,  g_wuq2);
    cudaGetSymbolAddress((void**)&wqr2,  g_wqr2);
    cudaGetSymbolAddress((void**)&wkr2,  g_wkr2);
    cudaGetSymbolAddress((void**)&w1s2,  g_w1s2);
    cudaGetSymbolAddress((void**)&w3s2,  g_w3s2);
    cudaGetSymbolAddress((void**)&w2s2,  g_w2s2);

    // ---- weight pre-split ----
    splitArr(wdkv, wdkv2, (long long)DC_*DIM_);
    splitArr(wdq,  wdq2,  (long long)DC_*DIM_);
    splitArr(wuk,  wuk2,  (long long)DH_*NH_*DC_);
    splitArr(wuv,  wuv2,  (long long)DH_*NH_*DC_);
    splitArr(wuq,  wuq2,  (long long)DH_*NH_*DC_);
    splitArr(wqr,  wqr2,  (long long)DRH_*NH_*DC_);
    splitArr(wkr,  wkr2,  (long long)DRH_*DIM_);
    splitArr(w1s,  w1s2,  (long long)DIM_*MOESH_);
    splitArr(w3s,  w3s2,  (long long)DIM_*MOESH_);
    splitArr(w2s,  w2s2,  (long long)MOESH_*DIM_);
    pack_wo_k<<<(DIM_*2048 + 255)/256, 256>>>(wo, Wo2);

    // ---- attention ----
    rmsnorm_k<<<BT_, 256>>>(x, attn_w, nullptr, h2);
    gemmCA<1>(h2, wdkv2, ckv2, BT_, DC_, DIM_, DIM_, DIM_, DC_, 1.f, nullptr,
              1, 1, 0,0,0,0,0,0, 0, 1);
    gemmCA<1>(h2, wdq2,  cq2,  BT_, DC_, DIM_, DIM_, DIM_, DC_, 1.f, nullptr,
              1, 1, 0,0,0,0,0,0, 0, 1);
    gemmCA<1>(ckv2, wuk2, K2, BT_, DH_, DC_, DC_, NH_*DC_, NH_*QKD_, 1.f, nullptr,
              NH_, NH_, 0,0, 0, DC_, 0, QKD_, 0, 1);
    gemmCA<1>(ckv2, wuv2, (void*)V, BT_, DH_, DC_, DC_, NH_*DC_, NH_*DH_, 1.f, nullptr,
              NH_, NH_, 0,0, 0, DC_, 0, DH_, 0, 0);
    gemmCA<1>(cq2, wuq2, Q2, BT_, DH_, DC_, DC_, NH_*DC_, NH_*QKD_, 1.f, nullptr,
              NH_, NH_, 0,0, 0, DC_, 0, QKD_, 0, 1);
    gemmCA<1>(cq2, wqr2, Q2 + DH_, BT_, DRH_, DC_, DC_, NH_*DC_, NH_*QKD_, 1.f, nullptr,
              NH_, NH_, 0,0, 0, DC_, 0, QKD_, 0, 1);
    gemmCA<1>(h2, wkr2, kr, BT_, DRH_, DIM_, DIM_, DIM_, DRH_, 1.f, nullptr,
              1, 1, 0,0,0,0,0,0, 0, 0);
    rope_q_k<<<BT_ * NH_, 32>>>(Q2);
    rope_kr_k<<<BT_, 32>>>(kr, K2);
    float scale = 1.0f / sqrtf((float)QKD_);
    gemmCA<1>(Q2, K2, S, T_, T_, QKD_, NH_*QKD_, NH_*QKD_, T_, scale, nullptr,
              B_*NH_, NH_,
              (long long)T_*NH_*QKD_, QKD_,
              (long long)T_*NH_*QKD_, QKD_,
              (long long)NH_*T_*T_, (long long)T_*T_,
              /*causal=*/1, 0);
    softmax_k<<<B_ * NH_ * T_, 256>>>(S);
    gemmRaw<2>(S, V, O2, T_, DH_, T_, T_, NH_*DH_, NH_*DH_, 1.f, nullptr,
               B_*NH_, NH_,
               (long long)NH_*T_*T_, (long long)T_*T_,
               (long long)T_*NH_*DH_, DH_,
               (long long)T_*NH_*DH_, DH_,
               nullptr, nullptr, nullptr, nullptr, 0, /*causalAV=*/1, /*outSplit=*/1);
    gemmCA<1>(O2, Wo2, x1, BT_, DIM_, NH_*DH_, NH_*DH_, NH_*DH_, DIM_, 1.f, x,
              1, 1, 0,0,0,0,0,0, 0, 0);

    // ---- MoE ----
    rmsnorm_k<<<BT_, 256>>>(x1, ffn_w, xn, xn2);
    cudaMemsetAsync(cnt, 0, NE_ * sizeof(int));
    float* affOut = (out_size >= BT_*DIM_ + BT_*NE_) ? out + (long long)BT_*DIM_ : nullptr;
    gate_k<<<BT_, 256>>>(xn, gate_w, gate_b, affOut, cnt, tok, wt);
    gemmCA<0>(xn2, w1s2, a1, BT_, MOESH_, DIM_, DIM_, MOESH_, MOESH_, 1.f, nullptr,
              1, 1, 0,0,0,0,0,0, 0, 0);
    gemmCA<0>(xn2, w3s2, a3, BT_, MOESH_, DIM_, DIM_, MOESH_, MOESH_, 1.f, nullptr,
              1, 1, 0,0,0,0,0,0, 0, 0);
    silumul_k<<<((BT_*MOESH_/4) + 255)/256, 256>>>((const float4*)a1, (const float4*)a3,
                                                   (uint4*)a1s, (long long)BT_*MOESH_/4);
    gemmCA<0>(a1s, w2s2, out, BT_, DIM_, MOESH_, MOESH_, DIM_, DIM_, 1.f, x1,
              1, 1, 0,0,0,0,0,0, 0, 0);
    // routed experts: exact R7 raw path
    gemmRaw<0>(xn, w1r, r1, CAP_, MOE_, DIM_, DIM_, MOE_, MOE_, 1.f, nullptr,
               NE_, NE_, 0,0, 0, (long long)DIM_*MOE_, 0, (long long)CAP_*MOE_,
               cnt, tok, nullptr, nullptr, CAP_);
    gemmRaw<0>(xn, w3r, r2, CAP_, MOE_, DIM_, DIM_, MOE_, MOE_, 1.f, nullptr,
               NE_, NE_, 0,0, 0, (long long)DIM_*MOE_, 0, (long long)CAP_*MOE_,
               cnt, tok, nullptr, nullptr, CAP_);
    silumul_routed_k<<<(((long long)NE_*CAP_*MOE_/4) + 255)/256, 256>>>(
        (float4*)r1, (const float4*)r2, cnt);
    gemmRaw<0>(r1, w2r, out, CAP_, DIM_, MOE_, MOE_, DIM_, DIM_, 1.f, nullptr,
               NE_, NE_, 0, (long long)CAP_*MOE_, 0, (long long)MOE_*DIM_, 0, 0,
               cnt, nullptr, tok, wt, CAP_);
}

// round 11
// speedup vs baseline: 1.2912x; 1.1037x over previous
#include <cuda_runtime.h>
#include <cuda_bf16.h>
#include <math.h>
#include <stdint.h>

#define B_    2
#define T_    1024
#define BT_   2048
#define DIM_  2048
#define NH_   16
#define DH_   128
#define DRH_  64
#define DC_   512
#define NE_   16
#define TOPK_ 4
#define MOE_  1024
#define MOESH_ 2048
#define CAP_  2048
#define QKD_  192   // DH + DRH
#define NCDQ_ 1088  // DC + DC + DRH  (merged dkv|dq|kr output width)

// ---------------- scratch (static device globals; no runtime alloc) ----------
__device__ float g_S  [(size_t)B_*NH_*T_*T_];
__device__ float g_V  [BT_*NH_*DH_];
__device__ float g_x1 [BT_*DIM_];
__device__ float g_xn [BT_*DIM_];
__device__ float g_a13[(size_t)BT_*2*MOESH_];
__device__ float g_r1 [(size_t)NE_*CAP_*MOE_];
__device__ float g_r2 [(size_t)NE_*CAP_*MOE_];
__device__ float g_pk [2][(size_t)BT_*NCDQ_];
__device__ int   g_cnt[NE_];
__device__ int   g_tok[NE_*CAP_];
__device__ float g_wt [NE_*CAP_];
// split (hi,lo) buffers
__device__ __align__(16) uint2 g_h2  [BT_*DIM_];
__device__ __align__(16) uint2 g_cdq2[(size_t)BT_*NCDQ_];
__device__ __align__(16) uint2 g_Q2  [BT_*NH_*QKD_];
__device__ __align__(16) uint2 g_K2  [BT_*NH_*QKD_];
__device__ __align__(16) uint2 g_O2  [BT_*NH_*DH_];
__device__ __align__(16) uint2 g_Wo2 [DIM_*NH_*DH_];
__device__ __align__(16) uint2 g_xn2 [BT_*DIM_];
__device__ __align__(16) uint2 g_a1s [BT_*MOESH_];
// split weights
__device__ __align__(16) uint2 g_wA2  [(size_t)NCDQ_*DIM_];   // [dkv|dq|kr] rows
__device__ __align__(16) uint2 g_wuk2 [DH_*NH_*DC_];
__device__ __align__(16) uint2 g_wuv2 [DH_*NH_*DC_];
__device__ __align__(16) uint2 g_wuq2 [DH_*NH_*DC_];
__device__ __align__(16) uint2 g_wqr2 [DRH_*NH_*DC_];
__device__ __align__(16) uint2 g_w13s2[(size_t)DIM_*2*MOESH_]; // [k][w1s|w3s]
__device__ __align__(16) uint2 g_w2s2 [MOESH_*DIM_];

__device__ __forceinline__ uint32_t f2t(float x) {
    uint32_t u; asm("cvt.rna.tf32.f32 %0, %1;" : "=r"(u) : "f"(x)); return u;
}
__device__ __forceinline__ uint2 split_hl(float x) {
    uint32_t h = f2t(x);
    uint32_t l = f2t(x - __uint_as_float(h));
    return make_uint2(h, l);
}
__device__ __forceinline__ void mma_tf32(float* c, const uint32_t* a, const uint32_t* b) {
    asm volatile("mma.sync.aligned.m16n8k8.row.col.f32.tf32.tf32.f32 "
        "{%0,%1,%2,%3}, {%4,%5,%6,%7}, {%8,%9}, {%0,%1,%2,%3};\n"
        : "+f"(c[0]), "+f"(c[1]), "+f"(c[2]), "+f"(c[3])
        : "r"(a[0]), "r"(a[1]), "r"(a[2]), "r"(a[3]), "r"(b[0]), "r"(b[1]));
}

struct GemmP {
    const void* A; const void* B; void* C; const float* res;
    int M, N, K, lda, ldb, ldc;
    float alpha;
    long long aO1, aO2, bO1, bO2, cO1, cO2;
    int zdiv, cap;
    const int* Mvec;
    const int* aRows;
    const int* cRows;
    const float* wRow;
    int causal, causalAV, outSplit;
};

// ============ cp.async GEMM: both operands pre-split uint2 =====================
#define CA_STAGE_U2 2112
#define CA_SMEM_BYTES (4 * CA_STAGE_U2 * 8)

__device__ __forceinline__ void cp_async8(uint32_t saddr, const void* gaddr, int sz) {
    asm volatile("cp.async.ca.shared.global [%0], [%1], 8, %2;"
                 :: "r"(saddr), "l"(gaddr), "r"(sz) : "memory");
}

template<int MODE>
__global__ __launch_bounds__(256, 2) void gemm_ca(GemmP p) {
    extern __shared__ uint2 dyn[];
    uint32_t smemBase = (uint32_t)__cvta_generic_to_shared(dyn);

    int z = blockIdx.z, z1 = z / p.zdiv, z2 = z - z1 * p.zdiv;
    long long zA = z1 * p.aO1 + z2 * p.aO2;
    long long zB = z1 * p.bO1 + z2 * p.bO2;
    long long zC = z1 * p.cO1 + z2 * p.cO2;
    int m0 = blockIdx.y * 128, n0 = blockIdx.x * 128;
    if (MODE == 1 && p.causal && n0 >= m0 + 128) return;
    int tid = threadIdx.x, lane = tid & 31, warp = tid >> 5;
    int wm = (warp & 1) << 6, wn = (warp >> 1) << 5;
    int gid = lane >> 2, tg = lane & 3;

    long long gA[4]; uint32_t sAoff[4]; int szA[4];
    long long gB[4]; uint32_t sBoff[4]; int szB[4];
    long long strideB = (MODE == 1) ? 8 : (long long)8 * p.ldb;
#pragma unroll
    for (int i = 0; i < 4; i++) {
        int e = tid + 256 * i;
        int am = e >> 3, ak = e & 7;
        bool va = (m0 + am) < p.M;
        gA[i] = zA + (long long)(va ? (m0 + am) : 0) * p.lda + ak;
        sAoff[i] = (uint32_t)(ak * 132 + am) * 8;
        szA[i] = va ? 8 : 0;
        if (MODE == 1) {
            int bn = e >> 3, bk = e & 7;
            bool vb = (n0 + bn) < p.N;
            gB[i] = zB + (long long)(vb ? (n0 + bn) : 0) * p.ldb + bk;
            sBoff[i] = (uint32_t)(1056 + bk * 132 + bn) * 8;
            szB[i] = vb ? 8 : 0;
        } else {
            int bk = e >> 7, bn = e & 127;
            bool vb = (n0 + bn) < p.N;
            gB[i] = zB + (long long)bk * p.ldb + n0 + (vb ? bn : 0);
            sBoff[i] = (uint32_t)(1056 + bk * 132 + bn) * 8;
            szB[i] = vb ? 8 : 0;
        }
    }

    float acc[4][4][4];
#pragma unroll
    for (int mi = 0; mi < 4; mi++)
#pragma unroll
        for (int ni = 0; ni < 4; ni++)
#pragma unroll
            for (int q = 0; q < 4; q++) acc[mi][ni][q] = 0.f;

    int nIter = p.K >> 3;
    const uint2* Ag = (const uint2*)p.A;
    const uint2* Bg = (const uint2*)p.B;

    auto issue = [&](int stage, int chunk) {
        uint32_t base = smemBase + (uint32_t)stage * CA_STAGE_U2 * 8;
        long long ka = (long long)chunk * 8;
        long long kb = (long long)chunk * strideB;
#pragma unroll
        for (int i = 0; i < 4; i++)
            cp_async8(base + sAoff[i], Ag + gA[i] + ka, szA[i]);
#pragma unroll
        for (int i = 0; i < 4; i++)
            cp_async8(base + sBoff[i], Bg + gB[i] + kb, szB[i]);
    };

#pragma unroll
    for (int s = 0; s < 3; s++) {
        if (s < nIter) issue(s, s);
        asm volatile("cp.async.commit_group;" ::: "memory");
    }

    for (int it = 0; it < nIter; it++) {
        asm volatile("cp.async.wait_group 2;" ::: "memory");
        __syncthreads();
        if (it + 3 < nIter) issue((it + 3) & 3, it + 3);
        asm volatile("cp.async.commit_group;" ::: "memory");

        const uint2* sA = dyn + (it & 3) * CA_STAGE_U2;
        const uint2* sB = sA + 1056;
        uint2 vB0[4], vB1[4];
#pragma unroll
        for (int ni = 0; ni < 4; ni++) {
            int nb2 = wn + ni * 8 + gid;
            vB0[ni] = sB[tg * 132 + nb2];
            vB1[ni] = sB[(tg + 4) * 132 + nb2];
        }
#pragma unroll
        for (int mi = 0; mi < 4; mi++) {
            int mb = wm + mi * 16 + gid;
            uint2 a0 = sA[tg * 132 + mb];
            uint2 a1 = sA[tg * 132 + mb + 8];
            uint2 a2 = sA[(tg + 4) * 132 + mb];
            uint2 a3 = sA[(tg + 4) * 132 + mb + 8];
            uint32_t ah[4] = {a0.x, a1.x, a2.x, a3.x};
            uint32_t al[4] = {a0.y, a1.y, a2.y, a3.y};
#pragma unroll
            for (int ni = 0; ni < 4; ni++) {
                uint32_t bh[2] = {vB0[ni].x, vB1[ni].x};
                mma_tf32(acc[mi][ni], ah, bh);
            }
#pragma unroll
            for (int ni = 0; ni < 4; ni++) {
                uint32_t bh[2] = {vB0[ni].x, vB1[ni].x};
                mma_tf32(acc[mi][ni], al, bh);
            }
#pragma unroll
            for (int ni = 0; ni < 4; ni++) {
                uint32_t bl[2] = {vB0[ni].y, vB1[ni].y};
                mma_tf32(acc[mi][ni], ah, bl);
            }
        }
    }

#pragma unroll
    for (int mi = 0; mi < 4; mi++) {
#pragma unroll
        for (int half = 0; half < 2; half++) {
            int m = m0 + wm + mi * 16 + gid + half * 8;
            if (m >= p.M) continue;
            long long crow = zC + (long long)m * p.ldc;
#pragma unroll
            for (int ni = 0; ni < 4; ni++) {
                int n = n0 + wn + ni * 8 + tg * 2;
                if (n >= p.N) continue;
                float v0 = acc[mi][ni][half * 2 + 0] * p.alpha;
                float v1 = acc[mi][ni][half * 2 + 1] * p.alpha;
                if (p.outSplit) {
                    uint2* Cs = (uint2*)p.C;
                    Cs[crow + n]     = split_hl(v0);
                    Cs[crow + n + 1] = split_hl(v1);
                } else {
                    float* Cf = (float*)p.C;
                    if (p.res) { v0 += p.res[crow + n]; v1 += p.res[crow + n + 1]; }
                    Cf[crow + n]     = v0;
                    Cf[crow + n + 1] = v1;
                }
            }
        }
    }
}

// ============ fallback GEMM (raw operands, R7 schedule) ========================
template<int MODE>
__global__ __launch_bounds__(256, 2) void gemm_k(GemmP p) {
    __shared__ uint2 sA[2][8][132];
    __shared__ uint2 sB[2][8][132];

    int z = blockIdx.z, z1 = z / p.zdiv, z2 = z - z1 * p.zdiv;
    const float* A  = (const float*)p.A + z1 * p.aO1 + z2 * p.aO2;
    const float* Bp = (const float*)p.B + z1 * p.bO1 + z2 * p.bO2;
    long long zC = z1 * p.cO1 + z2 * p.cO2;
    int M = p.Mvec ? p.Mvec[z] : p.M;
    int m0 = blockIdx.y * 128, n0 = blockIdx.x * 128;
    if (m0 >= M) return;
    int tid = threadIdx.x, lane = tid & 31, warp = tid >> 5;
    int wm = (warp & 1) << 6, wn = (warp >> 1) << 5;
    int gid = lane >> 2, tg = lane & 3;

    bool aValid; const float* aPtr; int aK, aM;
    if (MODE != 2) {
        int r = m0 + (tid >> 1);
        aValid = (r < M);
        long long ar = 0;
        if (aValid) ar = p.aRows ? (long long)p.aRows[(long long)z * p.cap + r]
                                 : (long long)r;
        aPtr = A + ar * (long long)p.lda + (tid & 1) * 4;
        aK = (tid & 1) * 4;  aM = tid >> 1;
    } else {
        int m = m0 + (tid & 31) * 4;
        aValid = (m < M);
        aPtr = A + (long long)(tid >> 5) * p.lda + (aValid ? m : 0);
        aK = tid >> 5;       aM = (tid & 31) * 4;
    }
    bool bValid; const float* bPtr; int bK, bM;
    {
        int n = n0 + (tid & 31) * 4;
        bValid = (n < p.N);
        bPtr = Bp + (long long)(tid >> 5) * p.ldb + (bValid ? n : 0);
        bK = tid >> 5;       bM = (tid & 31) * 4;
    }

    float acc[4][4][4];
#pragma unroll
    for (int mi = 0; mi < 4; mi++)
#pragma unroll
        for (int ni = 0; ni < 4; ni++)
#pragma unroll
            for (int q = 0; q < 4; q++) acc[mi][ni][q] = 0.f;

    const float4 z4 = make_float4(0.f, 0.f, 0.f, 0.f);
    int kStart = (MODE == 2 && p.causalAV) ? m0 : 0;
    int nIter = (p.K - kStart) >> 3;

    auto loadG = [&](int chunk, float4& oa, float4& ob) {
        int k = kStart + chunk * 8;
        long long ka = (MODE == 2) ? (long long)k * p.lda : (long long)k;
        long long kb = (long long)k * p.ldb;
        oa = aValid ? *(const float4*)(aPtr + ka) : z4;
        ob = bValid ? *(const float4*)(bPtr + kb) : z4;
    };
    auto storeS = [&](int buf, const float4& ia, const float4& ib) {
        const float* a4 = (const float*)&ia;
        const float* b4 = (const float*)&ib;
#pragma unroll
        for (int j = 0; j < 4; j++) {
            if (MODE == 2) sA[buf][aK][aM + j] = split_hl(a4[j]);
            else           sA[buf][aK + j][aM] = split_hl(a4[j]);
            sB[buf][bK][bM + j] = split_hl(b4[j]);
        }
    };

    float4 va, vb;
    loadG(0, va, vb);
    storeS(0, va, vb);
    __syncthreads();

    for (int it = 0; it < nIter; it++) {
        int cur = it & 1;
        float4 na = z4, nb = z4;
        if (it + 1 < nIter) loadG(it + 1, na, nb);

        uint2 vB0[4], vB1[4];
#pragma unroll
        for (int ni = 0; ni < 4; ni++) {
            int nb2 = wn + ni * 8 + gid;
            vB0[ni] = sB[cur][tg    ][nb2];
            vB1[ni] = sB[cur][tg + 4][nb2];
        }
#pragma unroll
        for (int mi = 0; mi < 4; mi++) {
            int mb = wm + mi * 16 + gid;
            uint2 a0 = sA[cur][tg    ][mb];
            uint2 a1 = sA[cur][tg    ][mb + 8];
            uint2 a2 = sA[cur][tg + 4][mb];
            uint2 a3 = sA[cur][tg + 4][mb + 8];
            uint32_t ah[4] = {a0.x, a1.x, a2.x, a3.x};
            uint32_t al[4] = {a0.y, a1.y, a2.y, a3.y};
#pragma unroll
            for (int ni = 0; ni < 4; ni++) {
                uint32_t bh[2] = {vB0[ni].x, vB1[ni].x};
                mma_tf32(acc[mi][ni], ah, bh);
            }
#pragma unroll
            for (int ni = 0; ni < 4; ni++) {
                uint32_t bh[2] = {vB0[ni].x, vB1[ni].x};
                mma_tf32(acc[mi][ni], al, bh);
            }
#pragma unroll
            for (int ni = 0; ni < 4; ni++) {
                uint32_t bl[2] = {vB0[ni].y, vB1[ni].y};
                mma_tf32(acc[mi][ni], ah, bl);
            }
        }

        if (it + 1 < nIter) storeS(cur ^ 1, na, nb);
        __syncthreads();
    }

#pragma unroll
    for (int mi = 0; mi < 4; mi++) {
#pragma unroll
        for (int half = 0; half < 2; half++) {
            int m = m0 + wm + mi * 16 + gid + half * 8;
            if (m >= M) continue;
            long long crow; float w = p.alpha;
            if (p.cRows) {
                crow = (long long)p.cRows[(long long)z * p.cap + m] * p.ldc;
                w *= p.wRow[(long long)z * p.cap + m];
            } else {
                crow = zC + (long long)m * p.ldc;
            }
#pragma unroll
            for (int ni = 0; ni < 4; ni++) {
                int n = n0 + wn + ni * 8 + tg * 2;
                if (n >= p.N) continue;
                float v0 = acc[mi][ni][half * 2 + 0] * w;
                float v1 = acc[mi][ni][half * 2 + 1] * w;
                if (p.cRows) {
                    atomicAdd(&((float*)p.C)[crow + n],     v0);
                    atomicAdd(&((float*)p.C)[crow + n + 1], v1);
                } else if (p.outSplit) {
                    uint2* Cs = (uint2*)p.C;
                    Cs[crow + n]     = split_hl(v0);
                    Cs[crow + n + 1] = split_hl(v1);
                } else {
                    float* Cf = (float*)p.C;
                    if (p.res) { v0 += p.res[crow + n]; v1 += p.res[crow + n + 1]; }
                    Cf[crow + n]     = v0;
                    Cf[crow + n + 1] = v1;
                }
            }
        }
    }
}

// ---------------- small fused kernels -----------------------------------------
__global__ void split_arr_k(const float4* __restrict__ in, uint4* __restrict__ out,
                            long long n4) {
    long long i = (long long)blockIdx.x * 256 + threadIdx.x;
    if (i >= n4) return;
    float4 v = in[i];
    uint2 a = split_hl(v.x), b = split_hl(v.y), c = split_hl(v.z), d = split_hl(v.w);
    out[2 * i]     = make_uint4(a.x, a.y, b.x, b.y);
    out[2 * i + 1] = make_uint4(c.x, c.y, d.x, d.y);
}

// strided split-pack: out[row*ldout + colOff + col] = split(in[row*ldin + col])
__global__ void split_pack_k(const float* __restrict__ in, uint2* __restrict__ out,
                             long long total, int ldin, int ldout, int colOff) {
    long long i = (long long)blockIdx.x * 256 + threadIdx.x;
    if (i >= total) return;
    long long row = i / ldin;
    int col = (int)(i - row * ldin);
    out[row * ldout + colOff + col] = split_hl(in[i]);
}

// sum 2 split-K partials, write split
__global__ void reduce_split_k(const float* __restrict__ p0, const float* __restrict__ p1,
                               uint2* __restrict__ out, long long n) {
    long long i = (long long)blockIdx.x * 256 + threadIdx.x;
    if (i >= n) return;
    out[i] = split_hl(p0[i] + p1[i]);
}

__global__ void rmsnorm_k(const float* __restrict__ x, const float* __restrict__ w,
                          float* __restrict__ oraw, uint2* __restrict__ osp) {
    int r = blockIdx.x;
    const float* xr = x + (long long)r * DIM_;
    float s = 0.f;
    for (int d = threadIdx.x; d < DIM_; d += 256) { float v = xr[d]; s += v * v; }
    __shared__ float red[256];
    red[threadIdx.x] = s; __syncthreads();
    for (int off = 128; off; off >>= 1) {
        if (threadIdx.x < off) red[threadIdx.x] += red[threadIdx.x + off];
        __syncthreads();
    }
    float inv = rsqrtf(red[0] / (float)DIM_ + 1e-6f);
    for (int d = threadIdx.x; d < DIM_; d += 256) {
        float v = w[d] * xr[d] * inv;
        if (oraw) oraw[(long long)r * DIM_ + d] = v;
        osp[(long long)r * DIM_ + d] = split_hl(v);
    }
}

__device__ __forceinline__ void rope_cs(int t, int j, float& c, float& s) {
    float freq = 1.0f / powf(10000.0f, (float)(2 * j) / (float)DRH_);
    float ang = (float)t * freq;
    sincosf(ang, &s, &c);
}

__global__ void rope_q_k(uint2* __restrict__ Q) {
    int idx = blockIdx.x;
    int bt = idx / NH_;
    int t = bt % T_;
    int j = threadIdx.x;
    uint2* base = Q + (long long)idx * QKD_ + DH_;
    uint2 ur = base[j], ui = base[32 + j];
    float re = __uint_as_float(ur.x) + __uint_as_float(ur.y);
    float im = __uint_as_float(ui.x) + __uint_as_float(ui.y);
    float c, s; rope_cs(t, j, c, s);
    base[j]      = split_hl(re * c - im * s);
    base[32 + j] = split_hl(re * s + im * c);
}

// kr lives in cdq2 cols [1024,1088), split format
__global__ void rope_kr_k(const uint2* __restrict__ cdq, uint2* __restrict__ Kb) {
    int bt = blockIdx.x;
    int t = bt % T_;
    int j = threadIdx.x;
    const uint2* src = cdq + (long long)bt * NCDQ_ + 1024;
    uint2 ur = src[j], ui = src[32 + j];
    float re = __uint_as_float(ur.x) + __uint_as_float(ur.y);
    float im = __uint_as_float(ui.x) + __uint_as_float(ui.y);
    float c, s; rope_cs(t, j, c, s);
    uint2 s1 = split_hl((re * c - im * s) / (float)NH_);
    uint2 s2 = split_hl((re * s + im * c) / (float)NH_);
    for (int h = 0; h < NH_; h++) {
        uint2* base = Kb + ((long long)bt * NH_ + h) * QKD_ + DH_;
        base[j] = s1; base[32 + j] = s2;
    }
}

__global__ void softmax_k(float* __restrict__ S) {
    long long r = blockIdx.x;
    int t = (int)(r & (T_ - 1));
    float* row = S + r * (long long)T_;
    int n = t + 1;
    __shared__ float red[256];
    int tid = threadIdx.x;
    float mx = -INFINITY;
    for (int l = tid; l < n; l += 256) mx = fmaxf(mx, row[l]);
    red[tid] = mx; __syncthreads();
    for (int off = 128; off; off >>= 1) {
        if (tid < off) red[tid] = fmaxf(red[tid], red[tid + off]);
        __syncthreads();
    }
    mx = red[0]; __syncthreads();
    float sum = 0.f;
    for (int l = tid; l < n; l += 256) { float e = expf(row[l] - mx); row[l] = e; sum += e; }
    red[tid] = sum; __syncthreads();
    for (int off = 128; off; off >>= 1) {
        if (tid < off) red[tid] += red[tid + off];
        __syncthreads();
    }
    float inv = 1.f / red[0];
    for (int l = tid; l < T_; l += 256) row[l] = (l < n) ? row[l] * inv : 0.f;
}

__global__ void pack_wo_k(const float* __restrict__ wo, uint2* __restrict__ out) {
    long long i = (long long)blockIdx.x * 256 + threadIdx.x;
    if (i >= (long long)DIM_ * 2048) return;
    int d = (int)(i >> 11);
    int r = (int)(i & 2047);
    int h = r >> 7, k = r & 127;
    out[i] = split_hl(wo[(long long)d * 2048 + k * NH_ + h]);
}

__global__ void gate_k(const float* __restrict__ xn, const float* __restrict__ gw,
                       const float* __restrict__ gb, float* affOut,
                       int* __restrict__ cnt, int* __restrict__ tok,
                       float* __restrict__ wt) {
    int bt = blockIdx.x;
    __shared__ float xrow[DIM_];
    __shared__ float aff[NE_];
    int tid = threadIdx.x;
    for (int d = tid; d < DIM_; d += 256) xrow[d] = xn[(long long)bt * DIM_ + d];
    __syncthreads();
    int w = tid >> 5, lane = tid & 31;
    for (int e = w; e < NE_; e += 8) {
        float s = 0.f;
        const float* gr = gw + (long long)e * DIM_;
        for (int d = lane; d < DIM_; d += 32) s += xrow[d] * gr[d];
        for (int o = 16; o; o >>= 1) s += __shfl_xor_sync(0xffffffffu, s, o);
        if (lane == 0) aff[e] = 1.f / (1.f + expf(-s)) + gb[e];
    }
    __syncthreads();
    if (tid == 0) {
        if (affOut) for (int e = 0; e < NE_; e++) affOut[(long long)bt * NE_ + e] = aff[e];
        bool used[NE_] = {};
        float wv[TOPK_]; int wi[TOPK_]; float sum = 0.f;
        for (int k = 0; k < TOPK_; k++) {
            float best = -1e30f; int bi = 0;
            for (int e = 0; e < NE_; e++)
                if (!used[e] && aff[e] > best) { best = aff[e]; bi = e; }
            used[bi] = true; wv[k] = best; wi[k] = bi; sum += best;
        }
        for (int k = 0; k < TOPK_; k++) {
            int e = wi[k];
            int pos = atomicAdd(&cnt[e], 1);
            tok[e * CAP_ + pos] = bt;
            wt [e * CAP_ + pos] = wv[k] / sum;
        }
    }
}

// silu(a13[:,0:2048] * a13[:,2048:4096]) -> split a1s
__global__ void silumul2_k(const float* __restrict__ a13, uint2* __restrict__ o) {
    long long i = (long long)blockIdx.x * 256 + threadIdx.x;
    if (i >= (long long)BT_ * MOESH_) return;
    long long row = i >> 11;
    int col = (int)(i & 2047);
    float x = a13[row * 4096 + col] * a13[row * 4096 + 2048 + col];
    x = x / (1.f + expf(-x));
    o[i] = split_hl(x);
}

__global__ void silumul_routed_k(float4* __restrict__ a, const float4* __restrict__ b,
                                 const int* __restrict__ cnt) {
    long long i = (long long)blockIdx.x * 256 + threadIdx.x;
    long long el = i << 2;
    int e = (int)(el >> 21);
    int ri = (int)((el >> 10) & (CAP_ - 1));
    if (ri >= cnt[e]) return;
    float4 x = a[i], y = b[i];
    x.x *= y.x; x.y *= y.y; x.z *= y.z; x.w *= y.w;
    x.x = x.x / (1.f + expf(-x.x));
    x.y = x.y / (1.f + expf(-x.y));
    x.z = x.z / (1.f + expf(-x.z));
    x.w = x.w / (1.f + expf(-x.w));
    a[i] = x;
}

// ---------------- host-side launch helpers ------------------------------------
static GemmP mkP(const void* A, const void* B, void* C, int M, int N, int K,
                 int lda, int ldb, int ldc, float alpha, const float* res,
                 int zdiv, long long a1, long long a2, long long b1, long long b2,
                 long long c1, long long c2,
                 const int* Mvec, const int* aRows, const int* cRows,
                 const float* wRow, int cap, int causal, int causalAV, int outSplit) {
    GemmP p;
    p.A = A; p.B = B; p.C = C; p.res = res;
    p.M = M; p.N = N; p.K = K; p.lda = lda; p.ldb = ldb; p.ldc = ldc;
    p.alpha = alpha;
    p.aO1 = a1; p.aO2 = a2; p.bO1 = b1; p.bO2 = b2; p.cO1 = c1; p.cO2 = c2;
    p.zdiv = zdiv; p.cap = cap;
    p.Mvec = Mvec; p.aRows = aRows; p.cRows = cRows; p.wRow = wRow;
    p.causal = causal; p.causalAV = causalAV; p.outSplit = outSplit;
    return p;
}

template<int MODE>
static void gemmCA(const uint2* A, const uint2* B, void* C, int M, int N, int K,
                   int lda, int ldb, int ldc, float alpha, const float* res,
                   int nz, int zdiv,
                   long long a1, long long a2, long long b1, long long b2,
                   long long c1, long long c2,
                   int causal = 0, int outSplit = 0) {
    GemmP p = mkP(A, B, C, M, N, K, lda, ldb, ldc, alpha, res, zdiv,
                  a1, a2, b1, b2, c1, c2,
                  nullptr, nullptr, nullptr, nullptr, 0, causal, 0, outSplit);
    cudaFuncSetAttribute(gemm_ca<MODE>, cudaFuncAttributeMaxDynamicSharedMemorySize,
                         CA_SMEM_BYTES);
    dim3 g((N + 127) / 128, (M + 127) / 128, nz);
    gemm_ca<MODE><<<g, 256, CA_SMEM_BYTES>>>(p);
}

template<int MODE>
static void gemmRaw(const float* A, const float* B, void* C, int M, int N, int K,
                    int lda, int ldb, int ldc, float alpha, const float* res,
                    int nz, int zdiv,
                    long long a1, long long a2, long long b1, long long b2,
                    long long c1, long long c2,
                    const int* Mvec = nullptr, const int* aRows = nullptr,
                    const int* cRows = nullptr, const float* wRow = nullptr,
                    int cap = 0, int causalAV = 0, int outSplit = 0) {
    GemmP p = mkP(A, B, C, M, N, K, lda, ldb, ldc, alpha, res, zdiv,
                  a1, a2, b1, b2, c1, c2,
                  Mvec, aRows, cRows, wRow, cap, 0, causalAV, outSplit);
    dim3 g((N + 127) / 128, (M + 127) / 128, nz);
    gemm_k<MODE><<<g, 256>>>(p);
}

static void splitArr(const float* in, uint2* out, long long n) {
    long long n4 = n >> 2;
    split_arr_k<<<(unsigned)((n4 + 255) / 256), 256>>>((const float4*)in, (uint4*)out, n4);
}

extern "C" void kernel_launch(void* const* d_in, const int* in_sizes, int n_in,
                              void* d_out, int out_size) {
    const float* x      = (const float*)d_in[0];
    const float* attn_w = (const float*)d_in[3];
    const float* ffn_w  = (const float*)d_in[4];
    const float* gate_w = (const float*)d_in[5];
    const float* gate_b = (const float*)d_in[6];
    const float* w1s    = (const float*)d_in[7];
    const float* w2s    = (const float*)d_in[8];
    const float* w3s    = (const float*)d_in[9];
    const float* w1r    = (const float*)d_in[10];
    const float* w2r    = (const float*)d_in[11];
    const float* w3r    = (const float*)d_in[12];
    const float* wdkv   = (const float*)d_in[13];
    const float* wuk    = (const float*)d_in[14];
    const float* wuv    = (const float*)d_in[15];
    const float* wdq    = (const float*)d_in[16];
    const float* wuq    = (const float*)d_in[17];
    const float* wqr    = (const float*)d_in[18];
    const float* wkr    = (const float*)d_in[19];
    const float* wo     = (const float*)d_in[20];
    float* out = (float*)d_out;

    float *S, *V, *x1, *xn, *a13, *r1, *r2, *pk, *wt;
    int *cnt, *tok;
    uint2 *h2, *cdq2, *Q2, *K2, *O2, *Wo2, *xn2, *a1s;
    uint2 *wA2, *wuk2, *wuv2, *wuq2, *wqr2, *w13s2, *w2s2;
    cudaGetSymbolAddress((void**)&S,   g_S);
    cudaGetSymbolAddress((void**)&V,   g_V);
    cudaGetSymbolAddress((void**)&x1,  g_x1);
    cudaGetSymbolAddress((void**)&xn,  g_xn);
    cudaGetSymbolAddress((void**)&a13, g_a13);
    cudaGetSymbolAddress((void**)&r1,  g_r1);
    cudaGetSymbolAddress((void**)&r2,  g_r2);
    cudaGetSymbolAddress((void**)&pk,  g_pk);
    cudaGetSymbolAddress((void**)&cnt, g_cnt);
    cudaGetSymbolAddress((void**)&tok, g_tok);
    cudaGetSymbolAddress((void**)&wt,  g_wt);
    cudaGetSymbolAddress((void**)&h2,  g_h2);
    cudaGetSymbolAddress((void**)&cdq2, g_cdq2);
    cudaGetSymbolAddress((void**)&Q2,  g_Q2);
    cudaGetSymbolAddress((void**)&K2,  g_K2);
    cudaGetSymbolAddress((void**)&O2,  g_O2);
    cudaGetSymbolAddress((void**)&Wo2, g_Wo2);
    cudaGetSymbolAddress((void**)&xn2, g_xn2);
    cudaGetSymbolAddress((void**)&a1s, g_a1s);
    cudaGetSymbolAddress((void**)&wA2,  g_wA2);
    cudaGetSymbolAddress((void**)&wuk2, g_wuk2);
    cudaGetSymbolAddress((void**)&wuv2, g_wuv2);
    cudaGetSymbolAddress((void**)&wuq2, g_wuq2);
    cudaGetSymbolAddress((void**)&wqr2, g_wqr2);
    cudaGetSymbolAddress((void**)&w13s2, g_w13s2);
    cudaGetSymbolAddress((void**)&w2s2,  g_w2s2);

    // ---- weight pre-split / packing ----
    splitArr(wdkv, wA2,                         (long long)DC_*DIM_);
    splitArr(wdq,  wA2 + (long long)DC_*DIM_,   (long long)DC_*DIM_);
    splitArr(wkr,  wA2 + (long long)2*DC_*DIM_, (long long)DRH_*DIM_);
    splitArr(wuk,  wuk2, (long long)DH_*NH_*DC_);
    splitArr(wuv,  wuv2, (long long)DH_*NH_*DC_);
    splitArr(wuq,  wuq2, (long long)DH_*NH_*DC_);
    splitArr(wqr,  wqr2, (long long)DRH_*NH_*DC_);
    {   // w1s|w3s interleaved: out[k][0:2048]=w1s[k], out[k][2048:4096]=w3s[k]
        long long tot = (long long)DIM_*MOESH_;
        unsigned nb = (unsigned)((tot + 255) / 256);
        split_pack_k<<<nb, 256>>>(w1s, w13s2, tot, MOESH_, 2*MOESH_, 0);
        split_pack_k<<<nb, 256>>>(w3s, w13s2, tot, MOESH_, 2*MOESH_, MOESH_);
    }
    splitArr(w2s, w2s2, (long long)MOESH_*DIM_);
    pack_wo_k<<<(DIM_*2048 + 255)/256, 256>>>(wo, Wo2);

    // ---- attention ----
    rmsnorm_k<<<BT_, 256>>>(x, attn_w, nullptr, h2);
    // merged dkv|dq|kr GEMM, split-K x2 into raw partials
    gemmCA<1>(h2, wA2, pk, BT_, NCDQ_, DIM_/2, DIM_, DIM_, NCDQ_, 1.f, nullptr,
              /*nz=*/2, /*zdiv=*/1,
              /*aO1=*/DIM_/2, 0, /*bO1=*/DIM_/2, 0,
              /*cO1=*/(long long)BT_*NCDQ_, 0, 0, 0);
    {
        long long n = (long long)BT_*NCDQ_;
        reduce_split_k<<<(unsigned)((n + 255)/256), 256>>>(pk, pk + n, cdq2, n);
    }
    // up-projections read cdq2 (lda = NCDQ): ckv = cols 0-511, cq = 512-1023
    gemmCA<1>(cdq2, wuk2, K2, BT_, DH_, DC_, NCDQ_, NH_*DC_, NH_*QKD_, 1.f, nullptr,
              NH_, NH_, 0,0, 0, DC_, 0, QKD_, 0, 1);
    gemmCA<1>(cdq2, wuv2, (void*)V, BT_, DH_, DC_, NCDQ_, NH_*DC_, NH_*DH_, 1.f, nullptr,
              NH_, NH_, 0,0, 0, DC_, 0, DH_, 0, 0);
    gemmCA<1>(cdq2 + DC_, wuq2, Q2, BT_, DH_, DC_, NCDQ_, NH_*DC_, NH_*QKD_, 1.f, nullptr,
              NH_, NH_, 0,0, 0, DC_, 0, QKD_, 0, 1);
    gemmCA<1>(cdq2 + DC_, wqr2, Q2 + DH_, BT_, DRH_, DC_, NCDQ_, NH_*DC_, NH_*QKD_,
              1.f, nullptr, NH_, NH_, 0,0, 0, DC_, 0, QKD_, 0, 1);
    rope_q_k<<<BT_ * NH_, 32>>>(Q2);
    rope_kr_k<<<BT_, 32>>>(cdq2, K2);
    float scale = 1.0f / sqrtf((float)QKD_);
    gemmCA<1>(Q2, K2, S, T_, T_, QKD_, NH_*QKD_, NH_*QKD_, T_, scale, nullptr,
              B_*NH_, NH_,
              (long long)T_*NH_*QKD_, QKD_,
              (long long)T_*NH_*QKD_, QKD_,
              (long long)NH_*T_*T_, (long long)T_*T_,
              /*causal=*/1, 0);
    softmax_k<<<B_ * NH_ * T_, 256>>>(S);
    gemmRaw<2>(S, V, O2, T_, DH_, T_, T_, NH_*DH_, NH_*DH_, 1.f, nullptr,
               B_*NH_, NH_,
               (long long)NH_*T_*T_, (long long)T_*T_,
               (long long)T_*NH_*DH_, DH_,
               (long long)T_*NH_*DH_, DH_,
               nullptr, nullptr, nullptr, nullptr, 0, /*causalAV=*/1, /*outSplit=*/1);
    gemmCA<1>(O2, Wo2, x1, BT_, DIM_, NH_*DH_, NH_*DH_, NH_*DH_, DIM_, 1.f, x,
              1, 1, 0,0,0,0,0,0, 0, 0);

    // ---- MoE ----
    rmsnorm_k<<<BT_, 256>>>(x1, ffn_w, xn, xn2);
    cudaMemsetAsync(cnt, 0, NE_ * sizeof(int));
    float* affOut = (out_size >= BT_*DIM_ + BT_*NE_) ? out + (long long)BT_*DIM_ : nullptr;
    gate_k<<<BT_, 256>>>(xn, gate_w, gate_b, affOut, cnt, tok, wt);
    // merged shared FFN up: N = 4096
    gemmCA<0>(xn2, w13s2, a13, BT_, 2*MOESH_, DIM_, DIM_, 2*MOESH_, 2*MOESH_, 1.f, nullptr,
              1, 1, 0,0,0,0,0,0, 0, 0);
    silumul2_k<<<(unsigned)(((long long)BT_*MOESH_ + 255)/256), 256>>>(a13, a1s);
    gemmCA<0>(a1s, w2s2, out, BT_, DIM_, MOESH_, MOESH_, DIM_, DIM_, 1.f, x1,
              1, 1, 0,0,0,0,0,0, 0, 0);
    // routed experts: R7 raw path
    gemmRaw<0>(xn, w1r, r1, CAP_, MOE_, DIM_, DIM_, MOE_, MOE_, 1.f, nullptr,
               NE_, NE_, 0,0, 0, (long long)DIM_*MOE_, 0, (long long)CAP_*MOE_,
               cnt, tok, nullptr, nullptr, CAP_);
    gemmRaw<0>(xn, w3r, r2, CAP_, MOE_, DIM_, DIM_, MOE_, MOE_, 1.f, nullptr,
               NE_, NE_, 0,0, 0, (long long)DIM_*MOE_, 0, (long long)CAP_*MOE_,
               cnt, tok, nullptr, nullptr, CAP_);
    silumul_routed_k<<<(unsigned)(((long long)NE_*CAP_*MOE_/4 + 255)/256), 256>>>(
        (float4*)r1, (const float4*)r2, cnt);
    gemmRaw<0>(r1, w2r, out, CAP_, DIM_, MOE_, MOE_, DIM_, DIM_, 1.f, nullptr,
               NE_, NE_, 0, (long long)CAP_*MOE_, 0, (long long)MOE_*DIM_, 0, 0,
               cnt, nullptr, tok, wt, CAP_);
}

// round 12
// speedup vs baseline: 2.2102x; 1.7118x over previous
#include <cuda_runtime.h>
#include <cuda_fp16.h>
#include <math.h>
#include <stdint.h>

#define B_    2
#define T_    1024
#define BT_   2048
#define DIM_  2048
#define NH_   16
#define DH_   128
#define DRH_  64
#define DC_   512
#define NE_   16
#define TOPK_ 4
#define MOE_  1024
#define MOESH_ 2048
#define CAP_  2048
#define QKD_  192
#define NCDQ_ 1088
#define SC_   256.0f
#define ASC_  (1.0f/65536.0f)

// ---------------- scratch ----------------
__device__ float g_S  [(size_t)B_*NH_*T_*T_];
__device__ float g_V  [BT_*NH_*DH_];
__device__ float g_x1 [BT_*DIM_];
__device__ float g_xn [BT_*DIM_];
__device__ float g_a13[(size_t)BT_*2*MOESH_];
__device__ float g_r1 [(size_t)NE_*CAP_*MOE_];
__device__ float g_r2 [(size_t)NE_*CAP_*MOE_];
__device__ float g_pk [2][(size_t)BT_*NCDQ_];
__device__ int   g_cnt[NE_];
__device__ int   g_tok[NE_*CAP_];
__device__ float g_wt [NE_*CAP_];
// fp16 pair-split buffers: uint2 = (half2 hi(k,k+1), half2 lo(k,k+1)), values x*256
__device__ __align__(16) uint2 g_h2  [BT_*DIM_/2];
__device__ __align__(16) uint2 g_cdq2[(size_t)BT_*NCDQ_/2];
__device__ __align__(16) uint2 g_Q2  [BT_*NH_*QKD_/2];
__device__ __align__(16) uint2 g_K2  [BT_*NH_*QKD_/2];
__device__ __align__(16) uint2 g_O2  [BT_*NH_*DH_/2];
__device__ __align__(16) uint2 g_Wo2 [(size_t)DIM_*NH_*DH_/2];
__device__ __align__(16) uint2 g_xn2 [BT_*DIM_/2];
__device__ __align__(16) uint2 g_a1s [BT_*MOESH_/2];
// split weights
__device__ __align__(16) uint2 g_wA2  [(size_t)NCDQ_*DIM_/2];
__device__ __align__(16) uint2 g_wuk2 [DH_*NH_*DC_/2];
__device__ __align__(16) uint2 g_wuv2 [DH_*NH_*DC_/2];
__device__ __align__(16) uint2 g_wuq2 [DH_*NH_*DC_/2];
__device__ __align__(16) uint2 g_wqr2 [DRH_*NH_*DC_/2];
__device__ __align__(16) uint2 g_w13s2[(size_t)(DIM_/2)*2*MOESH_];
__device__ __align__(16) uint2 g_w2s2 [(size_t)(MOESH_/2)*DIM_];

// pack two already-scaled floats into (hi half2, lo half2)
__device__ __forceinline__ uint2 split2(float x, float y) {
    __half hx = __float2half_rn(x), hy = __float2half_rn(y);
    float lx = x - __half2float(hx), ly = y - __half2float(hy);
    __half2 h = __halves2half2(hx, hy);
    __half2 l = __halves2half2(__float2half_rn(lx), __float2half_rn(ly));
    uint2 r; r.x = *(uint32_t*)&h; r.y = *(uint32_t*)&l;
    return r;
}
__device__ __forceinline__ void mma_f16(float* c, const uint32_t* a, const uint32_t* b) {
    asm volatile("mma.sync.aligned.m16n8k16.row.col.f32.f16.f16.f32 "
        "{%0,%1,%2,%3}, {%4,%5,%6,%7}, {%8,%9}, {%0,%1,%2,%3};\n"
        : "+f"(c[0]), "+f"(c[1]), "+f"(c[2]), "+f"(c[3])
        : "r"(a[0]), "r"(a[1]), "r"(a[2]), "r"(a[3]), "r"(b[0]), "r"(b[1]));
}

struct GemmP {
    const void* A; const void* B; void* C; const float* res;
    int M, N, K, lda, ldb, ldc;   // lda/ldb: PAIR strides for split ops; floats for raw
    float alpha;
    long long aO1, aO2, bO1, bO2, cO1, cO2;
    int zdiv, cap;
    const int* Mvec; const int* aRows; const int* cRows; const float* wRow;
    int causal, causalAV, outSplit;
};

// ============ cp.async GEMM (pair-split operands) ==============================
// MODE 0: B is NN pair-packed [K/2][N]; MODE 1: B is NT [N][K/2]. A always [M][K/2].
#define CA_STAGE_U2 2112
#define CA_SMEM_BYTES (4 * CA_STAGE_U2 * 8)

__device__ __forceinline__ void cp_async8(uint32_t saddr, const void* gaddr, int sz) {
    asm volatile("cp.async.ca.shared.global [%0], [%1], 8, %2;"
                 :: "r"(saddr), "l"(gaddr), "r"(sz) : "memory");
}

template<int MODE>
__global__ __launch_bounds__(256, 2) void gemm_ca(GemmP p) {
    extern __shared__ uint2 dyn[];
    uint32_t smemBase = (uint32_t)__cvta_generic_to_shared(dyn);

    int z = blockIdx.z, z1 = z / p.zdiv, z2 = z - z1 * p.zdiv;
    long long zA = z1 * p.aO1 + z2 * p.aO2;
    long long zB = z1 * p.bO1 + z2 * p.bO2;
    long long zC = z1 * p.cO1 + z2 * p.cO2;
    int m0 = blockIdx.y * 128, n0 = blockIdx.x * 128;
    if (MODE == 1 && p.causal && n0 >= m0 + 128) return;
    int tid = threadIdx.x, lane = tid & 31, warp = tid >> 5;
    int wm = (warp & 1) << 6, wn = (warp >> 1) << 5;
    int gid = lane >> 2, tg = lane & 3;

    long long gA[4]; uint32_t sAoff[4]; int szA[4];
    long long gB[4]; uint32_t sBoff[4]; int szB[4];
    long long strideB = (MODE == 1) ? 8 : (long long)8 * p.ldb;  // pairs per chunk
#pragma unroll
    for (int i = 0; i < 4; i++) {
        int e = tid + 256 * i;
        int am = e >> 3, ak = e & 7;
        bool va = (m0 + am) < p.M;
        gA[i] = zA + (long long)(va ? (m0 + am) : 0) * p.lda + ak;
        sAoff[i] = (uint32_t)(ak * 132 + am) * 8;
        szA[i] = va ? 8 : 0;
        if (MODE == 1) {
            int bn = e >> 3, bk = e & 7;
            bool vb = (n0 + bn) < p.N;
            gB[i] = zB + (long long)(vb ? (n0 + bn) : 0) * p.ldb + bk;
            sBoff[i] = (uint32_t)(1056 + bk * 132 + bn) * 8;
            szB[i] = vb ? 8 : 0;
        } else {
            int bk = e >> 7, bn = e & 127;
            bool vb = (n0 + bn) < p.N;
            gB[i] = zB + (long long)bk * p.ldb + n0 + (vb ? bn : 0);
            sBoff[i] = (uint32_t)(1056 + bk * 132 + bn) * 8;
            szB[i] = vb ? 8 : 0;
        }
    }

    float acc[4][4][4];
#pragma unroll
    for (int mi = 0; mi < 4; mi++)
#pragma unroll
        for (int ni = 0; ni < 4; ni++)
#pragma unroll
            for (int q = 0; q < 4; q++) acc[mi][ni][q] = 0.f;

    int nIter = p.K >> 4;   // K elements, 16 per chunk (8 pairs)
    const uint2* Ag = (const uint2*)p.A;
    const uint2* Bg = (const uint2*)p.B;

    auto issue = [&](int stage, int chunk) {
        uint32_t base = smemBase + (uint32_t)stage * CA_STAGE_U2 * 8;
        long long ka = (long long)chunk * 8;
        long long kb = (long long)chunk * strideB;
#pragma unroll
        for (int i = 0; i < 4; i++)
            cp_async8(base + sAoff[i], Ag + gA[i] + ka, szA[i]);
#pragma unroll
        for (int i = 0; i < 4; i++)
            cp_async8(base + sBoff[i], Bg + gB[i] + kb, szB[i]);
    };

#pragma unroll
    for (int s = 0; s < 3; s++) {
        if (s < nIter) issue(s, s);
        asm volatile("cp.async.commit_group;" ::: "memory");
    }

    for (int it = 0; it < nIter; it++) {
        asm volatile("cp.async.wait_group 2;" ::: "memory");
        __syncthreads();
        if (it + 3 < nIter) issue((it + 3) & 3, it + 3);
        asm volatile("cp.async.commit_group;" ::: "memory");

        const uint2* sA = dyn + (it & 3) * CA_STAGE_U2;
        const uint2* sB = sA + 1056;
        uint2 vB0[4], vB1[4];
#pragma unroll
        for (int ni = 0; ni < 4; ni++) {
            int nb2 = wn + ni * 8 + gid;
            vB0[ni] = sB[tg * 132 + nb2];
            vB1[ni] = sB[(tg + 4) * 132 + nb2];
        }
#pragma unroll
        for (int mi = 0; mi < 4; mi++) {
            int mb = wm + mi * 16 + gid;
            uint2 a0 = sA[tg * 132 + mb];
            uint2 a1 = sA[tg * 132 + mb + 8];
            uint2 a2 = sA[(tg + 4) * 132 + mb];
            uint2 a3 = sA[(tg + 4) * 132 + mb + 8];
            uint32_t ah[4] = {a0.x, a1.x, a2.x, a3.x};
            uint32_t al[4] = {a0.y, a1.y, a2.y, a3.y};
#pragma unroll
            for (int ni = 0; ni < 4; ni++) {
                uint32_t bh[2] = {vB0[ni].x, vB1[ni].x};
                mma_f16(acc[mi][ni], ah, bh);
            }
#pragma unroll
            for (int ni = 0; ni < 4; ni++) {
                uint32_t bh[2] = {vB0[ni].x, vB1[ni].x};
                mma_f16(acc[mi][ni], al, bh);
            }
#pragma unroll
            for (int ni = 0; ni < 4; ni++) {
                uint32_t bl[2] = {vB0[ni].y, vB1[ni].y};
                mma_f16(acc[mi][ni], ah, bl);
            }
        }
    }

#pragma unroll
    for (int mi = 0; mi < 4; mi++) {
#pragma unroll
        for (int half = 0; half < 2; half++) {
            int m = m0 + wm + mi * 16 + gid + half * 8;
            if (m >= p.M) continue;
            long long crow = zC + (long long)m * p.ldc;   // ldc: pairs if outSplit else floats
#pragma unroll
            for (int ni = 0; ni < 4; ni++) {
                int n = n0 + wn + ni * 8 + tg * 2;
                if (n >= p.N) continue;
                float v0 = acc[mi][ni][half * 2 + 0] * p.alpha;
                float v1 = acc[mi][ni][half * 2 + 1] * p.alpha;
                if (p.outSplit) {
                    ((uint2*)p.C)[crow + (n >> 1)] = split2(v0 * SC_, v1 * SC_);
                } else {
                    float* Cf = (float*)p.C;
                    if (p.res) { v0 += p.res[crow + n]; v1 += p.res[crow + n + 1]; }
                    Cf[crow + n]     = v0;
                    Cf[crow + n + 1] = v1;
                }
            }
        }
    }
}

// ============ raw GEMM (fp16-split in loop, K-chunk 16) ========================
// MODE 0: NN (routed, gathered A, atomic scatter). MODE 2: TN (AV).
template<int MODE>
__global__ __launch_bounds__(256, 2) void gemm_k(GemmP p) {
    __shared__ uint2 sA[2][8][132];
    __shared__ uint2 sB[2][8][132];

    int z = blockIdx.z, z1 = z / p.zdiv, z2 = z - z1 * p.zdiv;
    const float* A  = (const float*)p.A + z1 * p.aO1 + z2 * p.aO2;
    const float* Bp = (const float*)p.B + z1 * p.bO1 + z2 * p.bO2;
    long long zC = z1 * p.cO1 + z2 * p.cO2;
    int M = p.Mvec ? p.Mvec[z] : p.M;
    int m0 = blockIdx.y * 128, n0 = blockIdx.x * 128;
    if (m0 >= M) return;
    int tid = threadIdx.x, lane = tid & 31, warp = tid >> 5;
    int wm = (warp & 1) << 6, wn = (warp >> 1) << 5;
    int gid = lane >> 2, tg = lane & 3;

    bool aValid; const float* aPtr; int aP, aM;
    if (MODE != 2) {            // A[row][k]: row=tid>>1, k half = (tid&1)*8..+7
        int r = m0 + (tid >> 1);
        aValid = (r < M);
        long long ar = 0;
        if (aValid) ar = p.aRows ? (long long)p.aRows[(long long)z * p.cap + r]
                                 : (long long)r;
        aPtr = A + ar * (long long)p.lda + (tid & 1) * 8;
        aP = (tid & 1) * 4;  aM = tid >> 1;
    } else {                    // A[k][m]: rows 2*(tid>>5), +1 at m=4*(tid&31)
        int m = m0 + (tid & 31) * 4;
        aValid = (m < M);
        aPtr = A + (long long)((tid >> 5) * 2) * p.lda + (aValid ? m : 0);
        aP = tid >> 5;       aM = (tid & 31) * 4;
    }
    bool bValid; const float* bPtr; int bP, bM;
    {                           // B[k][n]: rows 2*(tid>>5), +1 at n=4*(tid&31)
        int n = n0 + (tid & 31) * 4;
        bValid = (n < p.N);
        bPtr = Bp + (long long)((tid >> 5) * 2) * p.ldb + (bValid ? n : 0);
        bP = tid >> 5;       bM = (tid & 31) * 4;
    }

    float acc[4][4][4];
#pragma unroll
    for (int mi = 0; mi < 4; mi++)
#pragma unroll
        for (int ni = 0; ni < 4; ni++)
#pragma unroll
            for (int q = 0; q < 4; q++) acc[mi][ni][q] = 0.f;

    const float4 z4 = make_float4(0.f, 0.f, 0.f, 0.f);
    int kStart = (MODE == 2 && p.causalAV) ? m0 : 0;   // m0 % 16 == 0
    int nIter = (p.K - kStart) >> 4;

    auto loadG = [&](int chunk, float4* fa, float4* fb) {
        int k = kStart + chunk * 16;
        if (MODE != 2) {
            fa[0] = aValid ? *(const float4*)(aPtr + k)     : z4;
            fa[1] = aValid ? *(const float4*)(aPtr + k + 4) : z4;
        } else {
            long long o = (long long)k * p.lda;
            fa[0] = aValid ? *(const float4*)(aPtr + o)          : z4;
            fa[1] = aValid ? *(const float4*)(aPtr + o + p.lda)  : z4;
        }
        long long ob = (long long)k * p.ldb;
        fb[0] = bValid ? *(const float4*)(bPtr + ob)         : z4;
        fb[1] = bValid ? *(const float4*)(bPtr + ob + p.ldb) : z4;
    };
    auto storeS = [&](int buf, const float4* fa, const float4* fb) {
        if (MODE != 2) {   // fa: 8 consecutive k for one row -> 4 pairs
            const float* a8 = (const float*)fa;
#pragma unroll
            for (int j = 0; j < 4; j++)
                sA[buf][aP + j][aM] = split2(a8[2*j] * SC_, a8[2*j+1] * SC_);
        } else {           // fa[0]=row k, fa[1]=row k+1, 4 m each -> pair per m
            const float* r0 = (const float*)&fa[0];
            const float* r1 = (const float*)&fa[1];
#pragma unroll
            for (int j = 0; j < 4; j++)
                sA[buf][aP][aM + j] = split2(r0[j] * SC_, r1[j] * SC_);
        }
        const float* b0 = (const float*)&fb[0];
        const float* b1 = (const float*)&fb[1];
#pragma unroll
        for (int j = 0; j < 4; j++)
            sB[buf][bP][bM + j] = split2(b0[j] * SC_, b1[j] * SC_);
    };

    float4 va[2], vb[2];
    loadG(0, va, vb);
    storeS(0, va, vb);
    __syncthreads();

    for (int it = 0; it < nIter; it++) {
        int cur = it & 1;
        float4 na[2] = {z4, z4}, nb[2] = {z4, z4};
        if (it + 1 < nIter) loadG(it + 1, na, nb);

        uint2 vB0[4], vB1[4];
#pragma unroll
        for (int ni = 0; ni < 4; ni++) {
            int nb2 = wn + ni * 8 + gid;
            vB0[ni] = sB[cur][tg    ][nb2];
            vB1[ni] = sB[cur][tg + 4][nb2];
        }
#pragma unroll
        for (int mi = 0; mi < 4; mi++) {
            int mb = wm + mi * 16 + gid;
            uint2 a0 = sA[cur][tg    ][mb];
            uint2 a1 = sA[cur][tg    ][mb + 8];
            uint2 a2 = sA[cur][tg + 4][mb];
            uint2 a3 = sA[cur][tg + 4][mb + 8];
            uint32_t ah[4] = {a0.x, a1.x, a2.x, a3.x};
            uint32_t al[4] = {a0.y, a1.y, a2.y, a3.y};
#pragma unroll
            for (int ni = 0; ni < 4; ni++) {
                uint32_t bh[2] = {vB0[ni].x, vB1[ni].x};
                mma_f16(acc[mi][ni], ah, bh);
            }
#pragma unroll
            for (int ni = 0; ni < 4; ni++) {
                uint32_t bh[2] = {vB0[ni].x, vB1[ni].x};
                mma_f16(acc[mi][ni], al, bh);
            }
#pragma unroll
            for (int ni = 0; ni < 4; ni++) {
                uint32_t bl[2] = {vB0[ni].y, vB1[ni].y};
                mma_f16(acc[mi][ni], ah, bl);
            }
        }

        if (it + 1 < nIter) storeS(cur ^ 1, na, nb);
        __syncthreads();
    }

#pragma unroll
    for (int mi = 0; mi < 4; mi++) {
#pragma unroll
        for (int half = 0; half < 2; half++) {
            int m = m0 + wm + mi * 16 + gid + half * 8;
            if (m >= M) continue;
            long long crow; float w = p.alpha;
            if (p.cRows) {
                crow = (long long)p.cRows[(long long)z * p.cap + m] * p.ldc;
                w *= p.wRow[(long long)z * p.cap + m];
            } else {
                crow = zC + (long long)m * p.ldc;
            }
#pragma unroll
            for (int ni = 0; ni < 4; ni++) {
                int n = n0 + wn + ni * 8 + tg * 2;
                if (n >= p.N) continue;
                float v0 = acc[mi][ni][half * 2 + 0] * w;
                float v1 = acc[mi][ni][half * 2 + 1] * w;
                if (p.cRows) {
                    atomicAdd(&((float*)p.C)[crow + n],     v0);
                    atomicAdd(&((float*)p.C)[crow + n + 1], v1);
                } else if (p.outSplit) {
                    ((uint2*)p.C)[crow + (n >> 1)] = split2(v0 * SC_, v1 * SC_);
                } else {
                    float* Cf = (float*)p.C;
                    if (p.res) { v0 += p.res[crow + n]; v1 += p.res[crow + n + 1]; }
                    Cf[crow + n]     = v0;
                    Cf[crow + n + 1] = v1;
                }
            }
        }
    }
}

// ---------------- producers / small kernels ------------------------------------
__global__ void split_arr_k(const float4* __restrict__ in, uint2* __restrict__ out,
                            long long n4) {
    long long i = (long long)blockIdx.x * 256 + threadIdx.x;
    if (i >= n4) return;
    float4 v = in[i];
    out[2 * i]     = split2(v.x * SC_, v.y * SC_);
    out[2 * i + 1] = split2(v.z * SC_, v.w * SC_);
}

// NN pair pack: out[p*ldout + colOff + n] = split2(in[2p][n], in[2p+1][n])
__global__ void split_pack_nn_k(const float* __restrict__ in, uint2* __restrict__ out,
                                long long total, int N, int ldout, int colOff) {
    long long i = (long long)blockIdx.x * 256 + threadIdx.x;
    if (i >= total) return;
    long long pr = i / N;
    int n = (int)(i - pr * N);
    out[pr * ldout + colOff + n] =
        split2(in[(2 * pr) * N + n] * SC_, in[(2 * pr + 1) * N + n] * SC_);
}

__global__ void reduce_split_k(const float* __restrict__ p0, const float* __restrict__ p1,
                               uint2* __restrict__ out, long long npair) {
    long long i = (long long)blockIdx.x * 256 + threadIdx.x;
    if (i >= npair) return;
    float v0 = p0[2*i]   + p1[2*i];
    float v1 = p0[2*i+1] + p1[2*i+1];
    out[i] = split2(v0 * SC_, v1 * SC_);
}

__global__ void rmsnorm_k(const float* __restrict__ x, const float* __restrict__ w,
                          float* __restrict__ oraw, uint2* __restrict__ osp) {
    int r = blockIdx.x;
    const float* xr = x + (long long)r * DIM_;
    float s = 0.f;
    for (int d = threadIdx.x; d < DIM_; d += 256) { float v = xr[d]; s += v * v; }
    __shared__ float red[256];
    red[threadIdx.x] = s; __syncthreads();
    for (int off = 128; off; off >>= 1) {
        if (threadIdx.x < off) red[threadIdx.x] += red[threadIdx.x + off];
        __syncthreads();
    }
    float inv = rsqrtf(red[0] / (float)DIM_ + 1e-6f);
    for (int pd = threadIdx.x; pd < DIM_/2; pd += 256) {
        int d = pd * 2;
        float v0 = w[d] * xr[d] * inv;
        float v1 = w[d+1] * xr[d+1] * inv;
        if (oraw) { oraw[(long long)r * DIM_ + d] = v0; oraw[(long long)r * DIM_ + d+1] = v1; }
        osp[(long long)r * (DIM_/2) + pd] = split2(v0 * SC_, v1 * SC_);
    }
}

__device__ __forceinline__ void rope_cs(int t, int j, float& c, float& s) {
    float freq = 1.0f / powf(10000.0f, (float)(2 * j) / (float)DRH_);
    float ang = (float)t * freq;
    sincosf(ang, &s, &c);
}
__device__ __forceinline__ void unpack2(uint2 u, float& a, float& b) {
    __half2 h = *(__half2*)&u.x, l = *(__half2*)&u.y;
    a = __low2float(h) + __low2float(l);
    b = __high2float(h) + __high2float(l);
}

__global__ void rope_q_k(uint2* __restrict__ Q) {   // 16 threads
    int idx = blockIdx.x;
    int bt = idx / NH_;
    int t = bt % T_;
    int pp = threadIdx.x;                 // 0..15
    uint2* base = Q + (long long)idx * (QKD_/2) + DH_/2;
    float re0, re1, im0, im1;
    unpack2(base[pp], re0, re1);
    unpack2(base[16 + pp], im0, im1);
    float c0, s0, c1, s1;
    rope_cs(t, 2*pp, c0, s0); rope_cs(t, 2*pp + 1, c1, s1);
    base[pp]      = split2(re0 * c0 - im0 * s0, re1 * c1 - im1 * s1);
    base[16 + pp] = split2(re0 * s0 + im0 * c0, re1 * s1 + im1 * c1);
}

__global__ void rope_kr_k(const uint2* __restrict__ cdq, uint2* __restrict__ Kb) {
    int bt = blockIdx.x;
    int t = bt % T_;
    int pp = threadIdx.x;                 // 0..15
    const uint2* src = cdq + (long long)bt * (NCDQ_/2) + 512;
    float re0, re1, im0, im1;
    unpack2(src[pp], re0, re1);
    unpack2(src[16 + pp], im0, im1);
    float c0, s0, c1, s1;
    rope_cs(t, 2*pp, c0, s0); rope_cs(t, 2*pp + 1, c1, s1);
    float inh = 1.0f / (float)NH_;
    uint2 o1 = split2((re0 * c0 - im0 * s0) * inh, (re1 * c1 - im1 * s1) * inh);
    uint2 o2 = split2((re0 * s0 + im0 * c0) * inh, (re1 * s1 + im1 * c1) * inh);
    for (int h = 0; h < NH_; h++) {
        uint2* base = Kb + ((long long)bt * NH_ + h) * (QKD_/2) + DH_/2;
        base[pp] = o1; base[16 + pp] = o2;
    }
}

__global__ void softmax_k(float* __restrict__ S) {
    long long r = blockIdx.x;
    int t = (int)(r & (T_ - 1));
    float* row = S + r * (long long)T_;
    int n = t + 1;
    __shared__ float red[256];
    int tid = threadIdx.x;
    float mx = -INFINITY;
    for (int l = tid; l < n; l += 256) mx = fmaxf(mx, row[l]);
    red[tid] = mx; __syncthreads();
    for (int off = 128; off; off >>= 1) {
        if (tid < off) red[tid] = fmaxf(red[tid], red[tid + off]);
        __syncthreads();
    }
    mx = red[0]; __syncthreads();
    float sum = 0.f;
    for (int l = tid; l < n; l += 256) { float e = expf(row[l] - mx); row[l] = e; sum += e; }
    red[tid] = sum; __syncthreads();
    for (int off = 128; off; off >>= 1) {
        if (tid < off) red[tid] += red[tid + off];
        __syncthreads();
    }
    float inv = 1.f / red[0];
    for (int l = tid; l < T_; l += 256) row[l] = (l < n) ? row[l] * inv : 0.f;
}

__global__ void pack_wo_k(const float* __restrict__ wo, uint2* __restrict__ out) {
    long long i = (long long)blockIdx.x * 256 + threadIdx.x;   // DIM * 1024 pairs
    if (i >= (long long)DIM_ * 1024) return;
    int d = (int)(i >> 10);
    int pr = (int)(i & 1023);
    int e = pr * 2;
    int h = e >> 7, k = e & 127;
    float s0 = wo[(long long)d * 2048 + k * NH_ + h];
    float s1 = wo[(long long)d * 2048 + (k + 1) * NH_ + h];
    out[i] = split2(s0 * SC_, s1 * SC_);
}

__global__ void gate_k(const float* __restrict__ xn, const float* __restrict__ gw,
                       const float* __restrict__ gb, float* affOut,
                       int* __restrict__ cnt, int* __restrict__ tok,
                       float* __restrict__ wt) {
    int bt = blockIdx.x;
    __shared__ float xrow[DIM_];
    __shared__ float aff[NE_];
    int tid = threadIdx.x;
    for (int d = tid; d < DIM_; d += 256) xrow[d] = xn[(long long)bt * DIM_ + d];
    __syncthreads();
    int w = tid >> 5, lane = tid & 31;
    for (int e = w; e < NE_; e += 8) {
        float s = 0.f;
        const float* gr = gw + (long long)e * DIM_;
        for (int d = lane; d < DIM_; d += 32) s += xrow[d] * gr[d];
        for (int o = 16; o; o >>= 1) s += __shfl_xor_sync(0xffffffffu, s, o);
        if (lane == 0) aff[e] = 1.f / (1.f + expf(-s)) + gb[e];
    }
    __syncthreads();
    if (tid == 0) {
        if (affOut) for (int e = 0; e < NE_; e++) affOut[(long long)bt * NE_ + e] = aff[e];
        bool used[NE_] = {};
        float wv[TOPK_]; int wi[TOPK_]; float sum = 0.f;
        for (int k = 0; k < TOPK_; k++) {
            float best = -1e30f; int bi = 0;
            for (int e = 0; e < NE_; e++)
                if (!used[e] && aff[e] > best) { best = aff[e]; bi = e; }
            used[bi] = true; wv[k] = best; wi[k] = bi; sum += best;
        }
        for (int k = 0; k < TOPK_; k++) {
            int e = wi[k];
            int pos = atomicAdd(&cnt[e], 1);
            tok[e * CAP_ + pos] = bt;
            wt [e * CAP_ + pos] = wv[k] / sum;
        }
    }
}

__global__ void silumul2_k(const float* __restrict__ a13, uint2* __restrict__ o) {
    long long i = (long long)blockIdx.x * 256 + threadIdx.x;   // BT * 1024 pairs
    if (i >= (long long)BT_ * (MOESH_/2)) return;
    long long row = i >> 10;
    int c = (int)(i & 1023) * 2;
    const float* ar = a13 + row * 4096;
    float x0 = ar[c] * ar[2048 + c];
    float x1 = ar[c + 1] * ar[2048 + c + 1];
    x0 = x0 / (1.f + expf(-x0));
    x1 = x1 / (1.f + expf(-x1));
    o[i] = split2(x0 * SC_, x1 * SC_);
}

__global__ void silumul_routed_k(float4* __restrict__ a, const float4* __restrict__ b,
                                 const int* __restrict__ cnt) {
    long long i = (long long)blockIdx.x * 256 + threadIdx.x;
    long long el = i << 2;
    int e = (int)(el >> 21);
    int ri = (int)((el >> 10) & (CAP_ - 1));
    if (ri >= cnt[e]) return;
    float4 x = a[i], y = b[i];
    x.x *= y.x; x.y *= y.y; x.z *= y.z; x.w *= y.w;
    x.x = x.x / (1.f + expf(-x.x));
    x.y = x.y / (1.f + expf(-x.y));
    x.z = x.z / (1.f + expf(-x.z));
    x.w = x.w / (1.f + expf(-x.w));
    a[i] = x;
}

// ---------------- host helpers ------------------------------------------------
static GemmP mkP(const void* A, const void* B, void* C, int M, int N, int K,
                 int lda, int ldb, int ldc, float alpha, const float* res,
                 int zdiv, long long a1, long long a2, long long b1, long long b2,
                 long long c1, long long c2,
                 const int* Mvec, const int* aRows, const int* cRows,
                 const float* wRow, int cap, int causal, int causalAV, int outSplit) {
    GemmP p;
    p.A = A; p.B = B; p.C = C; p.res = res;
    p.M = M; p.N = N; p.K = K; p.lda = lda; p.ldb = ldb; p.ldc = ldc;
    p.alpha = alpha;
    p.aO1 = a1; p.aO2 = a2; p.bO1 = b1; p.bO2 = b2; p.cO1 = c1; p.cO2 = c2;
    p.zdiv = zdiv; p.cap = cap;
    p.Mvec = Mvec; p.aRows = aRows; p.cRows = cRows; p.wRow = wRow;
    p.causal = causal; p.causalAV = causalAV; p.outSplit = outSplit;
    return p;
}

template<int MODE>
static void gemmCA(const uint2* A, const uint2* B, void* C, int M, int N, int K,
                   int ldaP, int ldbP, int ldc, float alpha, const float* res,
                   int nz, int zdiv,
                   long long a1, long long a2, long long b1, long long b2,
                   long long c1, long long c2,
                   int causal = 0, int outSplit = 0) {
    GemmP p = mkP(A, B, C, M, N, K, ldaP, ldbP, ldc, alpha, res, zdiv,
                  a1, a2, b1, b2, c1, c2,
                  nullptr, nullptr, nullptr, nullptr, 0, causal, 0, outSplit);
    cudaFuncSetAttribute(gemm_ca<MODE>, cudaFuncAttributeMaxDynamicSharedMemorySize,
                         CA_SMEM_BYTES);
    dim3 g((N + 127) / 128, (M + 127) / 128, nz);
    gemm_ca<MODE><<<g, 256, CA_SMEM_BYTES>>>(p);
}

template<int MODE>
static void gemmRaw(const float* A, const float* B, void* C, int M, int N, int K,
                    int lda, int ldb, int ldc, float alpha, const float* res,
                    int nz, int zdiv,
                    long long a1, long long a2, long long b1, long long b2,
                    long long c1, long long c2,
                    const int* Mvec = nullptr, const int* aRows = nullptr,
                    const int* cRows = nullptr, const float* wRow = nullptr,
                    int cap = 0, int causalAV = 0, int outSplit = 0) {
    GemmP p = mkP(A, B, C, M, N, K, lda, ldb, ldc, alpha, res, zdiv,
                  a1, a2, b1, b2, c1, c2,
                  Mvec, aRows, cRows, wRow, cap, 0, causalAV, outSplit);
    dim3 g((N + 127) / 128, (M + 127) / 128, nz);
    gemm_k<MODE><<<g, 256>>>(p);
}

static void splitArr(const float* in, uint2* out, long long n) {
    long long n4 = n >> 2;
    split_arr_k<<<(unsigned)((n4 + 255) / 256), 256>>>((const float4*)in, out, n4);
}

extern "C" void kernel_launch(void* const* d_in, const int* in_sizes, int n_in,
                              void* d_out, int out_size) {
    const float* x      = (const float*)d_in[0];
    const float* attn_w = (const float*)d_in[3];
    const float* ffn_w  = (const float*)d_in[4];
    const float* gate_w = (const float*)d_in[5];
    const float* gate_b = (const float*)d_in[6];
    const float* w1s    = (const float*)d_in[7];
    const float* w2s    = (const float*)d_in[8];
    const float* w3s    = (const float*)d_in[9];
    const float* w1r    = (const float*)d_in[10];
    const float* w2r    = (const float*)d_in[11];
    const float* w3r    = (const float*)d_in[12];
    const float* wdkv   = (const float*)d_in[13];
    const float* wuk    = (const float*)d_in[14];
    const float* wuv    = (const float*)d_in[15];
    const float* wdq    = (const float*)d_in[16];
    const float* wuq    = (const float*)d_in[17];
    const float* wqr    = (const float*)d_in[18];
    const float* wkr    = (const float*)d_in[19];
    const float* wo     = (const float*)d_in[20];
    float* out = (float*)d_out;

    float *S, *V, *x1, *xn, *a13, *r1, *r2, *pk, *wt;
    int *cnt, *tok;
    uint2 *h2, *cdq2, *Q2, *K2, *O2, *Wo2, *xn2, *a1s;
    uint2 *wA2, *wuk2, *wuv2, *wuq2, *wqr2, *w13s2, *w2s2;
    cudaGetSymbolAddress((void**)&S,   g_S);
    cudaGetSymbolAddress((void**)&V,   g_V);
    cudaGetSymbolAddress((void**)&x1,  g_x1);
    cudaGetSymbolAddress((void**)&xn,  g_xn);
    cudaGetSymbolAddress((void**)&a13, g_a13);
    cudaGetSymbolAddress((void**)&r1,  g_r1);
    cudaGetSymbolAddress((void**)&r2,  g_r2);
    cudaGetSymbolAddress((void**)&pk,  g_pk);
    cudaGetSymbolAddress((void**)&cnt, g_cnt);
    cudaGetSymbolAddress((void**)&tok, g_tok);
    cudaGetSymbolAddress((void**)&wt,  g_wt);
    cudaGetSymbolAddress((void**)&h2,  g_h2);
    cudaGetSymbolAddress((void**)&cdq2, g_cdq2);
    cudaGetSymbolAddress((void**)&Q2,  g_Q2);
    cudaGetSymbolAddress((void**)&K2,  g_K2);
    cudaGetSymbolAddress((void**)&O2,  g_O2);
    cudaGetSymbolAddress((void**)&Wo2, g_Wo2);
    cudaGetSymbolAddress((void**)&xn2, g_xn2);
    cudaGetSymbolAddress((void**)&a1s, g_a1s);
    cudaGetSymbolAddress((void**)&wA2,  g_wA2);
    cudaGetSymbolAddress((void**)&wuk2, g_wuk2);
    cudaGetSymbolAddress((void**)&wuv2, g_wuv2);
    cudaGetSymbolAddress((void**)&wuq2, g_wuq2);
    cudaGetSymbolAddress((void**)&wqr2, g_wqr2);
    cudaGetSymbolAddress((void**)&w13s2, g_w13s2);
    cudaGetSymbolAddress((void**)&w2s2,  g_w2s2);

    // ---- weight pre-split / packing (pair format) ----
    splitArr(wdkv, wA2,                           (long long)DC_*DIM_);
    splitArr(wdq,  wA2 + (long long)DC_*DIM_/2,   (long long)DC_*DIM_);
    splitArr(wkr,  wA2 + (long long)DC_*DIM_,     (long long)DRH_*DIM_);
    splitArr(wuk,  wuk2, (long long)DH_*NH_*DC_);
    splitArr(wuv,  wuv2, (long long)DH_*NH_*DC_);
    splitArr(wuq,  wuq2, (long long)DH_*NH_*DC_);
    splitArr(wqr,  wqr2, (long long)DRH_*NH_*DC_);
    {   // NN pair pack: w1s -> cols [0,2048), w3s -> cols [2048,4096)
        long long tot = (long long)(DIM_/2) * MOESH_;
        unsigned nb = (unsigned)((tot + 255) / 256);
        split_pack_nn_k<<<nb, 256>>>(w1s, w13s2, tot, MOESH_, 2*MOESH_, 0);
        split_pack_nn_k<<<nb, 256>>>(w3s, w13s2, tot, MOESH_, 2*MOESH_, MOESH_);
        long long tot2 = (long long)(MOESH_/2) * DIM_;
        split_pack_nn_k<<<(unsigned)((tot2 + 255)/256), 256>>>(w2s, w2s2, tot2, DIM_, DIM_, 0);
    }
    pack_wo_k<<<(unsigned)(((long long)DIM_*1024 + 255)/256), 256>>>(wo, Wo2);

    // ---- attention ----
    rmsnorm_k<<<BT_, 256>>>(x, attn_w, nullptr, h2);
    // merged dkv|dq|kr, split-K x2, raw partials
    gemmCA<1>(h2, wA2, pk, BT_, NCDQ_, DIM_/2, DIM_/2, DIM_/2, NCDQ_, ASC_, nullptr,
              2, 1,
              /*aO1=*/DIM_/4, 0, /*bO1=*/DIM_/4, 0,
              /*cO1=*/(long long)BT_*NCDQ_, 0, 0, 0);
    {
        long long np = (long long)BT_*NCDQ_/2;
        reduce_split_k<<<(unsigned)((np + 255)/256), 256>>>(pk, pk + (long long)BT_*NCDQ_, cdq2, np);
    }
    gemmCA<1>(cdq2, wuk2, K2, BT_, DH_, DC_, NCDQ_/2, NH_*DC_/2, NH_*QKD_/2, ASC_, nullptr,
              NH_, NH_, 0,0, 0, DC_/2, 0, QKD_/2, 0, 1);
    gemmCA<1>(cdq2, wuv2, (void*)V, BT_, DH_, DC_, NCDQ_/2, NH_*DC_/2, NH_*DH_, ASC_, nullptr,
              NH_, NH_, 0,0, 0, DC_/2, 0, DH_, 0, 0);
    gemmCA<1>(cdq2 + DC_/2, wuq2, Q2, BT_, DH_, DC_, NCDQ_/2, NH_*DC_/2, NH_*QKD_/2,
              ASC_, nullptr, NH_, NH_, 0,0, 0, DC_/2, 0, QKD_/2, 0, 1);
    gemmCA<1>(cdq2 + DC_/2, wqr2, Q2 + DH_/2, BT_, DRH_, DC_, NCDQ_/2, NH_*DC_/2, NH_*QKD_/2,
              ASC_, nullptr, NH_, NH_, 0,0, 0, DC_/2, 0, QKD_/2, 0, 1);
    rope_q_k<<<BT_ * NH_, 16>>>(Q2);
    rope_kr_k<<<BT_, 16>>>(cdq2, K2);
    float scale = ASC_ / sqrtf((float)QKD_);
    gemmCA<1>(Q2, K2, S, T_, T_, QKD_, NH_*QKD_/2, NH_*QKD_/2, T_, scale, nullptr,
              B_*NH_, NH_,
              (long long)T_*NH_*QKD_/2, QKD_/2,
              (long long)T_*NH_*QKD_/2, QKD_/2,
              (long long)NH_*T_*T_, (long long)T_*T_,
              /*causal=*/1, 0);
    softmax_k<<<B_ * NH_ * T_, 256>>>(S);
    gemmRaw<2>(S, V, O2, T_, DH_, T_, T_, NH_*DH_, NH_*DH_/2, ASC_, nullptr,
               B_*NH_, NH_,
               (long long)NH_*T_*T_, (long long)T_*T_,
               (long long)T_*NH_*DH_, DH_,
               (long long)T_*NH_*DH_/2, DH_/2,
               nullptr, nullptr, nullptr, nullptr, 0, /*causalAV=*/1, /*outSplit=*/1);
    gemmCA<1>(O2, Wo2, x1, BT_, DIM_, NH_*DH_, NH_*DH_/2, NH_*DH_/2, DIM_, ASC_, x,
              1, 1, 0,0,0,0,0,0, 0, 0);

    // ---- MoE ----
    rmsnorm_k<<<BT_, 256>>>(x1, ffn_w, xn, xn2);
    cudaMemsetAsync(cnt, 0, NE_ * sizeof(int));
    float* affOut = (out_size >= BT_*DIM_ + BT_*NE_) ? out + (long long)BT_*DIM_ : nullptr;
    gate_k<<<BT_, 256>>>(xn, gate_w, gate_b, affOut, cnt, tok, wt);
    gemmCA<0>(xn2, w13s2, a13, BT_, 2*MOESH_, DIM_, DIM_/2, 2*MOESH_, 2*MOESH_, ASC_, nullptr,
              1, 1, 0,0,0,0,0,0, 0, 0);
    silumul2_k<<<(unsigned)(((long long)BT_*(MOESH_/2) + 255)/256), 256>>>(a13, a1s);
    gemmCA<0>(a1s, w2s2, out, BT_, DIM_, MOESH_, MOESH_/2, DIM_, DIM_, ASC_, x1,
              1, 1, 0,0,0,0,0,0, 0, 0);
    // routed experts: raw fp16-split path
    gemmRaw<0>(xn, w1r, r1, CAP_, MOE_, DIM_, DIM_, MOE_, MOE_, ASC_, nullptr,
               NE_, NE_, 0,0, 0, (long long)DIM_*MOE_, 0, (long long)CAP_*MOE_,
               cnt, tok, nullptr, nullptr, CAP_);
    gemmRaw<0>(xn, w3r, r2, CAP_, MOE_, DIM_, DIM_, MOE_, MOE_, ASC_, nullptr,
               NE_, NE_, 0,0, 0, (long long)DIM_*MOE_, 0, (long long)CAP_*MOE_,
               cnt, tok, nullptr, nullptr, CAP_);
    silumul_routed_k<<<(unsigned)(((long long)NE_*CAP_*MOE_/4 + 255)/256), 256>>>(
        (float4*)r1, (const float4*)r2, cnt);
    gemmRaw<0>(r1, w2r, out, CAP_, DIM_, MOE_, MOE_, DIM_, DIM_, ASC_, nullptr,
               NE_, NE_, 0, (long long)CAP_*MOE_, 0, (long long)MOE_*DIM_, 0, 0,
               cnt, nullptr, tok, wt, CAP_);
}

// round 14
// speedup vs baseline: 2.2608x; 1.0229x over previous
#include <cuda_runtime.h>
#include <cuda_fp16.h>
#include <math.h>
#include <stdint.h>

#define B_    2
#define T_    1024
#define BT_   2048
#define DIM_  2048
#define NH_   16
#define DH_   128
#define DRH_  64
#define DC_   512
#define NE_   16
#define TOPK_ 4
#define MOE_  1024
#define MOESH_ 2048
#define CAP_  2048
#define QKD_  192
#define NCDQ_ 1088
#define SC_   256.0f
#define ASC_  (1.0f/65536.0f)

// ---------------- scratch ----------------
__device__ float g_S  [(size_t)B_*NH_*T_*T_];
__device__ float g_V  [BT_*NH_*DH_];
__device__ float g_x1 [BT_*DIM_];
__device__ float g_xn [BT_*DIM_];
__device__ float g_a13[(size_t)BT_*2*MOESH_];
__device__ float g_h12[(size_t)NE_*CAP_*2*MOE_];
__device__ float g_pk [2][(size_t)BT_*NCDQ_];
__device__ int   g_cnt[NE_];
__device__ int   g_tok[NE_*CAP_];
__device__ float g_wt [NE_*CAP_];
// fp16 pair-split buffers: uint2 = (half2 hi(k,k+1), half2 lo(k,k+1)), values x*256
__device__ __align__(16) uint2 g_h2  [BT_*DIM_/2];
__device__ __align__(16) uint2 g_cdq2[(size_t)BT_*NCDQ_/2];
__device__ __align__(16) uint2 g_Q2  [BT_*NH_*QKD_/2];
__device__ __align__(16) uint2 g_K2  [BT_*NH_*QKD_/2];
__device__ __align__(16) uint2 g_O2  [BT_*NH_*DH_/2];
__device__ __align__(16) uint2 g_Wo2 [(size_t)DIM_*NH_*DH_/2];
__device__ __align__(16) uint2 g_xn2 [BT_*DIM_/2];
__device__ __align__(16) uint2 g_a1s [BT_*MOESH_/2];
__device__ __align__(16) uint2 g_h1S [(size_t)NE_*CAP_*MOE_/2];
// split weights
__device__ __align__(16) uint2 g_wA2  [(size_t)NCDQ_*DIM_/2];
__device__ __align__(16) uint2 g_wuk2 [DH_*NH_*DC_/2];
__device__ __align__(16) uint2 g_wuv2 [DH_*NH_*DC_/2];
__device__ __align__(16) uint2 g_wuq2 [DH_*NH_*DC_/2];
__device__ __align__(16) uint2 g_wqr2 [DRH_*NH_*DC_/2];
__device__ __align__(16) uint2 g_w13s2[(size_t)(DIM_/2)*2*MOESH_];
__device__ __align__(16) uint2 g_w2s2 [(size_t)(MOESH_/2)*DIM_];
__device__ __align__(16) uint2 g_w13r2[(size_t)NE_*(DIM_/2)*2*MOE_];
__device__ __align__(16) uint2 g_w2r2 [(size_t)NE_*(MOE_/2)*DIM_];

__device__ __forceinline__ uint2 split2(float x, float y) {
    __half hx = __float2half_rn(x), hy = __float2half_rn(y);
    float lx = x - __half2float(hx), ly = y - __half2float(hy);
    __half2 h = __halves2half2(hx, hy);
    __half2 l = __halves2half2(__float2half_rn(lx), __float2half_rn(ly));
    uint2 r; r.x = *(uint32_t*)&h; r.y = *(uint32_t*)&l;
    return r;
}
__device__ __forceinline__ void mma_f16(float* c, const uint32_t* a, const uint32_t* b) {
    asm volatile("mma.sync.aligned.m16n8k16.row.col.f32.f16.f16.f32 "
        "{%0,%1,%2,%3}, {%4,%5,%6,%7}, {%8,%9}, {%0,%1,%2,%3};\n"
        : "+f"(c[0]), "+f"(c[1]), "+f"(c[2]), "+f"(c[3])
        : "r"(a[0]), "r"(a[1]), "r"(a[2]), "r"(a[3]), "r"(b[0]), "r"(b[1]));
}

struct GemmP {
    const void* A; const void* B; void* C; const float* res;
    int M, N, K, lda, ldb, ldc;   // lda/ldb: PAIR strides for split ops; floats for raw
    float alpha;
    long long aO1, aO2, bO1, bO2, cO1, cO2;
    int zdiv, cap;
    const int* Mvec; const int* aRows; const int* cRows; const float* wRow;
    int causal, causalAV, outSplit;
};

// ============ cp.async GEMM (pair-split operands) ==============================
// MODE 0: B NN pair-packed [K/2][N]; MODE 1: B NT [N][K/2]. A always [M][K/2].
// Supports gathered A rows (aRows), dynamic M (Mvec), atomic scatter (cRows/wRow).
#define CA_STAGE_U2 2112
#define CA_SMEM_BYTES (4 * CA_STAGE_U2 * 8)

__device__ __forceinline__ void cp_async8(uint32_t saddr, const void* gaddr, int sz) {
    asm volatile("cp.async.ca.shared.global [%0], [%1], 8, %2;"
                 :: "r"(saddr), "l"(gaddr), "r"(sz) : "memory");
}

template<int MODE>
__global__ __launch_bounds__(256, 2) void gemm_ca(GemmP p) {
    extern __shared__ uint2 dyn[];
    uint32_t smemBase = (uint32_t)__cvta_generic_to_shared(dyn);

    int z = blockIdx.z, z1 = z / p.zdiv, z2 = z - z1 * p.zdiv;
    long long zA = z1 * p.aO1 + z2 * p.aO2;
    long long zB = z1 * p.bO1 + z2 * p.bO2;
    long long zC = z1 * p.cO1 + z2 * p.cO2;
    int M = p.Mvec ? p.Mvec[z] : p.M;
    int m0 = blockIdx.y * 128, n0 = blockIdx.x * 128;
    if (m0 >= M) return;
    if (MODE == 1 && p.causal && n0 >= m0 + 128) return;
    int tid = threadIdx.x, lane = tid & 31, warp = tid >> 5;
    int wm = (warp & 1) << 6, wn = (warp >> 1) << 5;
    int gid = lane >> 2, tg = lane & 3;

    long long gA[4]; uint32_t sAoff[4]; int szA[4];
    long long gB[4]; uint32_t sBoff[4]; int szB[4];
    long long strideB = (MODE == 1) ? 8 : (long long)8 * p.ldb;
#pragma unroll
    for (int i = 0; i < 4; i++) {
        int e = tid + 256 * i;
        int am = e >> 3, ak = e & 7;
        int row = m0 + am;
        bool va = row < M;
        long long ar = 0;
        if (va) ar = p.aRows ? (long long)p.aRows[(long long)z * p.cap + row]
                             : (long long)row;
        gA[i] = zA + ar * p.lda + ak;
        sAoff[i] = (uint32_t)(ak * 132 + am) * 8;
        szA[i] = va ? 8 : 0;
        if (MODE == 1) {
            int bn = e >> 3, bk = e & 7;
            bool vb = (n0 + bn) < p.N;
            gB[i] = zB + (long long)(vb ? (n0 + bn) : 0) * p.ldb + bk;
            sBoff[i] = (uint32_t)(1056 + bk * 132 + bn) * 8;
            szB[i] = vb ? 8 : 0;
        } else {
            int bk = e >> 7, bn = e & 127;
            bool vb = (n0 + bn) < p.N;
            gB[i] = zB + (long long)bk * p.ldb + n0 + (vb ? bn : 0);
            sBoff[i] = (uint32_t)(1056 + bk * 132 + bn) * 8;
            szB[i] = vb ? 8 : 0;
        }
    }

    float acc[4][4][4];
#pragma unroll
    for (int mi = 0; mi < 4; mi++)
#pragma unroll
        for (int ni = 0; ni < 4; ni++)
#pragma unroll
            for (int q = 0; q < 4; q++) acc[mi][ni][q] = 0.f;

    int nIter = p.K >> 4;
    const uint2* Ag = (const uint2*)p.A;
    const uint2* Bg = (const uint2*)p.B;

    auto issue = [&](int stage, int chunk) {
        uint32_t base = smemBase + (uint32_t)stage * CA_STAGE_U2 * 8;
        long long ka = (long long)chunk * 8;
        long long kb = (long long)chunk * strideB;
#pragma unroll
        for (int i = 0; i < 4; i++)
            cp_async8(base + sAoff[i], Ag + gA[i] + ka, szA[i]);
#pragma unroll
        for (int i = 0; i < 4; i++)
            cp_async8(base + sBoff[i], Bg + gB[i] + kb, szB[i]);
    };

#pragma unroll
    for (int s = 0; s < 3; s++) {
        if (s < nIter) issue(s, s);
        asm volatile("cp.async.commit_group;" ::: "memory");
    }

    for (int it = 0; it < nIter; it++) {
        asm volatile("cp.async.wait_group 2;" ::: "memory");
        __syncthreads();
        if (it + 3 < nIter) issue((it + 3) & 3, it + 3);
        asm volatile("cp.async.commit_group;" ::: "memory");

        const uint2* sA = dyn + (it & 3) * CA_STAGE_U2;
        const uint2* sB = sA + 1056;
        uint2 vB0[4], vB1[4];
#pragma unroll
        for (int ni = 0; ni < 4; ni++) {
            int nb2 = wn + ni * 8 + gid;
            vB0[ni] = sB[tg * 132 + nb2];
            vB1[ni] = sB[(tg + 4) * 132 + nb2];
        }
#pragma unroll
        for (int mi = 0; mi < 4; mi++) {
            int mb = wm + mi * 16 + gid;
            uint2 a0 = sA[tg * 132 + mb];
            uint2 a1 = sA[tg * 132 + mb + 8];
            uint2 a2 = sA[(tg + 4) * 132 + mb];
            uint2 a3 = sA[(tg + 4) * 132 + mb + 8];
            uint32_t ah[4] = {a0.x, a1.x, a2.x, a3.x};
            uint32_t al[4] = {a0.y, a1.y, a2.y, a3.y};
#pragma unroll
            for (int ni = 0; ni < 4; ni++) {
                uint32_t bh[2] = {vB0[ni].x, vB1[ni].x};
                mma_f16(acc[mi][ni], ah, bh);
            }
#pragma unroll
            for (int ni = 0; ni < 4; ni++) {
                uint32_t bh[2] = {vB0[ni].x, vB1[ni].x};
                mma_f16(acc[mi][ni], al, bh);
            }
#pragma unroll
            for (int ni = 0; ni < 4; ni++) {
                uint32_t bl[2] = {vB0[ni].y, vB1[ni].y};
                mma_f16(acc[mi][ni], ah, bl);
            }
        }
    }

#pragma unroll
    for (int mi = 0; mi < 4; mi++) {
#pragma unroll
        for (int half = 0; half < 2; half++) {
            int m = m0 + wm + mi * 16 + gid + half * 8;
            if (m >= M) continue;
            long long crow; float w = p.alpha;
            if (p.cRows) {
                crow = (long long)p.cRows[(long long)z * p.cap + m] * p.ldc;
                w *= p.wRow[(long long)z * p.cap + m];
            } else {
                crow = zC + (long long)m * p.ldc;
            }
#pragma unroll
            for (int ni = 0; ni < 4; ni++) {
                int n = n0 + wn + ni * 8 + tg * 2;
                if (n >= p.N) continue;
                float v0 = acc[mi][ni][half * 2 + 0] * w;
                float v1 = acc[mi][ni][half * 2 + 1] * w;
                if (p.cRows) {
                    atomicAdd(&((float*)p.C)[crow + n],     v0);
                    atomicAdd(&((float*)p.C)[crow + n + 1], v1);
                } else if (p.outSplit) {
                    ((uint2*)p.C)[crow + (n >> 1)] = split2(v0 * SC_, v1 * SC_);
                } else {
                    float* Cf = (float*)p.C;
                    if (p.res) { v0 += p.res[crow + n]; v1 += p.res[crow + n + 1]; }
                    Cf[crow + n]     = v0;
                    Cf[crow + n + 1] = v1;
                }
            }
        }
    }
}

// ============ raw mma.sync GEMM (fp16-split in loop) — AV only =================
template<int MODE>
__global__ __launch_bounds__(256, 2) void gemm_k(GemmP p) {
    __shared__ uint2 sA[2][8][132];
    __shared__ uint2 sB[2][8][132];

    int z = blockIdx.z, z1 = z / p.zdiv, z2 = z - z1 * p.zdiv;
    const float* A  = (const float*)p.A + z1 * p.aO1 + z2 * p.aO2;
    const float* Bp = (const float*)p.B + z1 * p.bO1 + z2 * p.bO2;
    long long zC = z1 * p.cO1 + z2 * p.cO2;
    int M = p.Mvec ? p.Mvec[z] : p.M;
    int m0 = blockIdx.y * 128, n0 = blockIdx.x * 128;
    if (m0 >= M) return;
    int tid = threadIdx.x, lane = tid & 31, warp = tid >> 5;
    int wm = (warp & 1) << 6, wn = (warp >> 1) << 5;
    int gid = lane >> 2, tg = lane & 3;

    bool aValid; const float* aPtr; int aP, aM;
    if (MODE != 2) {
        int r = m0 + (tid >> 1);
        aValid = (r < M);
        long long ar = 0;
        if (aValid) ar = p.aRows ? (long long)p.aRows[(long long)z * p.cap + r]
                                 : (long long)r;
        aPtr = A + ar * (long long)p.lda + (tid & 1) * 8;
        aP = (tid & 1) * 4;  aM = tid >> 1;
    } else {
        int m = m0 + (tid & 31) * 4;
        aValid = (m < M);
        aPtr = A + (long long)((tid >> 5) * 2) * p.lda + (aValid ? m : 0);
        aP = tid >> 5;       aM = (tid & 31) * 4;
    }
    bool bValid; const float* bPtr; int bP, bM;
    {
        int n = n0 + (tid & 31) * 4;
        bValid = (n < p.N);
        bPtr = Bp + (long long)((tid >> 5) * 2) * p.ldb + (bValid ? n : 0);
        bP = tid >> 5;       bM = (tid & 31) * 4;
    }

    float acc[4][4][4];
#pragma unroll
    for (int mi = 0; mi < 4; mi++)
#pragma unroll
        for (int ni = 0; ni < 4; ni++)
#pragma unroll
            for (int q = 0; q < 4; q++) acc[mi][ni][q] = 0.f;

    const float4 z4 = make_float4(0.f, 0.f, 0.f, 0.f);
    int kStart = (MODE == 2 && p.causalAV) ? m0 : 0;
    int nIter = (p.K - kStart) >> 4;

    auto loadG = [&](int chunk, float4* fa, float4* fb) {
        int k = kStart + chunk * 16;
        if (MODE != 2) {
            fa[0] = aValid ? *(const float4*)(aPtr + k)     : z4;
            fa[1] = aValid ? *(const float4*)(aPtr + k + 4) : z4;
        } else {
            long long o = (long long)k * p.lda;
            fa[0] = aValid ? *(const float4*)(aPtr + o)          : z4;
            fa[1] = aValid ? *(const float4*)(aPtr + o + p.lda)  : z4;
        }
        long long ob = (long long)k * p.ldb;
        fb[0] = bValid ? *(const float4*)(bPtr + ob)         : z4;
        fb[1] = bValid ? *(const float4*)(bPtr + ob + p.ldb) : z4;
    };
    auto storeS = [&](int buf, const float4* fa, const float4* fb) {
        if (MODE != 2) {
            const float* a8 = (const float*)fa;
#pragma unroll
            for (int j = 0; j < 4; j++)
                sA[buf][aP + j][aM] = split2(a8[2*j] * SC_, a8[2*j+1] * SC_);
        } else {
            const float* r0 = (const float*)&fa[0];
            const float* r1 = (const float*)&fa[1];
#pragma unroll
            for (int j = 0; j < 4; j++)
                sA[buf][aP][aM + j] = split2(r0[j] * SC_, r1[j] * SC_);
        }
        const float* b0 = (const float*)&fb[0];
        const float* b1 = (const float*)&fb[1];
#pragma unroll
        for (int j = 0; j < 4; j++)
            sB[buf][bP][bM + j] = split2(b0[j] * SC_, b1[j] * SC_);
    };

    float4 va[2], vb[2];
    loadG(0, va, vb);
    storeS(0, va, vb);
    __syncthreads();

    for (int it = 0; it < nIter; it++) {
        int cur = it & 1;
        float4 na[2] = {z4, z4}, nb[2] = {z4, z4};
        if (it + 1 < nIter) loadG(it + 1, na, nb);

        uint2 vB0[4], vB1[4];
#pragma unroll
        for (int ni = 0; ni < 4; ni++) {
            int nb2 = wn + ni * 8 + gid;
            vB0[ni] = sB[cur][tg    ][nb2];
            vB1[ni] = sB[cur][tg + 4][nb2];
        }
#pragma unroll
        for (int mi = 0; mi < 4; mi++) {
            int mbb = wm + mi * 16 + gid;
            uint2 a0 = sA[cur][tg    ][mbb];
            uint2 a1 = sA[cur][tg    ][mbb + 8];
            uint2 a2 = sA[cur][tg + 4][mbb];
            uint2 a3 = sA[cur][tg + 4][mbb + 8];
            uint32_t ah[4] = {a0.x, a1.x, a2.x, a3.x};
            uint32_t al[4] = {a0.y, a1.y, a2.y, a3.y};
#pragma unroll
            for (int ni = 0; ni < 4; ni++) {
                uint32_t bh[2] = {vB0[ni].x, vB1[ni].x};
                mma_f16(acc[mi][ni], ah, bh);
            }
#pragma unroll
            for (int ni = 0; ni < 4; ni++) {
                uint32_t bh[2] = {vB0[ni].x, vB1[ni].x};
                mma_f16(acc[mi][ni], al, bh);
            }
#pragma unroll
            for (int ni = 0; ni < 4; ni++) {
                uint32_t bl[2] = {vB0[ni].y, vB1[ni].y};
                mma_f16(acc[mi][ni], ah, bl);
            }
        }

        if (it + 1 < nIter) storeS(cur ^ 1, na, nb);
        __syncthreads();
    }

#pragma unroll
    for (int mi = 0; mi < 4; mi++) {
#pragma unroll
        for (int half = 0; half < 2; half++) {
            int m = m0 + wm + mi * 16 + gid + half * 8;
            if (m >= M) continue;
            long long crow; float w = p.alpha;
            if (p.cRows) {
                crow = (long long)p.cRows[(long long)z * p.cap + m] * p.ldc;
                w *= p.wRow[(long long)z * p.cap + m];
            } else {
                crow = zC + (long long)m * p.ldc;
            }
#pragma unroll
            for (int ni = 0; ni < 4; ni++) {
                int n = n0 + wn + ni * 8 + tg * 2;
                if (n >= p.N) continue;
                float v0 = acc[mi][ni][half * 2 + 0] * w;
                float v1 = acc[mi][ni][half * 2 + 1] * w;
                if (p.cRows) {
                    atomicAdd(&((float*)p.C)[crow + n],     v0);
                    atomicAdd(&((float*)p.C)[crow + n + 1], v1);
                } else if (p.outSplit) {
                    ((uint2*)p.C)[crow + (n >> 1)] = split2(v0 * SC_, v1 * SC_);
                } else {
                    float* Cf = (float*)p.C;
                    if (p.res) { v0 += p.res[crow + n]; v1 += p.res[crow + n + 1]; }
                    Cf[crow + n]     = v0;
                    Cf[crow + n + 1] = v1;
                }
            }
        }
    }
}

// ---------------- producers / small kernels ------------------------------------
__global__ void split_arr_k(const float4* __restrict__ in, uint2* __restrict__ out,
                            long long n4) {
    long long i = (long long)blockIdx.x * 256 + threadIdx.x;
    if (i >= n4) return;
    float4 v = in[i];
    out[2 * i]     = split2(v.x * SC_, v.y * SC_);
    out[2 * i + 1] = split2(v.z * SC_, v.w * SC_);
}

// NN pair pack: out[p*ldout + colOff + n] = split2(in[2p][n], in[2p+1][n])
__global__ void split_pack_nn_k(const float* __restrict__ in, uint2* __restrict__ out,
                                long long total, int N, int ldout, int colOff) {
    long long i = (long long)blockIdx.x * 256 + threadIdx.x;
    if (i >= total) return;
    long long pr = i / N;
    int n = (int)(i - pr * N);
    out[pr * ldout + colOff + n] =
        split2(in[(2 * pr) * N + n] * SC_, in[(2 * pr + 1) * N + n] * SC_);
}

__global__ void reduce_split_k(const float* __restrict__ p0, const float* __restrict__ p1,
                               uint2* __restrict__ out, long long npair) {
    long long i = (long long)blockIdx.x * 256 + threadIdx.x;
    if (i >= npair) return;
    float v0 = p0[2*i]   + p1[2*i];
    float v1 = p0[2*i+1] + p1[2*i+1];
    out[i] = split2(v0 * SC_, v1 * SC_);
}

__global__ void rmsnorm_k(const float* __restrict__ x, const float* __restrict__ w,
                          float* __restrict__ oraw, uint2* __restrict__ osp) {
    int r = blockIdx.x;
    const float* xr = x + (long long)r * DIM_;
    float s = 0.f;
    for (int d = threadIdx.x; d < DIM_; d += 256) { float v = xr[d]; s += v * v; }
    __shared__ float red[256];
    red[threadIdx.x] = s; __syncthreads();
    for (int off = 128; off; off >>= 1) {
        if (threadIdx.x < off) red[threadIdx.x] += red[threadIdx.x + off];
        __syncthreads();
    }
    float inv = rsqrtf(red[0] / (float)DIM_ + 1e-6f);
    for (int pd = threadIdx.x; pd < DIM_/2; pd += 256) {
        int d = pd * 2;
        float v0 = w[d] * xr[d] * inv;
        float v1 = w[d+1] * xr[d+1] * inv;
        if (oraw) { oraw[(long long)r * DIM_ + d] = v0; oraw[(long long)r * DIM_ + d+1] = v1; }
        osp[(long long)r * (DIM_/2) + pd] = split2(v0 * SC_, v1 * SC_);
    }
}

__device__ __forceinline__ void rope_cs(int t, int j, float& c, float& s) {
    float freq = 1.0f / powf(10000.0f, (float)(2 * j) / (float)DRH_);
    float ang = (float)t * freq;
    sincosf(ang, &s, &c);
}
__device__ __forceinline__ void unpack2(uint2 u, float& a, float& b) {
    __half2 h = *(__half2*)&u.x, l = *(__half2*)&u.y;
    a = __low2float(h) + __low2float(l);
    b = __high2float(h) + __high2float(l);
}

__global__ void rope_q_k(uint2* __restrict__ Q) {   // 16 threads
    int idx = blockIdx.x;
    int bt = idx / NH_;
    int t = bt % T_;
    int pp = threadIdx.x;
    uint2* base = Q + (long long)idx * (QKD_/2) + DH_/2;
    float re0, re1, im0, im1;
    unpack2(base[pp], re0, re1);
    unpack2(base[16 + pp], im0, im1);
    float c0, s0, c1, s1;
    rope_cs(t, 2*pp, c0, s0); rope_cs(t, 2*pp + 1, c1, s1);
    base[pp]      = split2(re0 * c0 - im0 * s0, re1 * c1 - im1 * s1);
    base[16 + pp] = split2(re0 * s0 + im0 * c0, re1 * s1 + im1 * c1);
}

__global__ void rope_kr_k(const uint2* __restrict__ cdq, uint2* __restrict__ Kb) {
    int bt = blockIdx.x;
    int t = bt % T_;
    int pp = threadIdx.x;
    const uint2* src = cdq + (long long)bt * (NCDQ_/2) + 512;
    float re0, re1, im0, im1;
    unpack2(src[pp], re0, re1);
    unpack2(src[16 + pp], im0, im1);
    float c0, s0, c1, s1;
    rope_cs(t, 2*pp, c0, s0); rope_cs(t, 2*pp + 1, c1, s1);
    float inh = 1.0f / (float)NH_;
    uint2 o1 = split2((re0 * c0 - im0 * s0) * inh, (re1 * c1 - im1 * s1) * inh);
    uint2 o2 = split2((re0 * s0 + im0 * c0) * inh, (re1 * s1 + im1 * c1) * inh);
    for (int h = 0; h < NH_; h++) {
        uint2* base = Kb + ((long long)bt * NH_ + h) * (QKD_/2) + DH_/2;
        base[pp] = o1; base[16 + pp] = o2;
    }
}

__global__ void softmax_k(float* __restrict__ S) {
    long long r = blockIdx.x;
    int t = (int)(r & (T_ - 1));
    float* row = S + r * (long long)T_;
    int n = t + 1;
    __shared__ float red[256];
    int tid = threadIdx.x;
    float mx = -INFINITY;
    for (int l = tid; l < n; l += 256) mx = fmaxf(mx, row[l]);
    red[tid] = mx; __syncthreads();
    for (int off = 128; off; off >>= 1) {
        if (tid < off) red[tid] = fmaxf(red[tid], red[tid + off]);
        __syncthreads();
    }
    mx = red[0]; __syncthreads();
    float sum = 0.f;
    for (int l = tid; l < n; l += 256) { float e = expf(row[l] - mx); row[l] = e; sum += e; }
    red[tid] = sum; __syncthreads();
    for (int off = 128; off; off >>= 1) {
        if (tid < off) red[tid] += red[tid + off];
        __syncthreads();
    }
    float inv = 1.f / red[0];
    for (int l = tid; l < T_; l += 256) row[l] = (l < n) ? row[l] * inv : 0.f;
}

__global__ void pack_wo_k(const float* __restrict__ wo, uint2* __restrict__ out) {
    long long i = (long long)blockIdx.x * 256 + threadIdx.x;
    if (i >= (long long)DIM_ * 1024) return;
    int d = (int)(i >> 10);
    int pr = (int)(i & 1023);
    int e = pr * 2;
    int h = e >> 7, k = e & 127;
    float s0 = wo[(long long)d * 2048 + k * NH_ + h];
    float s1 = wo[(long long)d * 2048 + (k + 1) * NH_ + h];
    out[i] = split2(s0 * SC_, s1 * SC_);
}

__global__ void gate_k(const float* __restrict__ xn, const float* __restrict__ gw,
                       const float* __restrict__ gb, float* affOut,
                       int* __restrict__ cnt, int* __restrict__ tok,
                       float* __restrict__ wt) {
    int bt = blockIdx.x;
    __shared__ float xrow[DIM_];
    __shared__ float aff[NE_];
    int tid = threadIdx.x;
    for (int d = tid; d < DIM_; d += 256) xrow[d] = xn[(long long)bt * DIM_ + d];
    __syncthreads();
    int w = tid >> 5, lane = tid & 31;
    for (int e = w; e < NE_; e += 8) {
        float s = 0.f;
        const float* gr = gw + (long long)e * DIM_;
        for (int d = lane; d < DIM_; d += 32) s += xrow[d] * gr[d];
        for (int o = 16; o; o >>= 1) s += __shfl_xor_sync(0xffffffffu, s, o);
        if (lane == 0) aff[e] = 1.f / (1.f + expf(-s)) + gb[e];
    }
    __syncthreads();
    if (tid == 0) {
        if (affOut) for (int e = 0; e < NE_; e++) affOut[(long long)bt * NE_ + e] = aff[e];
        bool used[NE_] = {};
        float wv[TOPK_]; int wi[TOPK_]; float sum = 0.f;
        for (int k = 0; k < TOPK_; k++) {
            float best = -1e30f; int bi = 0;
            for (int e = 0; e < NE_; e++)
                if (!used[e] && aff[e] > best) { best = aff[e]; bi = e; }
            used[bi] = true; wv[k] = best; wi[k] = bi; sum += best;
        }
        for (int k = 0; k < TOPK_; k++) {
            int e = wi[k];
            int pos = atomicAdd(&cnt[e], 1);
            tok[e * CAP_ + pos] = bt;
            wt [e * CAP_ + pos] = wv[k] / sum;
        }
    }
}

__global__ void silumul2_k(const float* __restrict__ a13, uint2* __restrict__ o) {
    long long i = (long long)blockIdx.x * 256 + threadIdx.x;
    if (i >= (long long)BT_ * (MOESH_/2)) return;
    long long row = i >> 10;
    int c = (int)(i & 1023) * 2;
    const float* ar = a13 + row * 4096;
    float x0 = ar[c] * ar[2048 + c];
    float x1 = ar[c + 1] * ar[2048 + c + 1];
    x0 = x0 / (1.f + expf(-x0));
    x1 = x1 / (1.f + expf(-x1));
    o[i] = split2(x0 * SC_, x1 * SC_);
}

// h12[e][ri][0:1024]=h1, [1024:2048]=h2 -> silu(h1*h2) pair-split into h1S
__global__ void silumul_routed2_k(const float* __restrict__ h12, uint2* __restrict__ o,
                                  const int* __restrict__ cnt) {
    long long i = (long long)blockIdx.x * 256 + threadIdx.x;   // NE*CAP*512 pairs
    if (i >= (long long)NE_ * CAP_ * (MOE_/2)) return;
    int e  = (int)(i >> 20);                 // CAP*512 = 2^20
    int ri = (int)((i >> 9) & (CAP_ - 1));
    if (ri >= cnt[e]) return;
    int c = (int)(i & 511) * 2;
    const float* base = h12 + ((long long)e * CAP_ + ri) * 2048;
    float x0 = base[c]     * base[1024 + c];
    float x1 = base[c + 1] * base[1024 + c + 1];
    x0 = x0 / (1.f + expf(-x0));
    x1 = x1 / (1.f + expf(-x1));
    o[i] = split2(x0 * SC_, x1 * SC_);
}

// ---------------- host helpers ------------------------------------------------
static GemmP mkP(const void* A, const void* B, void* C, int M, int N, int K,
                 int lda, int ldb, int ldc, float alpha, const float* res,
                 int zdiv, long long a1, long long a2, long long b1, long long b2,
                 long long c1, long long c2,
                 const int* Mvec, const int* aRows, const int* cRows,
                 const float* wRow, int cap, int causal, int causalAV, int outSplit) {
    GemmP p;
    p.A = A; p.B = B; p.C = C; p.res = res;
    p.M = M; p.N = N; p.K = K; p.lda = lda; p.ldb = ldb; p.ldc = ldc;
    p.alpha = alpha;
    p.aO1 = a1; p.aO2 = a2; p.bO1 = b1; p.bO2 = b2; p.cO1 = c1; p.cO2 = c2;
    p.zdiv = zdiv; p.cap = cap;
    p.Mvec = Mvec; p.aRows = aRows; p.cRows = cRows; p.wRow = wRow;
    p.causal = causal; p.causalAV = causalAV; p.outSplit = outSplit;
    return p;
}

template<int MODE>
static void gemmCA(const uint2* A, const uint2* B, void* C, int M, int N, int K,
                   int ldaP, int ldbP, int ldc, float alpha, const float* res,
                   int nz, int zdiv,
                   long long a1, long long a2, long long b1, long long b2,
                   long long c1, long long c2,
                   int causal = 0, int outSplit = 0,
                   const int* Mvec = nullptr, const int* aRows = nullptr,
                   const int* cRows = nullptr, const float* wRow = nullptr,
                   int cap = 0, int mBlocks = 0) {
    GemmP p = mkP(A, B, C, M, N, K, ldaP, ldbP, ldc, alpha, res, zdiv,
                  a1, a2, b1, b2, c1, c2,
                  Mvec, aRows, cRows, wRow, cap, causal, 0, outSplit);
    cudaFuncSetAttribute(gemm_ca<MODE>, cudaFuncAttributeMaxDynamicSharedMemorySize,
                         CA_SMEM_BYTES);
    int gy = mBlocks ? mBlocks : (M + 127) / 128;
    dim3 g((N + 127) / 128, gy, nz);
    gemm_ca<MODE><<<g, 256, CA_SMEM_BYTES>>>(p);
}

template<int MODE>
static void gemmRaw(const float* A, const float* B, void* C, int M, int N, int K,
                    int lda, int ldb, int ldc, float alpha, const float* res,
                    int nz, int zdiv,
                    long long a1, long long a2, long long b1, long long b2,
                    long long c1, long long c2,
                    const int* Mvec = nullptr, const int* aRows = nullptr,
                    const int* cRows = nullptr, const float* wRow = nullptr,
                    int cap = 0, int causalAV = 0, int outSplit = 0) {
    GemmP p = mkP(A, B, C, M, N, K, lda, ldb, ldc, alpha, res, zdiv,
                  a1, a2, b1, b2, c1, c2,
                  Mvec, aRows, cRows, wRow, cap, 0, causalAV, outSplit);
    dim3 g((N + 127) / 128, (M + 127) / 128, nz);
    gemm_k<MODE><<<g, 256>>>(p);
}

static void splitArr(const float* in, uint2* out, long long n) {
    long long n4 = n >> 2;
    split_arr_k<<<(unsigned)((n4 + 255) / 256), 256>>>((const float4*)in, out, n4);
}

extern "C" void kernel_launch(void* const* d_in, const int* in_sizes, int n_in,
                              void* d_out, int out_size) {
    const float* x      = (const float*)d_in[0];
    const float* attn_w = (const float*)d_in[3];
    const float* ffn_w  = (const float*)d_in[4];
    const float* gate_w = (const float*)d_in[5];
    const float* gate_b = (const float*)d_in[6];
    const float* w1s    = (const float*)d_in[7];
    const float* w2s    = (const float*)d_in[8];
    const float* w3s    = (const float*)d_in[9];
    const float* w1r    = (const float*)d_in[10];
    const float* w2r    = (const float*)d_in[11];
    const float* w3r    = (const float*)d_in[12];
    const float* wdkv   = (const float*)d_in[13];
    const float* wuk    = (const float*)d_in[14];
    const float* wuv    = (const float*)d_in[15];
    const float* wdq    = (const float*)d_in[16];
    const float* wuq    = (const float*)d_in[17];
    const float* wqr    = (const float*)d_in[18];
    const float* wkr    = (const float*)d_in[19];
    const float* wo     = (const float*)d_in[20];
    float* out = (float*)d_out;

    float *S, *V, *x1, *xn, *a13, *h12, *pk, *wt;
    int *cnt, *tok;
    uint2 *h2, *cdq2, *Q2, *K2, *O2, *Wo2, *xn2, *a1s, *h1S;
    uint2 *wA2, *wuk2, *wuv2, *wuq2, *wqr2, *w13s2, *w2s2, *w13r2, *w2r2;
    cudaGetSymbolAddress((void**)&S,   g_S);
    cudaGetSymbolAddress((void**)&V,   g_V);
    cudaGetSymbolAddress((void**)&x1,  g_x1);
    cudaGetSymbolAddress((void**)&xn,  g_xn);
    cudaGetSymbolAddress((void**)&a13, g_a13);
    cudaGetSymbolAddress((void**)&h12, g_h12);
    cudaGetSymbolAddress((void**)&pk,  g_pk);
    cudaGetSymbolAddress((void**)&cnt, g_cnt);
    cudaGetSymbolAddress((void**)&tok, g_tok);
    cudaGetSymbolAddress((void**)&wt,  g_wt);
    cudaGetSymbolAddress((void**)&h2,  g_h2);
    cudaGetSymbolAddress((void**)&cdq2, g_cdq2);
    cudaGetSymbolAddress((void**)&Q2,  g_Q2);
    cudaGetSymbolAddress((void**)&K2,  g_K2);
    cudaGetSymbolAddress((void**)&O2,  g_O2);
    cudaGetSymbolAddress((void**)&Wo2, g_Wo2);
    cudaGetSymbolAddress((void**)&xn2, g_xn2);
    cudaGetSymbolAddress((void**)&a1s, g_a1s);
    cudaGetSymbolAddress((void**)&h1S, g_h1S);
    cudaGetSymbolAddress((void**)&wA2,  g_wA2);
    cudaGetSymbolAddress((void**)&wuk2, g_wuk2);
    cudaGetSymbolAddress((void**)&wuv2, g_wuv2);
    cudaGetSymbolAddress((void**)&wuq2, g_wuq2);
    cudaGetSymbolAddress((void**)&wqr2, g_wqr2);
    cudaGetSymbolAddress((void**)&w13s2, g_w13s2);
    cudaGetSymbolAddress((void**)&w2s2,  g_w2s2);
    cudaGetSymbolAddress((void**)&w13r2, g_w13r2);
    cudaGetSymbolAddress((void**)&w2r2,  g_w2r2);

    // ---- weight pre-split / packing (pair format) ----
    splitArr(wdkv, wA2,                           (long long)DC_*DIM_);
    splitArr(wdq,  wA2 + (long long)DC_*DIM_/2,   (long long)DC_*DIM_);
    splitArr(wkr,  wA2 + (long long)DC_*DIM_,     (long long)DRH_*DIM_);
    splitArr(wuk,  wuk2, (long long)DH_*NH_*DC_);
    splitArr(wuv,  wuv2, (long long)DH_*NH_*DC_);
    splitArr(wuq,  wuq2, (long long)DH_*NH_*DC_);
    splitArr(wqr,  wqr2, (long long)DRH_*NH_*DC_);
    {   // shared FFN NN pair packs
        long long tot = (long long)(DIM_/2) * MOESH_;
        unsigned nb = (unsigned)((tot + 255) / 256);
        split_pack_nn_k<<<nb, 256>>>(w1s, w13s2, tot, MOESH_, 2*MOESH_, 0);
        split_pack_nn_k<<<nb, 256>>>(w3s, w13s2, tot, MOESH_, 2*MOESH_, MOESH_);
        long long tot2 = (long long)(MOESH_/2) * DIM_;
        split_pack_nn_k<<<(unsigned)((tot2 + 255)/256), 256>>>(w2s, w2s2, tot2, DIM_, DIM_, 0);
    }
    {   // routed NN pair packs (treat as [(NE*K)][N]; K even so pairs stay per-expert)
        long long totr = (long long)NE_ * (DIM_/2) * MOE_;
        unsigned nbr = (unsigned)((totr + 255) / 256);
        split_pack_nn_k<<<nbr, 256>>>(w1r, w13r2, totr, MOE_, 2*MOE_, 0);
        split_pack_nn_k<<<nbr, 256>>>(w3r, w13r2, totr, MOE_, 2*MOE_, MOE_);
        long long totr2 = (long long)NE_ * (MOE_/2) * DIM_;
        split_pack_nn_k<<<(unsigned)((totr2 + 255)/256), 256>>>(w2r, w2r2, totr2, DIM_, DIM_, 0);
    }
    pack_wo_k<<<(unsigned)(((long long)DIM_*1024 + 255)/256), 256>>>(wo, Wo2);

    // ---- attention ----
    rmsnorm_k<<<BT_, 256>>>(x, attn_w, nullptr, h2);
    gemmCA<1>(h2, wA2, pk, BT_, NCDQ_, DIM_/2, DIM_/2, DIM_/2, NCDQ_, ASC_, nullptr,
              2, 1, /*aO1=*/DIM_/4, 0, /*bO1=*/DIM_/4, 0,
              /*cO1=*/(long long)BT_*NCDQ_, 0, 0, 0);
    {
        long long np = (long long)BT_*NCDQ_/2;
        reduce_split_k<<<(unsigned)((np + 255)/256), 256>>>(pk, pk + (long long)BT_*NCDQ_, cdq2, np);
    }
    gemmCA<1>(cdq2, wuk2, K2, BT_, DH_, DC_, NCDQ_/2, NH_*DC_/2, NH_*QKD_/2, ASC_, nullptr,
              NH_, NH_, 0,0, 0, DC_/2, 0, QKD_/2, 0, 1);
    gemmCA<1>(cdq2, wuv2, (void*)V, BT_, DH_, DC_, NCDQ_/2, NH_*DC_/2, NH_*DH_, ASC_, nullptr,
              NH_, NH_, 0,0, 0, DC_/2, 0, DH_, 0, 0);
    gemmCA<1>(cdq2 + DC_/2, wuq2, Q2, BT_, DH_, DC_, NCDQ_/2, NH_*DC_/2, NH_*QKD_/2,
              ASC_, nullptr, NH_, NH_, 0,0, 0, DC_/2, 0, QKD_/2, 0, 1);
    gemmCA<1>(cdq2 + DC_/2, wqr2, Q2 + DH_/2, BT_, DRH_, DC_, NCDQ_/2, NH_*DC_/2, NH_*QKD_/2,
              ASC_, nullptr, NH_, NH_, 0,0, 0, DC_/2, 0, QKD_/2, 0, 1);
    rope_q_k<<<BT_ * NH_, 16>>>(Q2);
    rope_kr_k<<<BT_, 16>>>(cdq2, K2);
    float scale = ASC_ / sqrtf((float)QKD_);
    gemmCA<1>(Q2, K2, S, T_, T_, QKD_, NH_*QKD_/2, NH_*QKD_/2, T_, scale, nullptr,
              B_*NH_, NH_,
              (long long)T_*NH_*QKD_/2, QKD_/2,
              (long long)T_*NH_*QKD_/2, QKD_/2,
              (long long)NH_*T_*T_, (long long)T_*T_,
              /*causal=*/1, 0);
    softmax_k<<<B_ * NH_ * T_, 256>>>(S);
    gemmRaw<2>(S, V, O2, T_, DH_, T_, T_, NH_*DH_, NH_*DH_/2, ASC_, nullptr,
               B_*NH_, NH_,
               (long long)NH_*T_*T_, (long long)T_*T_,
               (long long)T_*NH_*DH_, DH_,
               (long long)T_*NH_*DH_/2, DH_/2,
               nullptr, nullptr, nullptr, nullptr, 0, /*causalAV=*/1, /*outSplit=*/1);
    gemmCA<1>(O2, Wo2, x1, BT_, DIM_, NH_*DH_, NH_*DH_/2, NH_*DH_/2, DIM_, ASC_, x,
              1, 1, 0,0,0,0,0,0, 0, 0);

    // ---- MoE ----
    rmsnorm_k<<<BT_, 256>>>(x1, ffn_w, xn, xn2);
    cudaMemsetAsync(cnt, 0, NE_ * sizeof(int));
    float* affOut = (out_size >= BT_*DIM_ + BT_*NE_) ? out + (long long)BT_*DIM_ : nullptr;
    gate_k<<<BT_, 256>>>(xn, gate_w, gate_b, affOut, cnt, tok, wt);
    gemmCA<0>(xn2, w13s2, a13, BT_, 2*MOESH_, DIM_, DIM_/2, 2*MOESH_, 2*MOESH_, ASC_, nullptr,
              1, 1, 0,0,0,0,0,0, 0, 0);
    silumul2_k<<<(unsigned)(((long long)BT_*(MOESH_/2) + 255)/256), 256>>>(a13, a1s);
    gemmCA<0>(a1s, w2s2, out, BT_, DIM_, MOESH_, MOESH_/2, DIM_, DIM_, ASC_, x1,
              1, 1, 0,0,0,0,0,0, 0, 0);
    // routed experts — all on the CA fast path
    gemmCA<0>(xn2, w13r2, h12, CAP_, 2*MOE_, DIM_, DIM_/2, 2*MOE_, 2*MOE_, ASC_, nullptr,
              NE_, NE_, 0,0, 0, (long long)(DIM_/2)*2*MOE_, 0, (long long)CAP_*2*MOE_,
              0, 0, cnt, tok, nullptr, nullptr, CAP_, CAP_/128);
    silumul_routed2_k<<<(unsigned)(((long long)NE_*CAP_*(MOE_/2) + 255)/256), 256>>>(
        h12, h1S, cnt);
    gemmCA<0>(h1S, w2r2, out, CAP_, DIM_, MOE_, MOE_/2, DIM_, DIM_, ASC_, nullptr,
              NE_, NE_, 0, (long long)CAP_*(MOE_/2), 0, (long long)(MOE_/2)*DIM_, 0, 0,
              0, 0, cnt, nullptr, tok, wt, CAP_, CAP_/128);
}